// round 1
// baseline (speedup 1.0000x reference)
#include <cuda_runtime.h>
#include <math.h>

// ---------------------------------------------------------------------------
// Problem constants
// ---------------------------------------------------------------------------
#define B_TOT 65536
// H=64, HC=128, N=8, OBS0=6, OBS1=1024, OBS2=7, NA=2

typedef unsigned long long u64;

// ---------------------------------------------------------------------------
// Packed f32x2 helpers (FFMA2 — PTX-only dual-issue fp32 on sm_103a)
// ---------------------------------------------------------------------------
static __device__ __forceinline__ u64 pack2(float lo, float hi) {
    u64 r; asm("mov.b64 %0,{%1,%2};" : "=l"(r) : "f"(lo), "f"(hi)); return r;
}
static __device__ __forceinline__ void unpack2(u64 v, float& lo, float& hi) {
    asm("mov.b64 {%0,%1},%2;" : "=f"(lo), "=f"(hi) : "l"(v));
}
static __device__ __forceinline__ void ffma2(u64& d, u64 a, u64 b) {
    asm("fma.rn.f32x2 %0,%1,%2,%0;" : "+l"(d) : "l"(a), "l"(b));
}

// ---------------------------------------------------------------------------
// Scratch (static device globals: allocation-free)
// ---------------------------------------------------------------------------
__device__ float g_M[64 * 64];                        // Wq @ Wk^T
__device__ float g_concat[(size_t)B_TOT * 192];       // [own | env | v_att]
__device__ float g_h[(size_t)B_TOT * 128];            // hidden after Wc1

// ---------------------------------------------------------------------------
// K0: M[i][j] = sum_h Wq[i][h] * Wk[j][h]
// ---------------------------------------------------------------------------
__global__ void k_prep(const float* __restrict__ Wq, const float* __restrict__ Wk) {
    int e = blockIdx.x * 256 + threadIdx.x;
    if (e < 4096) {
        int i = e >> 6, j = e & 63;
        float s = 0.f;
#pragma unroll
        for (int h = 0; h < 64; h++) s = fmaf(Wq[i * 64 + h], Wk[j * 64 + h], s);
        g_M[e] = s;
    }
}

// ---------------------------------------------------------------------------
// Generic 128x64 block-tile GEMM + bias + relu.
//   C[r, ccol0 + bcol + c] = relu(sum_k A[r,k] * Bw[k, bcol + c] + bias[bcol+c])
// bcol = blockIdx.y*64. Per-thread 8 rows x 4 cols via FFMA2 (row pairs).
// ---------------------------------------------------------------------------
template <int KTOT, int LDA, int LDB>
__global__ __launch_bounds__(256)
void k_gemm(const float* __restrict__ A, const float* __restrict__ Bw,
            const float* __restrict__ bias, float* __restrict__ C,
            int ldc, int ccol0) {
    __shared__ float As[16 * 128];
    __shared__ float Bs[16 * 64];
    const int tid  = threadIdx.x;
    const int row0 = blockIdx.x * 128;
    const int bcol = blockIdx.y * 64;
    const int m0   = (tid >> 4) * 8;
    const int c0   = (tid & 15) * 4;

    u64 acc[4][4];
#pragma unroll
    for (int i = 0; i < 4; i++)
#pragma unroll
        for (int j = 0; j < 4; j++) acc[i][j] = 0ull;

    for (int k0 = 0; k0 < KTOT; k0 += 16) {
        // A tile [128 x 16] -> transposed As[k][m]
#pragma unroll
        for (int l = 0; l < 2; l++) {
            int idx = tid + l * 256;
            int m = idx >> 2, kq = idx & 3;
            float4 v = *reinterpret_cast<const float4*>(
                &A[(size_t)(row0 + m) * LDA + k0 + kq * 4]);
            As[(kq * 4 + 0) * 128 + m] = v.x;
            As[(kq * 4 + 1) * 128 + m] = v.y;
            As[(kq * 4 + 2) * 128 + m] = v.z;
            As[(kq * 4 + 3) * 128 + m] = v.w;
        }
        // B tile [16 x 64]
        {
            int kk = tid >> 4, jq = tid & 15;
            *reinterpret_cast<float4*>(&Bs[kk * 64 + jq * 4]) =
                *reinterpret_cast<const float4*>(&Bw[(size_t)(k0 + kk) * LDB + bcol + jq * 4]);
        }
        __syncthreads();
#pragma unroll
        for (int kk = 0; kk < 16; kk++) {
            const float* ar = &As[kk * 128 + m0];
            u64 a0 = *reinterpret_cast<const u64*>(ar + 0);
            u64 a1 = *reinterpret_cast<const u64*>(ar + 2);
            u64 a2 = *reinterpret_cast<const u64*>(ar + 4);
            u64 a3 = *reinterpret_cast<const u64*>(ar + 6);
            float4 b = *reinterpret_cast<const float4*>(&Bs[kk * 64 + c0]);
            u64 b0p = pack2(b.x, b.x), b1p = pack2(b.y, b.y);
            u64 b2p = pack2(b.z, b.z), b3p = pack2(b.w, b.w);
            ffma2(acc[0][0], a0, b0p); ffma2(acc[0][1], a0, b1p);
            ffma2(acc[0][2], a0, b2p); ffma2(acc[0][3], a0, b3p);
            ffma2(acc[1][0], a1, b0p); ffma2(acc[1][1], a1, b1p);
            ffma2(acc[1][2], a1, b2p); ffma2(acc[1][3], a1, b3p);
            ffma2(acc[2][0], a2, b0p); ffma2(acc[2][1], a2, b1p);
            ffma2(acc[2][2], a2, b2p); ffma2(acc[2][3], a2, b3p);
            ffma2(acc[3][0], a3, b0p); ffma2(acc[3][1], a3, b1p);
            ffma2(acc[3][2], a3, b2p); ffma2(acc[3][3], a3, b3p);
        }
        __syncthreads();
    }
#pragma unroll
    for (int i = 0; i < 4; i++) {
#pragma unroll
        for (int j = 0; j < 4; j++) {
            float lo, hi; unpack2(acc[i][j], lo, hi);
            int c = bcol + c0 + j;
            float bb = __ldg(&bias[c]);
            size_t r = (size_t)(row0 + m0 + 2 * i);
            C[r * ldc + ccol0 + c]       = fmaxf(lo + bb, 0.f);
            C[(r + 1) * ldc + ccol0 + c] = fmaxf(hi + bb, 0.f);
        }
    }
}

// ---------------------------------------------------------------------------
// K2: fused attention path (64 batch rows / block, 256 threads)
//   own_e -> g_concat[:,0:64];  E = relu(relu(S2@Ws1)@Ws2);
//   t = own_e @ M;  score = t . E_n (masked);  softmax;  wsum = sum alpha*E_n;
//   v_att = wsum @ Wv -> g_concat[:,128:192]
// ---------------------------------------------------------------------------
#define ATTN_SMEM_FLOATS (384 + 448 + 4096 * 3 + 64 * 65 * 2 + 512 * 65 + 512 * 3 + 64 * 3)
#define ATTN_SMEM_BYTES  (ATTN_SMEM_FLOATS * 4)

__global__ __launch_bounds__(256)
void k_attn(const float* __restrict__ S0, const float* __restrict__ S2,
            const float* __restrict__ W0, const float* __restrict__ b0,
            const float* __restrict__ Ws1, const float* __restrict__ bs1,
            const float* __restrict__ Ws2, const float* __restrict__ bs2,
            const float* __restrict__ Wv) {
    extern __shared__ float sm[];
    float* W0s  = sm;              // 384
    float* Ws1s = W0s + 384;       // 448
    float* Ws2s = Ws1s + 448;      // 4096
    float* Ms   = Ws2s + 4096;     // 4096
    float* Wvs  = Ms + 4096;       // 4096
    float* own  = Wvs + 4096;      // 64*65
    float* tt   = own + 64 * 65;   // 64*65 (t, later wsum)
    float* E    = tt + 64 * 65;    // 512*65
    float* sc   = E + 512 * 65;    // 512
    float* al   = sc + 512;        // 512 alpha
    float* mk   = al + 512;        // 512 mask
    float* b0s  = mk + 512;        // 64
    float* bs1s = b0s + 64;        // 64
    float* bs2s = bs1s + 64;       // 64

    const int tid = threadIdx.x;
    const int gb0 = blockIdx.x * 64;

    for (int i = tid; i < 384; i += 256) W0s[i] = W0[i];
    for (int i = tid; i < 448; i += 256) Ws1s[i] = Ws1[i];
    for (int i = tid; i < 4096; i += 256) {
        Ws2s[i] = Ws2[i]; Ms[i] = g_M[i]; Wvs[i] = Wv[i];
    }
    if (tid < 64) { b0s[tid] = b0[tid]; bs1s[tid] = bs1[tid]; bs2s[tid] = bs2[tid]; }
    __syncthreads();

    // P1: own_e (row = tid/4, 16 cols per thread)
    {
        int row = tid >> 2;
        int c0 = (tid & 3) * 16;
        const float* s0 = S0 + (size_t)(gb0 + row) * 6;
        float x0 = s0[0], x1 = s0[1], x2 = s0[2], x3 = s0[3], x4 = s0[4], x5 = s0[5];
#pragma unroll
        for (int j = 0; j < 16; j++) {
            int c = c0 + j;
            float a = b0s[c];
            a = fmaf(x0, W0s[c], a);
            a = fmaf(x1, W0s[64 + c], a);
            a = fmaf(x2, W0s[128 + c], a);
            a = fmaf(x3, W0s[192 + c], a);
            a = fmaf(x4, W0s[256 + c], a);
            a = fmaf(x5, W0s[320 + c], a);
            a = fmaxf(a, 0.f);
            own[row * 65 + c] = a;
            g_concat[(size_t)(gb0 + row) * 192 + c] = a;
        }
    }

    // P2: E1 = relu(S2 @ Ws1 + bs1) + mask (2 rows/thread)
    for (int rr = tid; rr < 512; rr += 256) {
        const float* s2 = S2 + ((size_t)gb0 * 8 + rr) * 7;
        float y0 = s2[0], y1 = s2[1], y2 = s2[2], y3 = s2[3], y4 = s2[4], y5 = s2[5], y6 = s2[6];
        float ssum = y0 + y1 + y2 + y3 + y4 + y5 + y6;
        mk[rr] = (ssum != 0.f) ? 1.f : 0.f;
#pragma unroll
        for (int j = 0; j < 64; j++) {
            float a = bs1s[j];
            a = fmaf(y0, Ws1s[j], a);
            a = fmaf(y1, Ws1s[64 + j], a);
            a = fmaf(y2, Ws1s[128 + j], a);
            a = fmaf(y3, Ws1s[192 + j], a);
            a = fmaf(y4, Ws1s[256 + j], a);
            a = fmaf(y5, Ws1s[320 + j], a);
            a = fmaf(y6, Ws1s[384 + j], a);
            E[rr * 65 + j] = fmaxf(a, 0.f);
        }
    }

    // P3: E2 = relu(E1 @ Ws2 + bs2) in place (same thread owns its rows)
    for (int rr = tid; rr < 512; rr += 256) {
        float x[64];
#pragma unroll
        for (int k = 0; k < 64; k++) x[k] = E[rr * 65 + k];
#pragma unroll 1
        for (int j0 = 0; j0 < 64; j0 += 8) {
            u64 a0 = pack2(bs2s[j0 + 0], bs2s[j0 + 1]);
            u64 a1 = pack2(bs2s[j0 + 2], bs2s[j0 + 3]);
            u64 a2 = pack2(bs2s[j0 + 4], bs2s[j0 + 5]);
            u64 a3 = pack2(bs2s[j0 + 6], bs2s[j0 + 7]);
#pragma unroll
            for (int k = 0; k < 64; k++) {
                u64 xx = pack2(x[k], x[k]);
                const u64* w = reinterpret_cast<const u64*>(&Ws2s[k * 64 + j0]);
                ffma2(a0, xx, w[0]); ffma2(a1, xx, w[1]);
                ffma2(a2, xx, w[2]); ffma2(a3, xx, w[3]);
            }
            float lo, hi;
            unpack2(a0, lo, hi); E[rr * 65 + j0 + 0] = fmaxf(lo, 0.f); E[rr * 65 + j0 + 1] = fmaxf(hi, 0.f);
            unpack2(a1, lo, hi); E[rr * 65 + j0 + 2] = fmaxf(lo, 0.f); E[rr * 65 + j0 + 3] = fmaxf(hi, 0.f);
            unpack2(a2, lo, hi); E[rr * 65 + j0 + 4] = fmaxf(lo, 0.f); E[rr * 65 + j0 + 5] = fmaxf(hi, 0.f);
            unpack2(a3, lo, hi); E[rr * 65 + j0 + 6] = fmaxf(lo, 0.f); E[rr * 65 + j0 + 7] = fmaxf(hi, 0.f);
        }
    }
    __syncthreads();

    // P4: t = own_e @ M (row = tid&63, 16 cols per thread)
    {
        int row = tid & 63;
        int c0 = (tid >> 6) * 16;
        u64 acc[8];
#pragma unroll
        for (int jj = 0; jj < 8; jj++) acc[jj] = 0ull;
#pragma unroll
        for (int k = 0; k < 64; k++) {
            float xv = own[row * 65 + k];
            u64 xx = pack2(xv, xv);
            const u64* w = reinterpret_cast<const u64*>(&Ms[k * 64 + c0]);
#pragma unroll
            for (int jj = 0; jj < 8; jj++) ffma2(acc[jj], xx, w[jj]);
        }
#pragma unroll
        for (int jj = 0; jj < 8; jj++) {
            float lo, hi; unpack2(acc[jj], lo, hi);
            tt[row * 65 + c0 + 2 * jj]     = lo;
            tt[row * 65 + c0 + 2 * jj + 1] = hi;
        }
    }
    __syncthreads();

    // P5: scores (masked)
    for (int idx = tid; idx < 512; idx += 256) {
        int lb = idx >> 3;
        float s = 0.f;
#pragma unroll
        for (int k = 0; k < 64; k++) s = fmaf(tt[lb * 65 + k], E[idx * 65 + k], s);
        sc[idx] = (mk[idx] != 0.f) ? (s * 0.125f) : __int_as_float(0xff800000);
    }
    __syncthreads();

    // P6: softmax over n=8 (one thread per row; slot 0 always valid)
    if (tid < 64) {
        float m = __int_as_float(0xff800000);
#pragma unroll
        for (int n = 0; n < 8; n++) m = fmaxf(m, sc[tid * 8 + n]);
        float e[8]; float ssum = 0.f;
#pragma unroll
        for (int n = 0; n < 8; n++) { float v = expf(sc[tid * 8 + n] - m); e[n] = v; ssum += v; }
        float inv = 1.f / ssum;
#pragma unroll
        for (int n = 0; n < 8; n++) al[tid * 8 + n] = e[n] * inv;
    }
    __syncthreads();

    // P7a: wsum = sum_n alpha_n * E_n  (into tt, t no longer needed)
    {
        int row = tid & 63;
        int c0 = (tid >> 6) * 16;
        float av[8];
#pragma unroll
        for (int n = 0; n < 8; n++) av[n] = al[row * 8 + n];
#pragma unroll
        for (int j = 0; j < 16; j++) {
            float a = 0.f;
#pragma unroll
            for (int n = 0; n < 8; n++) a = fmaf(av[n], E[(row * 8 + n) * 65 + c0 + j], a);
            tt[row * 65 + c0 + j] = a;
        }
    }
    __syncthreads();

    // P7b: v_att = wsum @ Wv -> g_concat[:,128:192]
    {
        int row = tid & 63;
        int c0 = (tid >> 6) * 16;
        u64 acc[8];
#pragma unroll
        for (int jj = 0; jj < 8; jj++) acc[jj] = 0ull;
#pragma unroll
        for (int k = 0; k < 64; k++) {
            float xv = tt[row * 65 + k];
            u64 xx = pack2(xv, xv);
            const u64* w = reinterpret_cast<const u64*>(&Wvs[k * 64 + c0]);
#pragma unroll
            for (int jj = 0; jj < 8; jj++) ffma2(acc[jj], xx, w[jj]);
        }
        size_t base = (size_t)(gb0 + row) * 192 + 128 + c0;
#pragma unroll
        for (int jj = 0; jj < 8; jj++) {
            float lo, hi; unpack2(acc[jj], lo, hi);
            g_concat[base + 2 * jj]     = lo;
            g_concat[base + 2 * jj + 1] = hi;
        }
    }
}

// ---------------------------------------------------------------------------
// K3b: h2 = relu(g_h @ Wc2 + bc2); out = tanh(h2 @ Wc3 + bc3)
// 64 rows per block.
// ---------------------------------------------------------------------------
__global__ __launch_bounds__(256)
void k_head2(const float* __restrict__ Wc2, const float* __restrict__ bc2,
             const float* __restrict__ Wc3, const float* __restrict__ bc3,
             float* __restrict__ out) {
    __shared__ float As[16 * 64];
    __shared__ float Bs[16 * 128];
    __shared__ float Hs[64 * 129];
    __shared__ float W3s[256];
    __shared__ float b3s[2];
    const int tid = threadIdx.x;
    const int row0 = blockIdx.x * 64;

    W3s[tid] = Wc3[tid & 255];
    if (tid < 2) b3s[tid] = bc3[tid];

    const int m0 = (tid >> 5) * 8;
    const int c0 = (tid & 31) * 4;
    u64 acc[4][4];
#pragma unroll
    for (int i = 0; i < 4; i++)
#pragma unroll
        for (int j = 0; j < 4; j++) acc[i][j] = 0ull;

    for (int k0 = 0; k0 < 128; k0 += 16) {
        {
            int m = tid >> 2, kq = tid & 3;
            float4 v = *reinterpret_cast<const float4*>(
                &g_h[(size_t)(row0 + m) * 128 + k0 + kq * 4]);
            As[(kq * 4 + 0) * 64 + m] = v.x;
            As[(kq * 4 + 1) * 64 + m] = v.y;
            As[(kq * 4 + 2) * 64 + m] = v.z;
            As[(kq * 4 + 3) * 64 + m] = v.w;
        }
#pragma unroll
        for (int l = 0; l < 2; l++) {
            int idx = tid + l * 256;
            int kk = idx >> 5, jq = idx & 31;
            *reinterpret_cast<float4*>(&Bs[kk * 128 + jq * 4]) =
                *reinterpret_cast<const float4*>(&Wc2[(size_t)(k0 + kk) * 128 + jq * 4]);
        }
        __syncthreads();
#pragma unroll
        for (int kk = 0; kk < 16; kk++) {
            const float* ar = &As[kk * 64 + m0];
            u64 a0 = *reinterpret_cast<const u64*>(ar + 0);
            u64 a1 = *reinterpret_cast<const u64*>(ar + 2);
            u64 a2 = *reinterpret_cast<const u64*>(ar + 4);
            u64 a3 = *reinterpret_cast<const u64*>(ar + 6);
            float4 b = *reinterpret_cast<const float4*>(&Bs[kk * 128 + c0]);
            u64 b0p = pack2(b.x, b.x), b1p = pack2(b.y, b.y);
            u64 b2p = pack2(b.z, b.z), b3p = pack2(b.w, b.w);
            ffma2(acc[0][0], a0, b0p); ffma2(acc[0][1], a0, b1p);
            ffma2(acc[0][2], a0, b2p); ffma2(acc[0][3], a0, b3p);
            ffma2(acc[1][0], a1, b0p); ffma2(acc[1][1], a1, b1p);
            ffma2(acc[1][2], a1, b2p); ffma2(acc[1][3], a1, b3p);
            ffma2(acc[2][0], a2, b0p); ffma2(acc[2][1], a2, b1p);
            ffma2(acc[2][2], a2, b2p); ffma2(acc[2][3], a2, b3p);
            ffma2(acc[3][0], a3, b0p); ffma2(acc[3][1], a3, b1p);
            ffma2(acc[3][2], a3, b2p); ffma2(acc[3][3], a3, b3p);
        }
        __syncthreads();
    }
#pragma unroll
    for (int i = 0; i < 4; i++) {
#pragma unroll
        for (int j = 0; j < 4; j++) {
            float lo, hi; unpack2(acc[i][j], lo, hi);
            float bb = __ldg(&bc2[c0 + j]);
            Hs[(m0 + 2 * i) * 129 + c0 + j]     = fmaxf(lo + bb, 0.f);
            Hs[(m0 + 2 * i + 1) * 129 + c0 + j] = fmaxf(hi + bb, 0.f);
        }
    }
    __syncthreads();
    if (tid < 128) {
        int row = tid >> 1, a = tid & 1;
        float s = b3s[a];
#pragma unroll
        for (int k = 0; k < 128; k++) s = fmaf(Hs[row * 129 + k], W3s[k * 2 + a], s);
        out[(size_t)(row0 + row) * 2 + a] = tanhf(s);
    }
}

// ---------------------------------------------------------------------------
// kernel_launch
// ---------------------------------------------------------------------------
extern "C" void kernel_launch(void* const* d_in, const int* in_sizes, int n_in,
                              void* d_out, int out_size) {
    const float* S0  = (const float*)d_in[0];
    const float* S1  = (const float*)d_in[1];
    const float* S2  = (const float*)d_in[2];
    const float* W0  = (const float*)d_in[3];
    const float* b0  = (const float*)d_in[4];
    const float* Wg  = (const float*)d_in[5];
    const float* bg  = (const float*)d_in[6];
    const float* Ws1 = (const float*)d_in[7];
    const float* bs1 = (const float*)d_in[8];
    const float* Ws2 = (const float*)d_in[9];
    const float* bs2 = (const float*)d_in[10];
    const float* Wq  = (const float*)d_in[11];
    const float* Wk  = (const float*)d_in[12];
    const float* Wv  = (const float*)d_in[13];
    const float* Wc1 = (const float*)d_in[14];
    const float* bc1 = (const float*)d_in[15];
    const float* Wc2 = (const float*)d_in[16];
    const float* bc2 = (const float*)d_in[17];
    const float* Wc3 = (const float*)d_in[18];
    const float* bc3 = (const float*)d_in[19];
    float* out = (float*)d_out;

    void* pC; cudaGetSymbolAddress(&pC, g_concat);
    void* pH; cudaGetSymbolAddress(&pH, g_h);
    float* C = (float*)pC;
    float* Hb = (float*)pH;

    cudaFuncSetAttribute(k_attn, cudaFuncAttributeMaxDynamicSharedMemorySize,
                         ATTN_SMEM_BYTES);

    // K0: M = Wq @ Wk^T
    k_prep<<<16, 256>>>(Wq, Wk);
    // K1: env_e = relu(state1 @ Wg + bg) -> g_concat[:, 64:128]
    k_gemm<1024, 1024, 64><<<dim3(B_TOT / 128, 1), 256>>>(S1, Wg, bg, C, 192, 64);
    // K2: own_e / intru MLP / attention -> g_concat[:, 0:64] and [:, 128:192]
    k_attn<<<B_TOT / 64, 256, ATTN_SMEM_BYTES>>>(S0, S2, W0, b0, Ws1, bs1,
                                                 Ws2, bs2, Wv);
    // K3a: h1 = relu(concat @ Wc1 + bc1)
    k_gemm<192, 192, 128><<<dim3(B_TOT / 128, 2), 256>>>(C, Wc1, bc1, Hb, 128, 0);
    // K3b: out = tanh(relu(h1 @ Wc2 + bc2) @ Wc3 + bc3)
    k_head2<<<B_TOT / 64, 256>>>(Wc2, bc2, Wc3, bc3, out);
}

// round 3
// speedup vs baseline: 1.0937x; 1.0937x over previous
#include <cuda_runtime.h>
#include <cuda_bf16.h>
#include <math.h>
#include <stdint.h>

// ---------------------------------------------------------------------------
// Problem constants
// ---------------------------------------------------------------------------
#define B_TOT 65536
// H=64, HC=128, N=8, OBS0=6, OBS1=1024, OBS2=7, NA=2

typedef unsigned long long u64;
typedef unsigned short u16;
typedef unsigned int u32;

// ---------------------------------------------------------------------------
// Packed f32x2 helpers (FFMA2) — used by k_attn
// ---------------------------------------------------------------------------
static __device__ __forceinline__ u64 pack2(float lo, float hi) {
    u64 r; asm("mov.b64 %0,{%1,%2};" : "=l"(r) : "f"(lo), "f"(hi)); return r;
}
static __device__ __forceinline__ void unpack2(u64 v, float& lo, float& hi) {
    asm("mov.b64 {%0,%1},%2;" : "=f"(lo), "=f"(hi) : "l"(v));
}
static __device__ __forceinline__ void ffma2(u64& d, u64 a, u64 b) {
    asm("fma.rn.f32x2 %0,%1,%2,%0;" : "+l"(d) : "l"(a), "l"(b));
}

// ---------------------------------------------------------------------------
// bf16 split + warp-level HMMA (mma.sync — NOT arch-'a' gated)
// ---------------------------------------------------------------------------
static __device__ __forceinline__ void bf_split(float x, u16& h, u16& l) {
    __nv_bfloat16 hb = __float2bfloat16(x);
    float r = x - __bfloat162float(hb);
    __nv_bfloat16 lb = __float2bfloat16(r);
    h = __bfloat16_as_ushort(hb);
    l = __bfloat16_as_ushort(lb);
}
static __device__ __forceinline__ void mma16816(float* c, const u32* a, const u32* b) {
    asm volatile(
        "mma.sync.aligned.m16n8k16.row.col.f32.bf16.bf16.f32 "
        "{%0,%1,%2,%3}, {%4,%5,%6,%7}, {%8,%9}, {%0,%1,%2,%3};"
        : "+f"(c[0]), "+f"(c[1]), "+f"(c[2]), "+f"(c[3])
        : "r"(a[0]), "r"(a[1]), "r"(a[2]), "r"(a[3]), "r"(b[0]), "r"(b[1]));
}

// ---------------------------------------------------------------------------
// Scratch (static device globals: allocation-free)
// ---------------------------------------------------------------------------
__device__ float g_M[64 * 64];                        // Wq @ Wk^T
__device__ float g_concat[(size_t)B_TOT * 192];       // [own | env | v_att]
__device__ float g_h[(size_t)B_TOT * 128];            // hidden after Wc1
__device__ float g_h2[(size_t)B_TOT * 128];           // hidden after Wc2

// ---------------------------------------------------------------------------
// K0: M[i][j] = sum_h Wq[i][h] * Wk[j][h]
// ---------------------------------------------------------------------------
__global__ void k_prep(const float* __restrict__ Wq, const float* __restrict__ Wk) {
    int e = blockIdx.x * 256 + threadIdx.x;
    if (e < 4096) {
        int i = e >> 6, j = e & 63;
        float s = 0.f;
#pragma unroll
        for (int h = 0; h < 64; h++) s = fmaf(Wq[i * 64 + h], Wk[j * 64 + h], s);
        g_M[e] = s;
    }
}

// ---------------------------------------------------------------------------
// Tensor-core GEMM (bf16x3 split, mma.sync m16n8k16):
//   C[r, ccol0+bcol+c] = relu(sum_k A[r,k] * Bw[k, bcol+c] + bias[bcol+c])
// CTA: 128 rows x 64 cols, K chunks of 64. 8 warps (4m x 2n), warp tile 32x32.
// smem: Ah/Al [128][72] bf16, Bh/Bl(=B^T) [64][72] bf16, bias 64 f32.
// ---------------------------------------------------------------------------
#define MMA_SROW 72
#define MMA_SMEM_BYTES (128*72*2*2 + 64*72*2*2 + 64*4)   // 55552

template <int KTOT, int LDA, int LDB>
__global__ __launch_bounds__(256)
void k_mma(const float* __restrict__ A, const float* __restrict__ Bw,
           const float* __restrict__ bias, float* __restrict__ C,
           int ldc, int ccol0) {
    extern __shared__ char smemraw[];
    u16* Ah = (u16*)smemraw;            // [128][72]
    u16* Al = Ah + 128 * MMA_SROW;
    u16* Bh = Al + 128 * MMA_SROW;      // [64][72] (B^T: [n][k])
    u16* Bl = Bh + 64 * MMA_SROW;
    float* bs = (float*)(Bl + 64 * MMA_SROW);

    const int tid = threadIdx.x;
    const int wid = tid >> 5, lane = tid & 31;
    const int row0 = blockIdx.x * 128;
    const int bcol = blockIdx.y * 64;
    const int mwarp = wid >> 1, nwarp = wid & 1;
    const int g = lane >> 2, t = lane & 3;

    if (tid < 64) bs[tid] = bias[bcol + tid];

    float acc[2][4][4];
#pragma unroll
    for (int mt = 0; mt < 2; mt++)
#pragma unroll
        for (int nt = 0; nt < 4; nt++)
#pragma unroll
            for (int r = 0; r < 4; r++) acc[mt][nt][r] = 0.f;

    for (int c = 0; c < KTOT / 64; c++) {
        const int k0 = c * 64;
        // ---- A chunk [128 x 64] fp32 -> bf16 hi/lo ----
        {
            const int m = tid >> 1, h = tid & 1;
            const float* src = A + (size_t)(row0 + m) * LDA + k0 + h * 32;
            u16* dh = Ah + m * MMA_SROW + h * 32;
            u16* dl = Al + m * MMA_SROW + h * 32;
#pragma unroll
            for (int q = 0; q < 8; q++) {
                float4 v = *reinterpret_cast<const float4*>(src + q * 4);
                u16 h0, l0, h1, l1, h2, l2, h3, l3;
                bf_split(v.x, h0, l0); bf_split(v.y, h1, l1);
                bf_split(v.z, h2, l2); bf_split(v.w, h3, l3);
                uint2 uh, ul;
                uh.x = (u32)h0 | ((u32)h1 << 16); uh.y = (u32)h2 | ((u32)h3 << 16);
                ul.x = (u32)l0 | ((u32)l1 << 16); ul.y = (u32)l2 | ((u32)l3 << 16);
                *reinterpret_cast<uint2*>(dh + q * 4) = uh;
                *reinterpret_cast<uint2*>(dl + q * 4) = ul;
            }
        }
        // ---- B chunk: Bw[k0:k0+64, bcol:bcol+64] -> B^T[n][k] bf16 hi/lo ----
        {
            const int n = tid & 63, kb = (tid >> 6) * 16;
            const float* wsrc = Bw + (size_t)(k0 + kb) * LDB + bcol + n;
#pragma unroll
            for (int i = 0; i < 16; i++) {
                u16 hh, ll;
                bf_split(wsrc[(size_t)i * LDB], hh, ll);
                Bh[n * MMA_SROW + kb + i] = hh;
                Bl[n * MMA_SROW + kb + i] = ll;
            }
        }
        __syncthreads();

#pragma unroll
        for (int k16 = 0; k16 < 4; k16++) {
            const int kk = k16 * 16;
            u32 ahf[2][4], alf[2][4], bhf[4][2], blf[4][2];
#pragma unroll
            for (int mt = 0; mt < 2; mt++) {
                int rb = mwarp * 32 + mt * 16 + g;
                const u16* p0 = Ah + rb * MMA_SROW + kk + t * 2;
                const u16* p1 = p0 + 8 * MMA_SROW;
                ahf[mt][0] = *reinterpret_cast<const u32*>(p0);
                ahf[mt][1] = *reinterpret_cast<const u32*>(p1);
                ahf[mt][2] = *reinterpret_cast<const u32*>(p0 + 8);
                ahf[mt][3] = *reinterpret_cast<const u32*>(p1 + 8);
                const u16* q0 = p0 + 128 * MMA_SROW;  // Al
                const u16* q1 = p1 + 128 * MMA_SROW;
                alf[mt][0] = *reinterpret_cast<const u32*>(q0);
                alf[mt][1] = *reinterpret_cast<const u32*>(q1);
                alf[mt][2] = *reinterpret_cast<const u32*>(q0 + 8);
                alf[mt][3] = *reinterpret_cast<const u32*>(q1 + 8);
            }
#pragma unroll
            for (int nt = 0; nt < 4; nt++) {
                int nb = nwarp * 32 + nt * 8 + g;
                const u16* p0 = Bh + nb * MMA_SROW + kk + t * 2;
                bhf[nt][0] = *reinterpret_cast<const u32*>(p0);
                bhf[nt][1] = *reinterpret_cast<const u32*>(p0 + 8);
                const u16* q0 = p0 + 64 * MMA_SROW;  // Bl
                blf[nt][0] = *reinterpret_cast<const u32*>(q0);
                blf[nt][1] = *reinterpret_cast<const u32*>(q0 + 8);
            }
#pragma unroll
            for (int mt = 0; mt < 2; mt++)
#pragma unroll
                for (int nt = 0; nt < 4; nt++) {
                    mma16816(acc[mt][nt], ahf[mt], bhf[nt]);
                    mma16816(acc[mt][nt], ahf[mt], blf[nt]);
                    mma16816(acc[mt][nt], alf[mt], bhf[nt]);
                }
        }
        __syncthreads();
    }

    // ---- epilogue: bias + relu, float2 stores ----
#pragma unroll
    for (int mt = 0; mt < 2; mt++) {
#pragma unroll
        for (int nt = 0; nt < 4; nt++) {
            int r = row0 + mwarp * 32 + mt * 16 + g;
            int cl = nwarp * 32 + nt * 8 + t * 2;
            int cg = ccol0 + bcol + cl;
            float b0v = bs[cl], b1v = bs[cl + 1];
            float2 v0, v1;
            v0.x = fmaxf(acc[mt][nt][0] + b0v, 0.f);
            v0.y = fmaxf(acc[mt][nt][1] + b1v, 0.f);
            v1.x = fmaxf(acc[mt][nt][2] + b0v, 0.f);
            v1.y = fmaxf(acc[mt][nt][3] + b1v, 0.f);
            *reinterpret_cast<float2*>(C + (size_t)r * ldc + cg) = v0;
            *reinterpret_cast<float2*>(C + (size_t)(r + 8) * ldc + cg) = v1;
        }
    }
}

// ---------------------------------------------------------------------------
// K2: fused attention path (64 batch rows / block, 256 threads)
// ---------------------------------------------------------------------------
#define ATTN_SMEM_FLOATS (384 + 448 + 4096 * 3 + 64 * 65 * 2 + 512 * 65 + 512 * 3 + 64 * 3)
#define ATTN_SMEM_BYTES  (ATTN_SMEM_FLOATS * 4)

__global__ __launch_bounds__(256)
void k_attn(const float* __restrict__ S0, const float* __restrict__ S2,
            const float* __restrict__ W0, const float* __restrict__ b0,
            const float* __restrict__ Ws1, const float* __restrict__ bs1,
            const float* __restrict__ Ws2, const float* __restrict__ bs2,
            const float* __restrict__ Wv) {
    extern __shared__ float sm[];
    float* W0s  = sm;              // 384
    float* Ws1s = W0s + 384;       // 448
    float* Ws2s = Ws1s + 448;      // 4096
    float* Ms   = Ws2s + 4096;     // 4096
    float* Wvs  = Ms + 4096;       // 4096
    float* own  = Wvs + 4096;      // 64*65
    float* tt   = own + 64 * 65;   // 64*65
    float* E    = tt + 64 * 65;    // 512*65
    float* sc   = E + 512 * 65;    // 512
    float* al   = sc + 512;        // 512
    float* mk   = al + 512;        // 512
    float* b0s  = mk + 512;        // 64
    float* bs1s = b0s + 64;        // 64
    float* bs2s = bs1s + 64;       // 64

    const int tid = threadIdx.x;
    const int gb0 = blockIdx.x * 64;

    for (int i = tid; i < 384; i += 256) W0s[i] = W0[i];
    for (int i = tid; i < 448; i += 256) Ws1s[i] = Ws1[i];
    for (int i = tid; i < 4096; i += 256) {
        Ws2s[i] = Ws2[i]; Ms[i] = g_M[i]; Wvs[i] = Wv[i];
    }
    if (tid < 64) { b0s[tid] = b0[tid]; bs1s[tid] = bs1[tid]; bs2s[tid] = bs2[tid]; }
    __syncthreads();

    // P1: own_e
    {
        int row = tid >> 2;
        int c0 = (tid & 3) * 16;
        const float* s0 = S0 + (size_t)(gb0 + row) * 6;
        float x0 = s0[0], x1 = s0[1], x2 = s0[2], x3 = s0[3], x4 = s0[4], x5 = s0[5];
#pragma unroll
        for (int j = 0; j < 16; j++) {
            int c = c0 + j;
            float a = b0s[c];
            a = fmaf(x0, W0s[c], a);
            a = fmaf(x1, W0s[64 + c], a);
            a = fmaf(x2, W0s[128 + c], a);
            a = fmaf(x3, W0s[192 + c], a);
            a = fmaf(x4, W0s[256 + c], a);
            a = fmaf(x5, W0s[320 + c], a);
            a = fmaxf(a, 0.f);
            own[row * 65 + c] = a;
            g_concat[(size_t)(gb0 + row) * 192 + c] = a;
        }
    }

    // P2: E1 = relu(S2 @ Ws1 + bs1) + mask
    for (int rr = tid; rr < 512; rr += 256) {
        const float* s2 = S2 + ((size_t)gb0 * 8 + rr) * 7;
        float y0 = s2[0], y1 = s2[1], y2 = s2[2], y3 = s2[3], y4 = s2[4], y5 = s2[5], y6 = s2[6];
        float ssum = y0 + y1 + y2 + y3 + y4 + y5 + y6;
        mk[rr] = (ssum != 0.f) ? 1.f : 0.f;
#pragma unroll
        for (int j = 0; j < 64; j++) {
            float a = bs1s[j];
            a = fmaf(y0, Ws1s[j], a);
            a = fmaf(y1, Ws1s[64 + j], a);
            a = fmaf(y2, Ws1s[128 + j], a);
            a = fmaf(y3, Ws1s[192 + j], a);
            a = fmaf(y4, Ws1s[256 + j], a);
            a = fmaf(y5, Ws1s[320 + j], a);
            a = fmaf(y6, Ws1s[384 + j], a);
            E[rr * 65 + j] = fmaxf(a, 0.f);
        }
    }

    // P3: E2 = relu(E1 @ Ws2 + bs2)
    for (int rr = tid; rr < 512; rr += 256) {
        float x[64];
#pragma unroll
        for (int k = 0; k < 64; k++) x[k] = E[rr * 65 + k];
#pragma unroll 1
        for (int j0 = 0; j0 < 64; j0 += 8) {
            u64 a0 = pack2(bs2s[j0 + 0], bs2s[j0 + 1]);
            u64 a1 = pack2(bs2s[j0 + 2], bs2s[j0 + 3]);
            u64 a2 = pack2(bs2s[j0 + 4], bs2s[j0 + 5]);
            u64 a3 = pack2(bs2s[j0 + 6], bs2s[j0 + 7]);
#pragma unroll
            for (int k = 0; k < 64; k++) {
                u64 xx = pack2(x[k], x[k]);
                const u64* w = reinterpret_cast<const u64*>(&Ws2s[k * 64 + j0]);
                ffma2(a0, xx, w[0]); ffma2(a1, xx, w[1]);
                ffma2(a2, xx, w[2]); ffma2(a3, xx, w[3]);
            }
            float lo, hi;
            unpack2(a0, lo, hi); E[rr * 65 + j0 + 0] = fmaxf(lo, 0.f); E[rr * 65 + j0 + 1] = fmaxf(hi, 0.f);
            unpack2(a1, lo, hi); E[rr * 65 + j0 + 2] = fmaxf(lo, 0.f); E[rr * 65 + j0 + 3] = fmaxf(hi, 0.f);
            unpack2(a2, lo, hi); E[rr * 65 + j0 + 4] = fmaxf(lo, 0.f); E[rr * 65 + j0 + 5] = fmaxf(hi, 0.f);
            unpack2(a3, lo, hi); E[rr * 65 + j0 + 6] = fmaxf(lo, 0.f); E[rr * 65 + j0 + 7] = fmaxf(hi, 0.f);
        }
    }
    __syncthreads();

    // P4: t = own_e @ M
    {
        int row = tid & 63;
        int c0 = (tid >> 6) * 16;
        u64 acc[8];
#pragma unroll
        for (int jj = 0; jj < 8; jj++) acc[jj] = 0ull;
#pragma unroll
        for (int k = 0; k < 64; k++) {
            float xv = own[row * 65 + k];
            u64 xx = pack2(xv, xv);
            const u64* w = reinterpret_cast<const u64*>(&Ms[k * 64 + c0]);
#pragma unroll
            for (int jj = 0; jj < 8; jj++) ffma2(acc[jj], xx, w[jj]);
        }
#pragma unroll
        for (int jj = 0; jj < 8; jj++) {
            float lo, hi; unpack2(acc[jj], lo, hi);
            tt[row * 65 + c0 + 2 * jj]     = lo;
            tt[row * 65 + c0 + 2 * jj + 1] = hi;
        }
    }
    __syncthreads();

    // P5: scores (masked)
    for (int idx = tid; idx < 512; idx += 256) {
        int lb = idx >> 3;
        float s = 0.f;
#pragma unroll
        for (int k = 0; k < 64; k++) s = fmaf(tt[lb * 65 + k], E[idx * 65 + k], s);
        sc[idx] = (mk[idx] != 0.f) ? (s * 0.125f) : __int_as_float(0xff800000);
    }
    __syncthreads();

    // P6: softmax over n=8
    if (tid < 64) {
        float m = __int_as_float(0xff800000);
#pragma unroll
        for (int n = 0; n < 8; n++) m = fmaxf(m, sc[tid * 8 + n]);
        float e[8]; float ssum = 0.f;
#pragma unroll
        for (int n = 0; n < 8; n++) { float v = expf(sc[tid * 8 + n] - m); e[n] = v; ssum += v; }
        float inv = 1.f / ssum;
#pragma unroll
        for (int n = 0; n < 8; n++) al[tid * 8 + n] = e[n] * inv;
    }
    __syncthreads();

    // P7a: wsum
    {
        int row = tid & 63;
        int c0 = (tid >> 6) * 16;
        float av[8];
#pragma unroll
        for (int n = 0; n < 8; n++) av[n] = al[row * 8 + n];
#pragma unroll
        for (int j = 0; j < 16; j++) {
            float a = 0.f;
#pragma unroll
            for (int n = 0; n < 8; n++) a = fmaf(av[n], E[(row * 8 + n) * 65 + c0 + j], a);
            tt[row * 65 + c0 + j] = a;
        }
    }
    __syncthreads();

    // P7b: v_att = wsum @ Wv
    {
        int row = tid & 63;
        int c0 = (tid >> 6) * 16;
        u64 acc[8];
#pragma unroll
        for (int jj = 0; jj < 8; jj++) acc[jj] = 0ull;
#pragma unroll
        for (int k = 0; k < 64; k++) {
            float xv = tt[row * 65 + k];
            u64 xx = pack2(xv, xv);
            const u64* w = reinterpret_cast<const u64*>(&Wvs[k * 64 + c0]);
#pragma unroll
            for (int jj = 0; jj < 8; jj++) ffma2(acc[jj], xx, w[jj]);
        }
        size_t base = (size_t)(gb0 + row) * 192 + 128 + c0;
#pragma unroll
        for (int jj = 0; jj < 8; jj++) {
            float lo, hi; unpack2(acc[jj], lo, hi);
            g_concat[base + 2 * jj]     = lo;
            g_concat[base + 2 * jj + 1] = hi;
        }
    }
}

// ---------------------------------------------------------------------------
// K4: out = tanh(g_h2 @ Wc3 + bc3)  (memory-bound head; 1 warp per row)
// ---------------------------------------------------------------------------
__global__ __launch_bounds__(256)
void k_head(const float* __restrict__ Wc3, const float* __restrict__ bc3,
            float* __restrict__ out) {
    __shared__ float W3s[256];
    __shared__ float b3s[2];
    const int tid = threadIdx.x;
    const int wid = tid >> 5, lane = tid & 31;
    W3s[tid] = Wc3[tid];
    if (tid < 2) b3s[tid] = bc3[tid];
    __syncthreads();

    const int row = blockIdx.x * 8 + wid;
    float4 v = *reinterpret_cast<const float4*>(&g_h2[(size_t)row * 128 + lane * 4]);
    float s0 = 0.f, s1 = 0.f;
    int kb = lane * 4;
    s0 = fmaf(v.x, W3s[(kb + 0) * 2 + 0], s0); s1 = fmaf(v.x, W3s[(kb + 0) * 2 + 1], s1);
    s0 = fmaf(v.y, W3s[(kb + 1) * 2 + 0], s0); s1 = fmaf(v.y, W3s[(kb + 1) * 2 + 1], s1);
    s0 = fmaf(v.z, W3s[(kb + 2) * 2 + 0], s0); s1 = fmaf(v.z, W3s[(kb + 2) * 2 + 1], s1);
    s0 = fmaf(v.w, W3s[(kb + 3) * 2 + 0], s0); s1 = fmaf(v.w, W3s[(kb + 3) * 2 + 1], s1);
#pragma unroll
    for (int o = 16; o > 0; o >>= 1) {
        s0 += __shfl_xor_sync(0xffffffffu, s0, o);
        s1 += __shfl_xor_sync(0xffffffffu, s1, o);
    }
    if (lane == 0) {
        float2 o2;
        o2.x = tanhf(s0 + b3s[0]);
        o2.y = tanhf(s1 + b3s[1]);
        *reinterpret_cast<float2*>(out + (size_t)row * 2) = o2;
    }
}

// ---------------------------------------------------------------------------
// kernel_launch
// ---------------------------------------------------------------------------
extern "C" void kernel_launch(void* const* d_in, const int* in_sizes, int n_in,
                              void* d_out, int out_size) {
    const float* S0  = (const float*)d_in[0];
    const float* S1  = (const float*)d_in[1];
    const float* S2  = (const float*)d_in[2];
    const float* W0  = (const float*)d_in[3];
    const float* b0  = (const float*)d_in[4];
    const float* Wg  = (const float*)d_in[5];
    const float* bg  = (const float*)d_in[6];
    const float* Ws1 = (const float*)d_in[7];
    const float* bs1 = (const float*)d_in[8];
    const float* Ws2 = (const float*)d_in[9];
    const float* bs2 = (const float*)d_in[10];
    const float* Wq  = (const float*)d_in[11];
    const float* Wk  = (const float*)d_in[12];
    const float* Wv  = (const float*)d_in[13];
    const float* Wc1 = (const float*)d_in[14];
    const float* bc1 = (const float*)d_in[15];
    const float* Wc2 = (const float*)d_in[16];
    const float* bc2 = (const float*)d_in[17];
    const float* Wc3 = (const float*)d_in[18];
    const float* bc3 = (const float*)d_in[19];
    float* out = (float*)d_out;

    void* pC; cudaGetSymbolAddress(&pC, g_concat);
    void* pH; cudaGetSymbolAddress(&pH, g_h);
    void* pH2; cudaGetSymbolAddress(&pH2, g_h2);
    float* C = (float*)pC;
    float* Hb = (float*)pH;
    float* H2 = (float*)pH2;

    cudaFuncSetAttribute(k_attn, cudaFuncAttributeMaxDynamicSharedMemorySize,
                         ATTN_SMEM_BYTES);
    cudaFuncSetAttribute(k_mma<1024, 1024, 64>,
                         cudaFuncAttributeMaxDynamicSharedMemorySize, MMA_SMEM_BYTES);
    cudaFuncSetAttribute(k_mma<192, 192, 128>,
                         cudaFuncAttributeMaxDynamicSharedMemorySize, MMA_SMEM_BYTES);
    cudaFuncSetAttribute(k_mma<128, 128, 128>,
                         cudaFuncAttributeMaxDynamicSharedMemorySize, MMA_SMEM_BYTES);

    // K0: M = Wq @ Wk^T
    k_prep<<<16, 256>>>(Wq, Wk);
    // K1: env_e = relu(state1 @ Wg + bg) -> g_concat[:, 64:128]   (HMMA bf16x3)
    k_mma<1024, 1024, 64><<<dim3(B_TOT / 128, 1), 256, MMA_SMEM_BYTES>>>(
        S1, Wg, bg, C, 192, 64);
    // K2: own_e / intru MLP / attention -> g_concat[:, 0:64] and [:, 128:192]
    k_attn<<<B_TOT / 64, 256, ATTN_SMEM_BYTES>>>(S0, S2, W0, b0, Ws1, bs1,
                                                 Ws2, bs2, Wv);
    // K3a: h1 = relu(concat @ Wc1 + bc1) -> g_h                    (HMMA bf16x3)
    k_mma<192, 192, 128><<<dim3(B_TOT / 128, 2), 256, MMA_SMEM_BYTES>>>(
        C, Wc1, bc1, Hb, 128, 0);
    // K3b: h2 = relu(h1 @ Wc2 + bc2) -> g_h2                       (HMMA bf16x3)
    k_mma<128, 128, 128><<<dim3(B_TOT / 128, 2), 256, MMA_SMEM_BYTES>>>(
        Hb, Wc2, bc2, H2, 128, 0);
    // K4: out = tanh(h2 @ Wc3 + bc3)
    k_head<<<B_TOT / 8, 256>>>(Wc3, bc3, out);
}

// round 5
// speedup vs baseline: 1.3191x; 1.2061x over previous
#include <cuda_runtime.h>
#include <cuda_bf16.h>
#include <math.h>
#include <stdint.h>

#define B_TOT 65536
// H=64, HC=128, N=8, OBS0=6, OBS1=1024, OBS2=7, NA=2

typedef unsigned long long u64;
typedef unsigned short u16;
typedef unsigned int u32;

// ---------------------------------------------------------------------------
// helpers
// ---------------------------------------------------------------------------
static __device__ __forceinline__ uint32_t smem_u32(const void* p) {
    uint32_t a;
    asm("{ .reg .u64 t; cvta.to.shared.u64 t, %1; cvt.u32.u64 %0, t; }"
        : "=r"(a) : "l"(p));
    return a;
}
static __device__ __forceinline__ void mma16816(float* c, const u32* a, const u32* b) {
    asm volatile(
        "mma.sync.aligned.m16n8k16.row.col.f32.bf16.bf16.f32 "
        "{%0,%1,%2,%3}, {%4,%5,%6,%7}, {%8,%9}, {%0,%1,%2,%3};"
        : "+f"(c[0]), "+f"(c[1]), "+f"(c[2]), "+f"(c[3])
        : "r"(a[0]), "r"(a[1]), "r"(a[2]), "r"(a[3]), "r"(b[0]), "r"(b[1]));
}
static __device__ __forceinline__ void ldsm4(u32& r0, u32& r1, u32& r2, u32& r3, u32 a) {
    asm volatile("ldmatrix.sync.aligned.m8n8.x4.shared.b16 {%0,%1,%2,%3}, [%4];"
                 : "=r"(r0), "=r"(r1), "=r"(r2), "=r"(r3) : "r"(a));
}
static __device__ __forceinline__ void ldsm4t(u32& r0, u32& r1, u32& r2, u32& r3, u32 a) {
    asm volatile("ldmatrix.sync.aligned.m8n8.x4.trans.shared.b16 {%0,%1,%2,%3}, [%4];"
                 : "=r"(r0), "=r"(r1), "=r"(r2), "=r"(r3) : "r"(a));
}
// exact pair split: h2 = {x0>>16, x1>>16}; l2 = bf16rn(residuals), residual exact
static __device__ __forceinline__ void split2(float x0, float x1, u32& h2, u32& l2) {
    u32 b0 = __float_as_uint(x0), b1 = __float_as_uint(x1);
    asm("prmt.b32 %0, %1, %2, 0x7632;" : "=r"(h2) : "r"(b0), "r"(b1));
    float r0 = x0 - __uint_as_float(b0 & 0xffff0000u);
    float r1 = x1 - __uint_as_float(b1 & 0xffff0000u);
    asm("cvt.rn.bf16x2.f32 %0, %1, %2;" : "=r"(l2) : "f"(r1), "f"(r0));
}

// ---------------------------------------------------------------------------
// Scratch (static device globals: allocation-free)
// ---------------------------------------------------------------------------
__device__ float g_M[64 * 64];
__device__ float g_concat[(size_t)B_TOT * 192];
__device__ float g_h[(size_t)B_TOT * 128];
__device__ float g_h2[(size_t)B_TOT * 128];
// pre-split weights, [k][n] row-major bf16
__device__ u16 g_Wgh[1024 * 64],  g_Wgl[1024 * 64];
__device__ u16 g_Wc1h[192 * 128], g_Wc1l[192 * 128];
__device__ u16 g_Wc2h[128 * 128], g_Wc2l[128 * 128];
__device__ u16 g_Ws2h[64 * 64],   g_Ws2l[64 * 64];

// ---------------------------------------------------------------------------
// K0a: M = Wq @ Wk^T
// ---------------------------------------------------------------------------
__global__ void k_prep(const float* __restrict__ Wq, const float* __restrict__ Wk) {
    int e = blockIdx.x * 256 + threadIdx.x;
    if (e < 4096) {
        int i = e >> 6, j = e & 63;
        float s = 0.f;
#pragma unroll
        for (int h = 0; h < 64; h++) s = fmaf(Wq[i * 64 + h], Wk[j * 64 + h], s);
        g_M[e] = s;
    }
}

// ---------------------------------------------------------------------------
// K0b: split weights into bf16 hi/lo (RN split)
// ---------------------------------------------------------------------------
__global__ void k_split(const float* __restrict__ Wg, const float* __restrict__ Wc1,
                        const float* __restrict__ Wc2, const float* __restrict__ Ws2) {
    int i = blockIdx.x * 256 + threadIdx.x;
    const float* src; u16 *dh, *dl; int off;
    if (i < 65536)            { src = Wg;  dh = g_Wgh;  dl = g_Wgl;  off = i; }
    else if (i < 90112)       { src = Wc1; dh = g_Wc1h; dl = g_Wc1l; off = i - 65536; }
    else if (i < 106496)      { src = Wc2; dh = g_Wc2h; dl = g_Wc2l; off = i - 90112; }
    else if (i < 110592)      { src = Ws2; dh = g_Ws2h; dl = g_Ws2l; off = i - 106496; }
    else return;
    float x = src[off];
    __nv_bfloat16 hb = __float2bfloat16(x);
    __nv_bfloat16 lb = __float2bfloat16(x - __bfloat162float(hb));
    dh[off] = __bfloat16_as_ushort(hb);
    dl[off] = __bfloat16_as_ushort(lb);
}

// ---------------------------------------------------------------------------
// Tensor-core GEMM v2: ldmatrix + pre-split B.
//   C[r, ccol0+bcol+c] = relu(sum_k A[r,k]*B[k,bcol+c] + bias[bcol+c])
// CTA 128x64, chunks of k=64. 8 warps (4m x 2n), warp tile 32x32, bf16x3 split.
// smem: Ah/Al [128][72]u16, Bh/Bl [64][72]u16, bias[64]f32  (55.5 KB)
// ---------------------------------------------------------------------------
#define MMA_SMEM_BYTES (55296 + 256)

template <int KTOT, int LDA, int LDB>
__global__ __launch_bounds__(256)
void k_mma(const float* __restrict__ A,
           const u16* __restrict__ Bh_g, const u16* __restrict__ Bl_g,
           const float* __restrict__ bias, float* __restrict__ C,
           int ldc, int ccol0) {
    extern __shared__ char smem[];
    const u32 sbase = smem_u32(smem);
    const u32 ah_b = sbase, al_b = sbase + 18432;
    const u32 bh_b = sbase + 36864, bl_b = sbase + 46080;
    float* bs = (float*)(smem + 55296);

    const int tid = threadIdx.x;
    const int wid = tid >> 5, lane = tid & 31;
    const int row0 = blockIdx.x * 128;
    const int bcol = blockIdx.y * 64;
    const int mwarp = wid >> 1, nwarp = wid & 1;
    const int g = lane >> 2, t = lane & 3;
    const int lr = lane & 15, lc = (lane >> 4) << 3;

    if (tid < 64) bs[tid] = bias[bcol + tid];

    float acc[2][4][4];
#pragma unroll
    for (int mt = 0; mt < 2; mt++)
#pragma unroll
        for (int nt = 0; nt < 4; nt++)
#pragma unroll
            for (int r = 0; r < 4; r++) acc[mt][nt][r] = 0.f;

    const int mrow0 = mwarp * 32, ncol0 = nwarp * 32;

    for (int c = 0; c < KTOT / 64; c++) {
        const int k0 = c * 64;
        // ---- A chunk [128 x 64] fp32 -> split bf16 ----
        {
            const int m = tid >> 1, h = tid & 1;
            const float* src = A + (size_t)(row0 + m) * LDA + k0 + h * 32;
            char* dh = smem + m * 144 + h * 64;
            char* dl = smem + 18432 + m * 144 + h * 64;
#pragma unroll
            for (int q = 0; q < 8; q++) {
                float4 v = *reinterpret_cast<const float4*>(src + q * 4);
                uint2 hh, ll;
                split2(v.x, v.y, hh.x, ll.x);
                split2(v.z, v.w, hh.y, ll.y);
                *reinterpret_cast<uint2*>(dh + q * 8) = hh;
                *reinterpret_cast<uint2*>(dl + q * 8) = ll;
            }
        }
        // ---- B chunk: pre-split bf16, [k][n] -> smem stride 72 ----
        {
            const int kk = tid >> 2, cg = (tid & 3) * 16;
            const u16* sh = Bh_g + (size_t)(k0 + kk) * LDB + bcol + cg;
            const u16* sl = Bl_g + (size_t)(k0 + kk) * LDB + bcol + cg;
            char* dh = smem + 36864 + kk * 144 + cg * 2;
            char* dl = smem + 46080 + kk * 144 + cg * 2;
            *reinterpret_cast<uint4*>(dh)      = *reinterpret_cast<const uint4*>(sh);
            *reinterpret_cast<uint4*>(dh + 16) = *reinterpret_cast<const uint4*>(sh + 8);
            *reinterpret_cast<uint4*>(dl)      = *reinterpret_cast<const uint4*>(sl);
            *reinterpret_cast<uint4*>(dl + 16) = *reinterpret_cast<const uint4*>(sl + 8);
        }
        __syncthreads();

#pragma unroll
        for (int k16 = 0; k16 < 4; k16++) {
            const int kk = k16 * 16;
            u32 bh[8], bl[8];
            ldsm4t(bh[0], bh[1], bh[2], bh[3], bh_b + ((kk + lr) * 72 + ncol0 + lc) * 2);
            ldsm4t(bh[4], bh[5], bh[6], bh[7], bh_b + ((kk + lr) * 72 + ncol0 + 16 + lc) * 2);
            ldsm4t(bl[0], bl[1], bl[2], bl[3], bl_b + ((kk + lr) * 72 + ncol0 + lc) * 2);
            ldsm4t(bl[4], bl[5], bl[6], bl[7], bl_b + ((kk + lr) * 72 + ncol0 + 16 + lc) * 2);
#pragma unroll
            for (int mt = 0; mt < 2; mt++) {
                u32 ah[4], al[4];
                ldsm4(ah[0], ah[1], ah[2], ah[3],
                      ah_b + ((mrow0 + mt * 16 + lr) * 72 + kk + lc) * 2);
                ldsm4(al[0], al[1], al[2], al[3],
                      al_b + ((mrow0 + mt * 16 + lr) * 72 + kk + lc) * 2);
#pragma unroll
                for (int nt = 0; nt < 4; nt++) {
                    mma16816(acc[mt][nt], ah, &bh[nt * 2]);
                    mma16816(acc[mt][nt], ah, &bl[nt * 2]);
                    mma16816(acc[mt][nt], al, &bh[nt * 2]);
                }
            }
        }
        __syncthreads();
    }

#pragma unroll
    for (int mt = 0; mt < 2; mt++) {
#pragma unroll
        for (int nt = 0; nt < 4; nt++) {
            int r = row0 + mrow0 + mt * 16 + g;
            int cl = ncol0 + nt * 8 + t * 2;
            int cg = ccol0 + bcol + cl;
            float b0v = bs[cl], b1v = bs[cl + 1];
            float2 v0, v1;
            v0.x = fmaxf(acc[mt][nt][0] + b0v, 0.f);
            v0.y = fmaxf(acc[mt][nt][1] + b1v, 0.f);
            v1.x = fmaxf(acc[mt][nt][2] + b0v, 0.f);
            v1.y = fmaxf(acc[mt][nt][3] + b1v, 0.f);
            *reinterpret_cast<float2*>(C + (size_t)r * ldc + cg) = v0;
            *reinterpret_cast<float2*>(C + (size_t)(r + 8) * ldc + cg) = v1;
        }
    }
}

// ---------------------------------------------------------------------------
// K2 v2: fused attention, 32 batch rows (256 neighbor rows)/block, 256 thr.
// P3 (E2 = relu(E1@Ws2)) on tensor cores with split bf16.
// ---------------------------------------------------------------------------
#define AT_MS    0
#define AT_WVS   16384
#define AT_OWN   32768      // [32][65] f32
#define AT_TT    41088      // [32][65] f32
#define AT_W0    49408      // 384 f32
#define AT_WS1   50944      // 448 f32
#define AT_B0    52736      // 64 f32
#define AT_BS1   52992
#define AT_BS2   53248
#define AT_SC    53504      // 256 f32
#define AT_AL    54528
#define AT_MK    55552
#define AT_E1H   56576      // [256][72] u16
#define AT_E1L   93440
#define AT_WS2H  130304     // [64][72] u16
#define AT_WS2L  139520
#define AT_E2    148736     // [256][66] f32
#define ATTN_SMEM_BYTES (148736 + 256 * 66 * 4)   // 216320

__global__ __launch_bounds__(256)
void k_attn2(const float* __restrict__ S0, const float* __restrict__ S2,
             const float* __restrict__ W0, const float* __restrict__ b0,
             const float* __restrict__ Ws1, const float* __restrict__ bs1,
             const float* __restrict__ bs2, const float* __restrict__ Wv) {
    extern __shared__ char smem[];
    float* Ms   = (float*)(smem + AT_MS);
    float* Wvs  = (float*)(smem + AT_WVS);
    float* own  = (float*)(smem + AT_OWN);
    float* tt   = (float*)(smem + AT_TT);
    float* W0s  = (float*)(smem + AT_W0);
    float* Ws1s = (float*)(smem + AT_WS1);
    float* b0s  = (float*)(smem + AT_B0);
    float* bs1s = (float*)(smem + AT_BS1);
    float* bs2s = (float*)(smem + AT_BS2);
    float* sc   = (float*)(smem + AT_SC);
    float* al   = (float*)(smem + AT_AL);
    float* mk   = (float*)(smem + AT_MK);
    float* E2   = (float*)(smem + AT_E2);
    const u32 sbase = smem_u32(smem);
    const u32 e1h_b = sbase + AT_E1H, e1l_b = sbase + AT_E1L;
    const u32 wsh_b = sbase + AT_WS2H, wsl_b = sbase + AT_WS2L;

    const int tid = threadIdx.x;
    const int wid = tid >> 5, lane = tid & 31;
    const int gb0 = blockIdx.x * 32;

    for (int i = tid; i < 4096; i += 256) { Ms[i] = g_M[i]; Wvs[i] = Wv[i]; }
    for (int i = tid; i < 384; i += 256) W0s[i] = W0[i];
    for (int i = tid; i < 448; i += 256) Ws1s[i] = Ws1[i];
    if (tid < 64) { b0s[tid] = b0[tid]; bs1s[tid] = bs1[tid]; bs2s[tid] = bs2[tid]; }
    {
        const int kk = tid >> 2, cg = (tid & 3) * 16;
        const u16* sh = g_Ws2h + kk * 64 + cg;
        const u16* sl = g_Ws2l + kk * 64 + cg;
        char* dh = smem + AT_WS2H + kk * 144 + cg * 2;
        char* dl = smem + AT_WS2L + kk * 144 + cg * 2;
        *reinterpret_cast<uint4*>(dh)      = *reinterpret_cast<const uint4*>(sh);
        *reinterpret_cast<uint4*>(dh + 16) = *reinterpret_cast<const uint4*>(sh + 8);
        *reinterpret_cast<uint4*>(dl)      = *reinterpret_cast<const uint4*>(sl);
        *reinterpret_cast<uint4*>(dl + 16) = *reinterpret_cast<const uint4*>(sl + 8);
    }
    __syncthreads();

    // P1: own_e (32 rows, 8 cols/thread)
    {
        const int row = tid >> 3, c0 = (tid & 7) * 8;
        const float* s0 = S0 + (size_t)(gb0 + row) * 6;
        float x0 = s0[0], x1 = s0[1], x2 = s0[2], x3 = s0[3], x4 = s0[4], x5 = s0[5];
        float* og = g_concat + (size_t)(gb0 + row) * 192;
#pragma unroll
        for (int j = 0; j < 8; j++) {
            int c = c0 + j;
            float a = b0s[c];
            a = fmaf(x0, W0s[c], a);
            a = fmaf(x1, W0s[64 + c], a);
            a = fmaf(x2, W0s[128 + c], a);
            a = fmaf(x3, W0s[192 + c], a);
            a = fmaf(x4, W0s[256 + c], a);
            a = fmaf(x5, W0s[320 + c], a);
            a = fmaxf(a, 0.f);
            own[row * 65 + c] = a;
            og[c] = a;
        }
    }

    // P2: E1 = relu(S2@Ws1+bs1) -> split bf16 smem; mask
    {
        const int rr = tid;
        const float* s2 = S2 + ((size_t)gb0 * 8 + rr) * 7;
        float y0 = s2[0], y1 = s2[1], y2 = s2[2], y3 = s2[3], y4 = s2[4], y5 = s2[5], y6 = s2[6];
        mk[rr] = ((y0 + y1 + y2 + y3 + y4 + y5 + y6) != 0.f) ? 1.f : 0.f;
        float a[64];
#pragma unroll
        for (int j = 0; j < 64; j++) {
            float v = bs1s[j];
            v = fmaf(y0, Ws1s[j], v);
            v = fmaf(y1, Ws1s[64 + j], v);
            v = fmaf(y2, Ws1s[128 + j], v);
            v = fmaf(y3, Ws1s[192 + j], v);
            v = fmaf(y4, Ws1s[256 + j], v);
            v = fmaf(y5, Ws1s[320 + j], v);
            v = fmaf(y6, Ws1s[384 + j], v);
            a[j] = fmaxf(v, 0.f);
        }
        char* dh = smem + AT_E1H + rr * 144;
        char* dl = smem + AT_E1L + rr * 144;
#pragma unroll
        for (int j0 = 0; j0 < 64; j0 += 8) {
            uint4 vh, vl;
            split2(a[j0 + 0], a[j0 + 1], vh.x, vl.x);
            split2(a[j0 + 2], a[j0 + 3], vh.y, vl.y);
            split2(a[j0 + 4], a[j0 + 5], vh.z, vl.z);
            split2(a[j0 + 6], a[j0 + 7], vh.w, vl.w);
            *reinterpret_cast<uint4*>(dh + j0 * 2) = vh;
            *reinterpret_cast<uint4*>(dl + j0 * 2) = vl;
        }
    }
    __syncthreads();

    // P3: E2 = relu(E1 @ Ws2 + bs2) via HMMA (8 warps: 4m x 2n, warp 64x32)
    {
        const int mwarp = wid >> 1, nwarp = wid & 1;
        const int g = lane >> 2, t = lane & 3;
        const int lr = lane & 15, lc = (lane >> 4) << 3;
        const int mrow0 = mwarp * 64, ncol0 = nwarp * 32;
        float acc[4][4][4];
#pragma unroll
        for (int mt = 0; mt < 4; mt++)
#pragma unroll
            for (int nt = 0; nt < 4; nt++)
#pragma unroll
                for (int r = 0; r < 4; r++) acc[mt][nt][r] = 0.f;

#pragma unroll
        for (int k16 = 0; k16 < 4; k16++) {
            const int kk = k16 * 16;
            u32 bh[8], bl[8];
            ldsm4t(bh[0], bh[1], bh[2], bh[3], wsh_b + ((kk + lr) * 72 + ncol0 + lc) * 2);
            ldsm4t(bh[4], bh[5], bh[6], bh[7], wsh_b + ((kk + lr) * 72 + ncol0 + 16 + lc) * 2);
            ldsm4t(bl[0], bl[1], bl[2], bl[3], wsl_b + ((kk + lr) * 72 + ncol0 + lc) * 2);
            ldsm4t(bl[4], bl[5], bl[6], bl[7], wsl_b + ((kk + lr) * 72 + ncol0 + 16 + lc) * 2);
#pragma unroll
            for (int mt = 0; mt < 4; mt++) {
                u32 ah[4], alr[4];
                ldsm4(ah[0], ah[1], ah[2], ah[3],
                      e1h_b + ((mrow0 + mt * 16 + lr) * 72 + kk + lc) * 2);
                ldsm4(alr[0], alr[1], alr[2], alr[3],
                      e1l_b + ((mrow0 + mt * 16 + lr) * 72 + kk + lc) * 2);
#pragma unroll
                for (int nt = 0; nt < 4; nt++) {
                    mma16816(acc[mt][nt], ah, &bh[nt * 2]);
                    mma16816(acc[mt][nt], ah, &bl[nt * 2]);
                    mma16816(acc[mt][nt], alr, &bh[nt * 2]);
                }
            }
        }
        // epilogue -> E2 (stride 66)
#pragma unroll
        for (int mt = 0; mt < 4; mt++) {
#pragma unroll
            for (int nt = 0; nt < 4; nt++) {
                int r = mrow0 + mt * 16 + g;
                int cl = ncol0 + nt * 8 + t * 2;
                float b0v = bs2s[cl], b1v = bs2s[cl + 1];
                float2 v0, v1;
                v0.x = fmaxf(acc[mt][nt][0] + b0v, 0.f);
                v0.y = fmaxf(acc[mt][nt][1] + b1v, 0.f);
                v1.x = fmaxf(acc[mt][nt][2] + b0v, 0.f);
                v1.y = fmaxf(acc[mt][nt][3] + b1v, 0.f);
                *reinterpret_cast<float2*>(E2 + r * 66 + cl) = v0;
                *reinterpret_cast<float2*>(E2 + (r + 8) * 66 + cl) = v1;
            }
        }
    }

    // P4: t = own @ M (32 rows, 8 cols/thread)
    {
        const int row = tid >> 3, c0 = (tid & 7) * 8;
        float a[8];
#pragma unroll
        for (int j = 0; j < 8; j++) a[j] = 0.f;
#pragma unroll
        for (int k = 0; k < 64; k++) {
            float xv = own[row * 65 + k];
#pragma unroll
            for (int j = 0; j < 8; j++) a[j] = fmaf(xv, Ms[k * 64 + c0 + j], a[j]);
        }
#pragma unroll
        for (int j = 0; j < 8; j++) tt[row * 65 + c0 + j] = a[j];
    }
    __syncthreads();

    // P5: scores (256, 1/thread)
    {
        const int idx = tid, lb = idx >> 3;
        float s = 0.f;
#pragma unroll
        for (int k = 0; k < 64; k++) s = fmaf(tt[lb * 65 + k], E2[idx * 66 + k], s);
        sc[idx] = (mk[idx] != 0.f) ? (s * 0.125f) : __int_as_float(0xff800000);
    }
    __syncthreads();

    // P6: softmax over n=8
    if (tid < 32) {
        float m = __int_as_float(0xff800000);
#pragma unroll
        for (int n = 0; n < 8; n++) m = fmaxf(m, sc[tid * 8 + n]);
        float e[8]; float ssum = 0.f;
#pragma unroll
        for (int n = 0; n < 8; n++) { float v = expf(sc[tid * 8 + n] - m); e[n] = v; ssum += v; }
        float inv = 1.f / ssum;
#pragma unroll
        for (int n = 0; n < 8; n++) al[tid * 8 + n] = e[n] * inv;
    }
    __syncthreads();

    // P7a: wsum = sum_n alpha_n * E2_n -> tt
    {
        const int row = tid >> 3, c0 = (tid & 7) * 8;
        float av[8];
#pragma unroll
        for (int n = 0; n < 8; n++) av[n] = al[row * 8 + n];
#pragma unroll
        for (int j = 0; j < 8; j++) {
            float a = 0.f;
#pragma unroll
            for (int n = 0; n < 8; n++) a = fmaf(av[n], E2[(row * 8 + n) * 66 + c0 + j], a);
            tt[row * 65 + c0 + j] = a;
        }
    }
    __syncthreads();

    // P7b: v_att = wsum @ Wv -> g_concat[:,128:192]
    {
        const int row = tid >> 3, c0 = (tid & 7) * 8;
        float a[8];
#pragma unroll
        for (int j = 0; j < 8; j++) a[j] = 0.f;
#pragma unroll
        for (int k = 0; k < 64; k++) {
            float xv = tt[row * 65 + k];
#pragma unroll
            for (int j = 0; j < 8; j++) a[j] = fmaf(xv, Wvs[k * 64 + c0 + j], a[j]);
        }
        float* dst = g_concat + (size_t)(gb0 + row) * 192 + 128 + c0;
#pragma unroll
        for (int j = 0; j < 8; j++) dst[j] = a[j];
    }
}

// ---------------------------------------------------------------------------
// K4: out = tanh(g_h2 @ Wc3 + bc3)
// ---------------------------------------------------------------------------
__global__ __launch_bounds__(256)
void k_head(const float* __restrict__ Wc3, const float* __restrict__ bc3,
            float* __restrict__ out) {
    __shared__ float W3s[256];
    __shared__ float b3s[2];
    const int tid = threadIdx.x;
    const int wid = tid >> 5, lane = tid & 31;
    W3s[tid] = Wc3[tid];
    if (tid < 2) b3s[tid] = bc3[tid];
    __syncthreads();

    const int row = blockIdx.x * 8 + wid;
    float4 v = *reinterpret_cast<const float4*>(&g_h2[(size_t)row * 128 + lane * 4]);
    float s0 = 0.f, s1 = 0.f;
    int kb = lane * 4;
    s0 = fmaf(v.x, W3s[(kb + 0) * 2 + 0], s0); s1 = fmaf(v.x, W3s[(kb + 0) * 2 + 1], s1);
    s0 = fmaf(v.y, W3s[(kb + 1) * 2 + 0], s0); s1 = fmaf(v.y, W3s[(kb + 1) * 2 + 1], s1);
    s0 = fmaf(v.z, W3s[(kb + 2) * 2 + 0], s0); s1 = fmaf(v.z, W3s[(kb + 2) * 2 + 1], s1);
    s0 = fmaf(v.w, W3s[(kb + 3) * 2 + 0], s0); s1 = fmaf(v.w, W3s[(kb + 3) * 2 + 1], s1);
#pragma unroll
    for (int o = 16; o > 0; o >>= 1) {
        s0 += __shfl_xor_sync(0xffffffffu, s0, o);
        s1 += __shfl_xor_sync(0xffffffffu, s1, o);
    }
    if (lane == 0) {
        float2 o2;
        o2.x = tanhf(s0 + b3s[0]);
        o2.y = tanhf(s1 + b3s[1]);
        *reinterpret_cast<float2*>(out + (size_t)row * 2) = o2;
    }
}

// ---------------------------------------------------------------------------
// kernel_launch
// ---------------------------------------------------------------------------
extern "C" void kernel_launch(void* const* d_in, const int* in_sizes, int n_in,
                              void* d_out, int out_size) {
    const float* S0  = (const float*)d_in[0];
    const float* S1  = (const float*)d_in[1];
    const float* S2  = (const float*)d_in[2];
    const float* W0  = (const float*)d_in[3];
    const float* b0  = (const float*)d_in[4];
    const float* Wg  = (const float*)d_in[5];
    const float* bg  = (const float*)d_in[6];
    const float* Ws1 = (const float*)d_in[7];
    const float* bs1 = (const float*)d_in[8];
    const float* Ws2 = (const float*)d_in[9];
    const float* bs2 = (const float*)d_in[10];
    const float* Wq  = (const float*)d_in[11];
    const float* Wk  = (const float*)d_in[12];
    const float* Wv  = (const float*)d_in[13];
    const float* Wc1 = (const float*)d_in[14];
    const float* bc1 = (const float*)d_in[15];
    const float* Wc2 = (const float*)d_in[16];
    const float* bc2 = (const float*)d_in[17];
    const float* Wc3 = (const float*)d_in[18];
    const float* bc3 = (const float*)d_in[19];
    float* out = (float*)d_out;

    void* p;
    cudaGetSymbolAddress(&p, g_concat); float* C  = (float*)p;
    cudaGetSymbolAddress(&p, g_h);      float* Hb = (float*)p;
    cudaGetSymbolAddress(&p, g_h2);     float* H2 = (float*)p;
    cudaGetSymbolAddress(&p, g_Wgh);  u16* Wgh  = (u16*)p;
    cudaGetSymbolAddress(&p, g_Wgl);  u16* Wgl  = (u16*)p;
    cudaGetSymbolAddress(&p, g_Wc1h); u16* Wc1h = (u16*)p;
    cudaGetSymbolAddress(&p, g_Wc1l); u16* Wc1l = (u16*)p;
    cudaGetSymbolAddress(&p, g_Wc2h); u16* Wc2h = (u16*)p;
    cudaGetSymbolAddress(&p, g_Wc2l); u16* Wc2l = (u16*)p;

    cudaFuncSetAttribute(k_attn2, cudaFuncAttributeMaxDynamicSharedMemorySize,
                         ATTN_SMEM_BYTES);
    cudaFuncSetAttribute(k_mma<1024, 1024, 64>,
                         cudaFuncAttributeMaxDynamicSharedMemorySize, MMA_SMEM_BYTES);
    cudaFuncSetAttribute(k_mma<192, 192, 128>,
                         cudaFuncAttributeMaxDynamicSharedMemorySize, MMA_SMEM_BYTES);
    cudaFuncSetAttribute(k_mma<128, 128, 128>,
                         cudaFuncAttributeMaxDynamicSharedMemorySize, MMA_SMEM_BYTES);

    k_prep<<<16, 256>>>(Wq, Wk);
    k_split<<<432, 256>>>(Wg, Wc1, Wc2, Ws2);
    // K1: env_e -> g_concat[:,64:128]
    k_mma<1024, 1024, 64><<<dim3(B_TOT / 128, 1), 256, MMA_SMEM_BYTES>>>(
        S1, Wgh, Wgl, bg, C, 192, 64);
    // K2: own_e + attention -> g_concat[:,0:64], [:,128:192]
    k_attn2<<<B_TOT / 32, 256, ATTN_SMEM_BYTES>>>(S0, S2, W0, b0, Ws1, bs1, bs2, Wv);
    // K3a: h1 = relu(concat @ Wc1 + bc1)
    k_mma<192, 192, 128><<<dim3(B_TOT / 128, 2), 256, MMA_SMEM_BYTES>>>(
        C, Wc1h, Wc1l, bc1, Hb, 128, 0);
    // K3b: h2 = relu(h1 @ Wc2 + bc2)
    k_mma<128, 128, 128><<<dim3(B_TOT / 128, 2), 256, MMA_SMEM_BYTES>>>(
        Hb, Wc2h, Wc2l, bc2, H2, 128, 0);
    // K4: out
    k_head<<<B_TOT / 8, 256>>>(Wc3, bc3, out);
}

// round 6
// speedup vs baseline: 1.4649x; 1.1105x over previous
#include <cuda_runtime.h>
#include <cuda_bf16.h>
#include <math.h>
#include <stdint.h>

#define B_TOT 65536
// H=64, HC=128, N=8, OBS0=6, OBS1=1024, OBS2=7, NA=2

typedef unsigned long long u64;
typedef unsigned short u16;
typedef unsigned int u32;

// ---------------------------------------------------------------------------
// helpers
// ---------------------------------------------------------------------------
static __device__ __forceinline__ uint32_t smem_u32(const void* p) {
    uint32_t a;
    asm("{ .reg .u64 t; cvta.to.shared.u64 t, %1; cvt.u32.u64 %0, t; }"
        : "=r"(a) : "l"(p));
    return a;
}
static __device__ __forceinline__ void mma16816(float* c, const u32* a, const u32* b) {
    asm volatile(
        "mma.sync.aligned.m16n8k16.row.col.f32.bf16.bf16.f32 "
        "{%0,%1,%2,%3}, {%4,%5,%6,%7}, {%8,%9}, {%0,%1,%2,%3};"
        : "+f"(c[0]), "+f"(c[1]), "+f"(c[2]), "+f"(c[3])
        : "r"(a[0]), "r"(a[1]), "r"(a[2]), "r"(a[3]), "r"(b[0]), "r"(b[1]));
}
static __device__ __forceinline__ void ldsm4(u32& r0, u32& r1, u32& r2, u32& r3, u32 a) {
    asm volatile("ldmatrix.sync.aligned.m8n8.x4.shared.b16 {%0,%1,%2,%3}, [%4];"
                 : "=r"(r0), "=r"(r1), "=r"(r2), "=r"(r3) : "r"(a));
}
static __device__ __forceinline__ void ldsm4t(u32& r0, u32& r1, u32& r2, u32& r3, u32 a) {
    asm volatile("ldmatrix.sync.aligned.m8n8.x4.trans.shared.b16 {%0,%1,%2,%3}, [%4];"
                 : "=r"(r0), "=r"(r1), "=r"(r2), "=r"(r3) : "r"(a));
}
// exact pair split: h2 = {x0>>16, x1>>16}; l2 = bf16rn(residuals), residual exact
static __device__ __forceinline__ void split2(float x0, float x1, u32& h2, u32& l2) {
    u32 b0 = __float_as_uint(x0), b1 = __float_as_uint(x1);
    asm("prmt.b32 %0, %1, %2, 0x7632;" : "=r"(h2) : "r"(b0), "r"(b1));
    float r0 = x0 - __uint_as_float(b0 & 0xffff0000u);
    float r1 = x1 - __uint_as_float(b1 & 0xffff0000u);
    asm("cvt.rn.bf16x2.f32 %0, %1, %2;" : "=r"(l2) : "f"(r1), "f"(r0));
}

// ---------------------------------------------------------------------------
// Scratch (static device globals: allocation-free)
// ---------------------------------------------------------------------------
__device__ float g_M[64 * 64];
__device__ float g_concat[(size_t)B_TOT * 192];
__device__ float g_h[(size_t)B_TOT * 128];
__device__ float g_h2[(size_t)B_TOT * 128];
// pre-split weights, [k][n] row-major bf16
__device__ u16 g_Wgh[1024 * 64],  g_Wgl[1024 * 64];
__device__ u16 g_Wc1h[192 * 128], g_Wc1l[192 * 128];
__device__ u16 g_Wc2h[128 * 128], g_Wc2l[128 * 128];
__device__ u16 g_Ws2h[64 * 64],   g_Ws2l[64 * 64];

// ---------------------------------------------------------------------------
// K0a: M = Wq @ Wk^T
// ---------------------------------------------------------------------------
__global__ void k_prep(const float* __restrict__ Wq, const float* __restrict__ Wk) {
    int e = blockIdx.x * 256 + threadIdx.x;
    if (e < 4096) {
        int i = e >> 6, j = e & 63;
        float s = 0.f;
#pragma unroll
        for (int h = 0; h < 64; h++) s = fmaf(Wq[i * 64 + h], Wk[j * 64 + h], s);
        g_M[e] = s;
    }
}

// ---------------------------------------------------------------------------
// K0b: split weights into bf16 hi/lo (RN split)
// ---------------------------------------------------------------------------
__global__ void k_split(const float* __restrict__ Wg, const float* __restrict__ Wc1,
                        const float* __restrict__ Wc2, const float* __restrict__ Ws2) {
    int i = blockIdx.x * 256 + threadIdx.x;
    const float* src; u16 *dh, *dl; int off;
    if (i < 65536)            { src = Wg;  dh = g_Wgh;  dl = g_Wgl;  off = i; }
    else if (i < 90112)       { src = Wc1; dh = g_Wc1h; dl = g_Wc1l; off = i - 65536; }
    else if (i < 106496)      { src = Wc2; dh = g_Wc2h; dl = g_Wc2l; off = i - 90112; }
    else if (i < 110592)      { src = Ws2; dh = g_Ws2h; dl = g_Ws2l; off = i - 106496; }
    else return;
    float x = src[off];
    __nv_bfloat16 hb = __float2bfloat16(x);
    __nv_bfloat16 lb = __float2bfloat16(x - __bfloat162float(hb));
    dh[off] = __bfloat16_as_ushort(hb);
    dl[off] = __bfloat16_as_ushort(lb);
}

// ---------------------------------------------------------------------------
// Tensor-core GEMM: ldmatrix + pre-split B (unchanged from round 5)
// ---------------------------------------------------------------------------
#define MMA_SMEM_BYTES (55296 + 256)

template <int KTOT, int LDA, int LDB>
__global__ __launch_bounds__(256)
void k_mma(const float* __restrict__ A,
           const u16* __restrict__ Bh_g, const u16* __restrict__ Bl_g,
           const float* __restrict__ bias, float* __restrict__ C,
           int ldc, int ccol0) {
    extern __shared__ char smem[];
    const u32 sbase = smem_u32(smem);
    const u32 ah_b = sbase, al_b = sbase + 18432;
    const u32 bh_b = sbase + 36864, bl_b = sbase + 46080;
    float* bs = (float*)(smem + 55296);

    const int tid = threadIdx.x;
    const int wid = tid >> 5, lane = tid & 31;
    const int row0 = blockIdx.x * 128;
    const int bcol = blockIdx.y * 64;
    const int mwarp = wid >> 1, nwarp = wid & 1;
    const int g = lane >> 2, t = lane & 3;
    const int lr = lane & 15, lc = (lane >> 4) << 3;

    if (tid < 64) bs[tid] = bias[bcol + tid];

    float acc[2][4][4];
#pragma unroll
    for (int mt = 0; mt < 2; mt++)
#pragma unroll
        for (int nt = 0; nt < 4; nt++)
#pragma unroll
            for (int r = 0; r < 4; r++) acc[mt][nt][r] = 0.f;

    const int mrow0 = mwarp * 32, ncol0 = nwarp * 32;

    for (int c = 0; c < KTOT / 64; c++) {
        const int k0 = c * 64;
        // ---- A chunk [128 x 64] fp32 -> split bf16 ----
        {
            const int m = tid >> 1, h = tid & 1;
            const float* src = A + (size_t)(row0 + m) * LDA + k0 + h * 32;
            char* dh = smem + m * 144 + h * 64;
            char* dl = smem + 18432 + m * 144 + h * 64;
#pragma unroll
            for (int q = 0; q < 8; q++) {
                float4 v = *reinterpret_cast<const float4*>(src + q * 4);
                uint2 hh, ll;
                split2(v.x, v.y, hh.x, ll.x);
                split2(v.z, v.w, hh.y, ll.y);
                *reinterpret_cast<uint2*>(dh + q * 8) = hh;
                *reinterpret_cast<uint2*>(dl + q * 8) = ll;
            }
        }
        // ---- B chunk: pre-split bf16, [k][n] -> smem stride 72 ----
        {
            const int kk = tid >> 2, cg = (tid & 3) * 16;
            const u16* sh = Bh_g + (size_t)(k0 + kk) * LDB + bcol + cg;
            const u16* sl = Bl_g + (size_t)(k0 + kk) * LDB + bcol + cg;
            char* dh = smem + 36864 + kk * 144 + cg * 2;
            char* dl = smem + 46080 + kk * 144 + cg * 2;
            *reinterpret_cast<uint4*>(dh)      = *reinterpret_cast<const uint4*>(sh);
            *reinterpret_cast<uint4*>(dh + 16) = *reinterpret_cast<const uint4*>(sh + 8);
            *reinterpret_cast<uint4*>(dl)      = *reinterpret_cast<const uint4*>(sl);
            *reinterpret_cast<uint4*>(dl + 16) = *reinterpret_cast<const uint4*>(sl + 8);
        }
        __syncthreads();

#pragma unroll
        for (int k16 = 0; k16 < 4; k16++) {
            const int kk = k16 * 16;
            u32 bh[8], bl[8];
            ldsm4t(bh[0], bh[1], bh[2], bh[3], bh_b + ((kk + lr) * 72 + ncol0 + lc) * 2);
            ldsm4t(bh[4], bh[5], bh[6], bh[7], bh_b + ((kk + lr) * 72 + ncol0 + 16 + lc) * 2);
            ldsm4t(bl[0], bl[1], bl[2], bl[3], bl_b + ((kk + lr) * 72 + ncol0 + lc) * 2);
            ldsm4t(bl[4], bl[5], bl[6], bl[7], bl_b + ((kk + lr) * 72 + ncol0 + 16 + lc) * 2);
#pragma unroll
            for (int mt = 0; mt < 2; mt++) {
                u32 ah[4], al[4];
                ldsm4(ah[0], ah[1], ah[2], ah[3],
                      ah_b + ((mrow0 + mt * 16 + lr) * 72 + kk + lc) * 2);
                ldsm4(al[0], al[1], al[2], al[3],
                      al_b + ((mrow0 + mt * 16 + lr) * 72 + kk + lc) * 2);
#pragma unroll
                for (int nt = 0; nt < 4; nt++) {
                    mma16816(acc[mt][nt], ah, &bh[nt * 2]);
                    mma16816(acc[mt][nt], ah, &bl[nt * 2]);
                    mma16816(acc[mt][nt], al, &bh[nt * 2]);
                }
            }
        }
        __syncthreads();
    }

#pragma unroll
    for (int mt = 0; mt < 2; mt++) {
#pragma unroll
        for (int nt = 0; nt < 4; nt++) {
            int r = row0 + mrow0 + mt * 16 + g;
            int cl = ncol0 + nt * 8 + t * 2;
            int cg = ccol0 + bcol + cl;
            float b0v = bs[cl], b1v = bs[cl + 1];
            float2 v0, v1;
            v0.x = fmaxf(acc[mt][nt][0] + b0v, 0.f);
            v0.y = fmaxf(acc[mt][nt][1] + b1v, 0.f);
            v1.x = fmaxf(acc[mt][nt][2] + b0v, 0.f);
            v1.y = fmaxf(acc[mt][nt][3] + b1v, 0.f);
            *reinterpret_cast<float2*>(C + (size_t)r * ldc + cg) = v0;
            *reinterpret_cast<float2*>(C + (size_t)(r + 8) * ldc + cg) = v1;
        }
    }
}

// ---------------------------------------------------------------------------
// K2 v3: fused attention, 16 batch rows (128 neighbor rows)/CTA, 256 thr.
// E2 (f32, stride 65) aliases the E1 hi/lo buffers. ~99.6 KB smem -> 2 CTA/SM.
// ---------------------------------------------------------------------------
#define AT_E1H   0          // [128][72] u16 (18432)       } union with
#define AT_E1L   18432      // [128][72] u16 (18432)       } E2 [128][65] f32 (33280)
#define AT_E2    0
#define AT_WS2H  36864      // [64][72] u16 (9216)
#define AT_WS2L  46080      // (9216)
#define AT_MS    55296      // 4096 f32
#define AT_WVS   71680      // 4096 f32
#define AT_OWN   88064      // [16][65] f32 (4160)
#define AT_TT    92224      // [16][65] f32 (4160)
#define AT_W0    96384      // 384 f32
#define AT_WS1   97920      // 448 f32
#define AT_B0    99712      // 64 f32
#define AT_BS1   99968
#define AT_BS2   100224
#define AT_SC    100480     // 128 f32
#define AT_AL    100992     // 128 f32
#define AT_MK    101504     // 128 f32
#define ATTN_SMEM_BYTES 102016

__global__ __launch_bounds__(256, 2)
void k_attn3(const float* __restrict__ S0, const float* __restrict__ S2,
             const float* __restrict__ W0, const float* __restrict__ b0,
             const float* __restrict__ Ws1, const float* __restrict__ bs1,
             const float* __restrict__ bs2, const float* __restrict__ Wv) {
    extern __shared__ char smem[];
    float* E2   = (float*)(smem + AT_E2);
    float* Ms   = (float*)(smem + AT_MS);
    float* Wvs  = (float*)(smem + AT_WVS);
    float* own  = (float*)(smem + AT_OWN);
    float* tt   = (float*)(smem + AT_TT);
    float* W0s  = (float*)(smem + AT_W0);
    float* Ws1s = (float*)(smem + AT_WS1);
    float* b0s  = (float*)(smem + AT_B0);
    float* bs1s = (float*)(smem + AT_BS1);
    float* bs2s = (float*)(smem + AT_BS2);
    float* sc   = (float*)(smem + AT_SC);
    float* al   = (float*)(smem + AT_AL);
    float* mk   = (float*)(smem + AT_MK);
    const u32 sbase = smem_u32(smem);
    const u32 e1h_b = sbase + AT_E1H, e1l_b = sbase + AT_E1L;
    const u32 wsh_b = sbase + AT_WS2H, wsl_b = sbase + AT_WS2L;

    const int tid = threadIdx.x;
    const int wid = tid >> 5, lane = tid & 31;
    const int gb0 = blockIdx.x * 16;

    for (int i = tid; i < 4096; i += 256) { Ms[i] = g_M[i]; Wvs[i] = Wv[i]; }
    for (int i = tid; i < 384; i += 256) W0s[i] = W0[i];
    for (int i = tid; i < 448; i += 256) Ws1s[i] = Ws1[i];
    if (tid < 64) { b0s[tid] = b0[tid]; bs1s[tid] = bs1[tid]; bs2s[tid] = bs2[tid]; }
    {   // Ws2 pre-split -> smem stride 72
        const int kk = tid >> 2, cg = (tid & 3) * 16;
        const u16* sh = g_Ws2h + kk * 64 + cg;
        const u16* sl = g_Ws2l + kk * 64 + cg;
        char* dh = smem + AT_WS2H + kk * 144 + cg * 2;
        char* dl = smem + AT_WS2L + kk * 144 + cg * 2;
        *reinterpret_cast<uint4*>(dh)      = *reinterpret_cast<const uint4*>(sh);
        *reinterpret_cast<uint4*>(dh + 16) = *reinterpret_cast<const uint4*>(sh + 8);
        *reinterpret_cast<uint4*>(dl)      = *reinterpret_cast<const uint4*>(sl);
        *reinterpret_cast<uint4*>(dl + 16) = *reinterpret_cast<const uint4*>(sl + 8);
    }

    // P1: own_e (16 rows, 4 cols/thread) — no sync needed before P2 wrt own
    {
        const int row = tid >> 4, c0 = (tid & 15) * 4;
        const float* s0 = S0 + (size_t)(gb0 + row) * 6;
        float x0 = s0[0], x1 = s0[1], x2 = s0[2], x3 = s0[3], x4 = s0[4], x5 = s0[5];
        float* og = g_concat + (size_t)(gb0 + row) * 192;
        __syncthreads();  // weights (W0s) ready
#pragma unroll
        for (int j = 0; j < 4; j++) {
            int c = c0 + j;
            float a = b0s[c];
            a = fmaf(x0, W0s[c], a);
            a = fmaf(x1, W0s[64 + c], a);
            a = fmaf(x2, W0s[128 + c], a);
            a = fmaf(x3, W0s[192 + c], a);
            a = fmaf(x4, W0s[256 + c], a);
            a = fmaf(x5, W0s[320 + c], a);
            a = fmaxf(a, 0.f);
            own[row * 65 + c] = a;
            og[c] = a;
        }
    }

    // P2: E1 = relu(S2@Ws1+bs1) -> split bf16; 2 threads/row, 32 cols each
    {
        const int rr = tid >> 1, h = tid & 1, j0 = h * 32;
        const float* s2 = S2 + ((size_t)gb0 * 8 + rr) * 7;
        float y0 = s2[0], y1 = s2[1], y2 = s2[2], y3 = s2[3], y4 = s2[4], y5 = s2[5], y6 = s2[6];
        if (h == 0)
            mk[rr] = ((y0 + y1 + y2 + y3 + y4 + y5 + y6) != 0.f) ? 1.f : 0.f;
        float a[32];
#pragma unroll
        for (int j = 0; j < 32; j++) {
            int c = j0 + j;
            float v = bs1s[c];
            v = fmaf(y0, Ws1s[c], v);
            v = fmaf(y1, Ws1s[64 + c], v);
            v = fmaf(y2, Ws1s[128 + c], v);
            v = fmaf(y3, Ws1s[192 + c], v);
            v = fmaf(y4, Ws1s[256 + c], v);
            v = fmaf(y5, Ws1s[320 + c], v);
            v = fmaf(y6, Ws1s[384 + c], v);
            a[j] = fmaxf(v, 0.f);
        }
        char* dh = smem + AT_E1H + rr * 144 + j0 * 2;
        char* dl = smem + AT_E1L + rr * 144 + j0 * 2;
#pragma unroll
        for (int q = 0; q < 32; q += 8) {
            uint4 vh, vl;
            split2(a[q + 0], a[q + 1], vh.x, vl.x);
            split2(a[q + 2], a[q + 3], vh.y, vl.y);
            split2(a[q + 4], a[q + 5], vh.z, vl.z);
            split2(a[q + 6], a[q + 7], vh.w, vl.w);
            *reinterpret_cast<uint4*>(dh + q * 2) = vh;
            *reinterpret_cast<uint4*>(dl + q * 2) = vl;
        }
    }
    __syncthreads();

    // P3: E2 = relu(E1 @ Ws2 + bs2) via HMMA; 8 warps 4m x 2n, warp 32x32
    float acc[2][4][4];
    {
        const int mwarp = wid >> 1, nwarp = wid & 1;
        const int lr = lane & 15, lc = (lane >> 4) << 3;
        const int mrow0 = mwarp * 32, ncol0 = nwarp * 32;
#pragma unroll
        for (int mt = 0; mt < 2; mt++)
#pragma unroll
            for (int nt = 0; nt < 4; nt++)
#pragma unroll
                for (int r = 0; r < 4; r++) acc[mt][nt][r] = 0.f;

#pragma unroll
        for (int k16 = 0; k16 < 4; k16++) {
            const int kk = k16 * 16;
            u32 bh[8], bl[8];
            ldsm4t(bh[0], bh[1], bh[2], bh[3], wsh_b + ((kk + lr) * 72 + ncol0 + lc) * 2);
            ldsm4t(bh[4], bh[5], bh[6], bh[7], wsh_b + ((kk + lr) * 72 + ncol0 + 16 + lc) * 2);
            ldsm4t(bl[0], bl[1], bl[2], bl[3], wsl_b + ((kk + lr) * 72 + ncol0 + lc) * 2);
            ldsm4t(bl[4], bl[5], bl[6], bl[7], wsl_b + ((kk + lr) * 72 + ncol0 + 16 + lc) * 2);
#pragma unroll
            for (int mt = 0; mt < 2; mt++) {
                u32 ah[4], alr[4];
                ldsm4(ah[0], ah[1], ah[2], ah[3],
                      e1h_b + ((mrow0 + mt * 16 + lr) * 72 + kk + lc) * 2);
                ldsm4(alr[0], alr[1], alr[2], alr[3],
                      e1l_b + ((mrow0 + mt * 16 + lr) * 72 + kk + lc) * 2);
#pragma unroll
                for (int nt = 0; nt < 4; nt++) {
                    mma16816(acc[mt][nt], ah, &bh[nt * 2]);
                    mma16816(acc[mt][nt], ah, &bl[nt * 2]);
                    mma16816(acc[mt][nt], alr, &bh[nt * 2]);
                }
            }
        }
    }
    __syncthreads();   // all ldsm reads of E1 done; safe to overwrite with E2

    // E2 epilogue (stride 65, scalar stores) + P4 (t = own@M) in one region
    {
        const int mwarp = wid >> 1, nwarp = wid & 1;
        const int g = lane >> 2, t = lane & 3;
        const int mrow0 = mwarp * 32, ncol0 = nwarp * 32;
#pragma unroll
        for (int mt = 0; mt < 2; mt++) {
#pragma unroll
            for (int nt = 0; nt < 4; nt++) {
                int r = mrow0 + mt * 16 + g;
                int cl = ncol0 + nt * 8 + t * 2;
                float b0v = bs2s[cl], b1v = bs2s[cl + 1];
                E2[r * 65 + cl]           = fmaxf(acc[0 + mt][nt][0] + b0v, 0.f);
                E2[r * 65 + cl + 1]       = fmaxf(acc[mt][nt][1] + b1v, 0.f);
                E2[(r + 8) * 65 + cl]     = fmaxf(acc[mt][nt][2] + b0v, 0.f);
                E2[(r + 8) * 65 + cl + 1] = fmaxf(acc[mt][nt][3] + b1v, 0.f);
            }
        }
    }
    {   // P4: t = own @ M (16 rows, 4 cols/thread)
        const int row = tid >> 4, c0 = (tid & 15) * 4;
        float a[4] = {0.f, 0.f, 0.f, 0.f};
#pragma unroll
        for (int k = 0; k < 64; k++) {
            float xv = own[row * 65 + k];
#pragma unroll
            for (int j = 0; j < 4; j++) a[j] = fmaf(xv, Ms[k * 64 + c0 + j], a[j]);
        }
#pragma unroll
        for (int j = 0; j < 4; j++) tt[row * 65 + c0 + j] = a[j];
    }
    __syncthreads();

    // P5: scores — 2 threads/row, 32 k each, pair-combine via shfl
    {
        const int rr = tid >> 1, h = tid & 1, k0 = h * 32;
        const int lb = rr >> 3;
        float s = 0.f;
#pragma unroll
        for (int k = 0; k < 32; k++)
            s = fmaf(tt[lb * 65 + k0 + k], E2[rr * 65 + k0 + k], s);
        s += __shfl_xor_sync(0xffffffffu, s, 1);
        if (h == 0)
            sc[rr] = (mk[rr] != 0.f) ? (s * 0.125f) : __int_as_float(0xff800000);
    }
    __syncthreads();

    // P6: softmax over n=8 (16 rows)
    if (tid < 16) {
        float m = __int_as_float(0xff800000);
#pragma unroll
        for (int n = 0; n < 8; n++) m = fmaxf(m, sc[tid * 8 + n]);
        float e[8]; float ssum = 0.f;
#pragma unroll
        for (int n = 0; n < 8; n++) { float v = expf(sc[tid * 8 + n] - m); e[n] = v; ssum += v; }
        float inv = 1.f / ssum;
#pragma unroll
        for (int n = 0; n < 8; n++) al[tid * 8 + n] = e[n] * inv;
    }
    __syncthreads();

    // P7a: wsum = sum_n alpha_n * E2_n -> tt
    {
        const int row = tid >> 4, c0 = (tid & 15) * 4;
        float av[8];
#pragma unroll
        for (int n = 0; n < 8; n++) av[n] = al[row * 8 + n];
#pragma unroll
        for (int j = 0; j < 4; j++) {
            float a = 0.f;
#pragma unroll
            for (int n = 0; n < 8; n++)
                a = fmaf(av[n], E2[(row * 8 + n) * 65 + c0 + j], a);
            tt[row * 65 + c0 + j] = a;
        }
    }
    __syncthreads();

    // P7b: v_att = wsum @ Wv -> g_concat[:,128:192]
    {
        const int row = tid >> 4, c0 = (tid & 15) * 4;
        float a[4] = {0.f, 0.f, 0.f, 0.f};
#pragma unroll
        for (int k = 0; k < 64; k++) {
            float xv = tt[row * 65 + k];
#pragma unroll
            for (int j = 0; j < 4; j++) a[j] = fmaf(xv, Wvs[k * 64 + c0 + j], a[j]);
        }
        float* dst = g_concat + (size_t)(gb0 + row) * 192 + 128 + c0;
#pragma unroll
        for (int j = 0; j < 4; j++) dst[j] = a[j];
    }
}

// ---------------------------------------------------------------------------
// K4: out = tanh(g_h2 @ Wc3 + bc3)
// ---------------------------------------------------------------------------
__global__ __launch_bounds__(256)
void k_head(const float* __restrict__ Wc3, const float* __restrict__ bc3,
            float* __restrict__ out) {
    __shared__ float W3s[256];
    __shared__ float b3s[2];
    const int tid = threadIdx.x;
    const int wid = tid >> 5, lane = tid & 31;
    W3s[tid] = Wc3[tid];
    if (tid < 2) b3s[tid] = bc3[tid];
    __syncthreads();

    const int row = blockIdx.x * 8 + wid;
    float4 v = *reinterpret_cast<const float4*>(&g_h2[(size_t)row * 128 + lane * 4]);
    float s0 = 0.f, s1 = 0.f;
    int kb = lane * 4;
    s0 = fmaf(v.x, W3s[(kb + 0) * 2 + 0], s0); s1 = fmaf(v.x, W3s[(kb + 0) * 2 + 1], s1);
    s0 = fmaf(v.y, W3s[(kb + 1) * 2 + 0], s0); s1 = fmaf(v.y, W3s[(kb + 1) * 2 + 1], s1);
    s0 = fmaf(v.z, W3s[(kb + 2) * 2 + 0], s0); s1 = fmaf(v.z, W3s[(kb + 2) * 2 + 1], s1);
    s0 = fmaf(v.w, W3s[(kb + 3) * 2 + 0], s0); s1 = fmaf(v.w, W3s[(kb + 3) * 2 + 1], s1);
#pragma unroll
    for (int o = 16; o > 0; o >>= 1) {
        s0 += __shfl_xor_sync(0xffffffffu, s0, o);
        s1 += __shfl_xor_sync(0xffffffffu, s1, o);
    }
    if (lane == 0) {
        float2 o2;
        o2.x = tanhf(s0 + b3s[0]);
        o2.y = tanhf(s1 + b3s[1]);
        *reinterpret_cast<float2*>(out + (size_t)row * 2) = o2;
    }
}

// ---------------------------------------------------------------------------
// kernel_launch
// ---------------------------------------------------------------------------
extern "C" void kernel_launch(void* const* d_in, const int* in_sizes, int n_in,
                              void* d_out, int out_size) {
    const float* S0  = (const float*)d_in[0];
    const float* S1  = (const float*)d_in[1];
    const float* S2  = (const float*)d_in[2];
    const float* W0  = (const float*)d_in[3];
    const float* b0  = (const float*)d_in[4];
    const float* Wg  = (const float*)d_in[5];
    const float* bg  = (const float*)d_in[6];
    const float* Ws1 = (const float*)d_in[7];
    const float* bs1 = (const float*)d_in[8];
    const float* Ws2 = (const float*)d_in[9];
    const float* bs2 = (const float*)d_in[10];
    const float* Wq  = (const float*)d_in[11];
    const float* Wk  = (const float*)d_in[12];
    const float* Wv  = (const float*)d_in[13];
    const float* Wc1 = (const float*)d_in[14];
    const float* bc1 = (const float*)d_in[15];
    const float* Wc2 = (const float*)d_in[16];
    const float* bc2 = (const float*)d_in[17];
    const float* Wc3 = (const float*)d_in[18];
    const float* bc3 = (const float*)d_in[19];
    float* out = (float*)d_out;

    void* p;
    cudaGetSymbolAddress(&p, g_concat); float* C  = (float*)p;
    cudaGetSymbolAddress(&p, g_h);      float* Hb = (float*)p;
    cudaGetSymbolAddress(&p, g_h2);     float* H2 = (float*)p;
    cudaGetSymbolAddress(&p, g_Wgh);  u16* Wgh  = (u16*)p;
    cudaGetSymbolAddress(&p, g_Wgl);  u16* Wgl  = (u16*)p;
    cudaGetSymbolAddress(&p, g_Wc1h); u16* Wc1h = (u16*)p;
    cudaGetSymbolAddress(&p, g_Wc1l); u16* Wc1l = (u16*)p;
    cudaGetSymbolAddress(&p, g_Wc2h); u16* Wc2h = (u16*)p;
    cudaGetSymbolAddress(&p, g_Wc2l); u16* Wc2l = (u16*)p;

    cudaFuncSetAttribute(k_attn3, cudaFuncAttributeMaxDynamicSharedMemorySize,
                         ATTN_SMEM_BYTES);
    cudaFuncSetAttribute(k_mma<1024, 1024, 64>,
                         cudaFuncAttributeMaxDynamicSharedMemorySize, MMA_SMEM_BYTES);
    cudaFuncSetAttribute(k_mma<192, 192, 128>,
                         cudaFuncAttributeMaxDynamicSharedMemorySize, MMA_SMEM_BYTES);
    cudaFuncSetAttribute(k_mma<128, 128, 128>,
                         cudaFuncAttributeMaxDynamicSharedMemorySize, MMA_SMEM_BYTES);

    k_prep<<<16, 256>>>(Wq, Wk);
    k_split<<<432, 256>>>(Wg, Wc1, Wc2, Ws2);
    // K1: env_e -> g_concat[:,64:128]
    k_mma<1024, 1024, 64><<<dim3(B_TOT / 128, 1), 256, MMA_SMEM_BYTES>>>(
        S1, Wgh, Wgl, bg, C, 192, 64);
    // K2: own_e + attention -> g_concat[:,0:64], [:,128:192]
    k_attn3<<<B_TOT / 16, 256, ATTN_SMEM_BYTES>>>(S0, S2, W0, b0, Ws1, bs1, bs2, Wv);
    // K3a: h1 = relu(concat @ Wc1 + bc1)
    k_mma<192, 192, 128><<<dim3(B_TOT / 128, 2), 256, MMA_SMEM_BYTES>>>(
        C, Wc1h, Wc1l, bc1, Hb, 128, 0);
    // K3b: h2 = relu(h1 @ Wc2 + bc2)
    k_mma<128, 128, 128><<<dim3(B_TOT / 128, 2), 256, MMA_SMEM_BYTES>>>(
        Hb, Wc2h, Wc2l, bc2, H2, 128, 0);
    // K4: out
    k_head<<<B_TOT / 8, 256>>>(Wc3, bc3, out);
}

// round 7
// speedup vs baseline: 1.6846x; 1.1500x over previous
#include <cuda_runtime.h>
#include <cuda_bf16.h>
#include <math.h>
#include <stdint.h>

#define B_TOT 65536
// H=64, HC=128, N=8, OBS0=6, OBS1=1024, OBS2=7, NA=2

typedef unsigned long long u64;
typedef unsigned short u16;
typedef unsigned int u32;

// ---------------------------------------------------------------------------
// helpers
// ---------------------------------------------------------------------------
static __device__ __forceinline__ uint32_t smem_u32(const void* p) {
    uint32_t a;
    asm("{ .reg .u64 t; cvta.to.shared.u64 t, %1; cvt.u32.u64 %0, t; }"
        : "=r"(a) : "l"(p));
    return a;
}
static __device__ __forceinline__ void mma16816(float* c, const u32* a, const u32* b) {
    asm volatile(
        "mma.sync.aligned.m16n8k16.row.col.f32.bf16.bf16.f32 "
        "{%0,%1,%2,%3}, {%4,%5,%6,%7}, {%8,%9}, {%0,%1,%2,%3};"
        : "+f"(c[0]), "+f"(c[1]), "+f"(c[2]), "+f"(c[3])
        : "r"(a[0]), "r"(a[1]), "r"(a[2]), "r"(a[3]), "r"(b[0]), "r"(b[1]));
}
static __device__ __forceinline__ void ldsm4(u32& r0, u32& r1, u32& r2, u32& r3, u32 a) {
    asm volatile("ldmatrix.sync.aligned.m8n8.x4.shared.b16 {%0,%1,%2,%3}, [%4];"
                 : "=r"(r0), "=r"(r1), "=r"(r2), "=r"(r3) : "r"(a));
}
static __device__ __forceinline__ void ldsm4t(u32& r0, u32& r1, u32& r2, u32& r3, u32 a) {
    asm volatile("ldmatrix.sync.aligned.m8n8.x4.trans.shared.b16 {%0,%1,%2,%3}, [%4];"
                 : "=r"(r0), "=r"(r1), "=r"(r2), "=r"(r3) : "r"(a));
}
// exact pair split: h2 = {x0>>16, x1>>16}; l2 = bf16rn(residuals), residual exact
static __device__ __forceinline__ void split2(float x0, float x1, u32& h2, u32& l2) {
    u32 b0 = __float_as_uint(x0), b1 = __float_as_uint(x1);
    asm("prmt.b32 %0, %1, %2, 0x7632;" : "=r"(h2) : "r"(b0), "r"(b1));
    float r0 = x0 - __uint_as_float(b0 & 0xffff0000u);
    float r1 = x1 - __uint_as_float(b1 & 0xffff0000u);
    asm("cvt.rn.bf16x2.f32 %0, %1, %2;" : "=r"(l2) : "f"(r1), "f"(r0));
}

// ---------------------------------------------------------------------------
// Scratch (static device globals: allocation-free)
// ---------------------------------------------------------------------------
__device__ float g_M[64 * 64];
__device__ float g_concat[(size_t)B_TOT * 192];
__device__ float g_h[(size_t)B_TOT * 128];
__device__ float g_h2[(size_t)B_TOT * 128];
// pre-split weights, [k][n] row-major bf16
__device__ u16 g_Wgh[1024 * 64],  g_Wgl[1024 * 64];
__device__ u16 g_Wc1h[192 * 128], g_Wc1l[192 * 128];
__device__ u16 g_Wc2h[128 * 128], g_Wc2l[128 * 128];
__device__ u16 g_Ws2h[64 * 64],   g_Ws2l[64 * 64];

// ---------------------------------------------------------------------------
// K0a: M = Wq @ Wk^T
// ---------------------------------------------------------------------------
__global__ void k_prep(const float* __restrict__ Wq, const float* __restrict__ Wk) {
    int e = blockIdx.x * 256 + threadIdx.x;
    if (e < 4096) {
        int i = e >> 6, j = e & 63;
        float s = 0.f;
#pragma unroll
        for (int h = 0; h < 64; h++) s = fmaf(Wq[i * 64 + h], Wk[j * 64 + h], s);
        g_M[e] = s;
    }
}

// ---------------------------------------------------------------------------
// K0b: split weights into bf16 hi/lo (RN split)
// ---------------------------------------------------------------------------
__global__ void k_split(const float* __restrict__ Wg, const float* __restrict__ Wc1,
                        const float* __restrict__ Wc2, const float* __restrict__ Ws2) {
    int i = blockIdx.x * 256 + threadIdx.x;
    const float* src; u16 *dh, *dl; int off;
    if (i < 65536)            { src = Wg;  dh = g_Wgh;  dl = g_Wgl;  off = i; }
    else if (i < 90112)       { src = Wc1; dh = g_Wc1h; dl = g_Wc1l; off = i - 65536; }
    else if (i < 106496)      { src = Wc2; dh = g_Wc2h; dl = g_Wc2l; off = i - 90112; }
    else if (i < 110592)      { src = Ws2; dh = g_Ws2h; dl = g_Ws2l; off = i - 106496; }
    else return;
    float x = src[off];
    __nv_bfloat16 hb = __float2bfloat16(x);
    __nv_bfloat16 lb = __float2bfloat16(x - __bfloat162float(hb));
    dh[off] = __bfloat16_as_ushort(hb);
    dl[off] = __bfloat16_as_ushort(lb);
}

// ---------------------------------------------------------------------------
// Tensor-core GEMM: ldmatrix + pre-split B (unchanged)
// ---------------------------------------------------------------------------
#define MMA_SMEM_BYTES (55296 + 256)

template <int KTOT, int LDA, int LDB>
__global__ __launch_bounds__(256)
void k_mma(const float* __restrict__ A,
           const u16* __restrict__ Bh_g, const u16* __restrict__ Bl_g,
           const float* __restrict__ bias, float* __restrict__ C,
           int ldc, int ccol0) {
    extern __shared__ char smem[];
    const u32 sbase = smem_u32(smem);
    const u32 ah_b = sbase, al_b = sbase + 18432;
    const u32 bh_b = sbase + 36864, bl_b = sbase + 46080;
    float* bs = (float*)(smem + 55296);

    const int tid = threadIdx.x;
    const int wid = tid >> 5, lane = tid & 31;
    const int row0 = blockIdx.x * 128;
    const int bcol = blockIdx.y * 64;
    const int mwarp = wid >> 1, nwarp = wid & 1;
    const int g = lane >> 2, t = lane & 3;
    const int lr = lane & 15, lc = (lane >> 4) << 3;

    if (tid < 64) bs[tid] = bias[bcol + tid];

    float acc[2][4][4];
#pragma unroll
    for (int mt = 0; mt < 2; mt++)
#pragma unroll
        for (int nt = 0; nt < 4; nt++)
#pragma unroll
            for (int r = 0; r < 4; r++) acc[mt][nt][r] = 0.f;

    const int mrow0 = mwarp * 32, ncol0 = nwarp * 32;

    for (int c = 0; c < KTOT / 64; c++) {
        const int k0 = c * 64;
        {
            const int m = tid >> 1, h = tid & 1;
            const float* src = A + (size_t)(row0 + m) * LDA + k0 + h * 32;
            char* dh = smem + m * 144 + h * 64;
            char* dl = smem + 18432 + m * 144 + h * 64;
#pragma unroll
            for (int q = 0; q < 8; q++) {
                float4 v = *reinterpret_cast<const float4*>(src + q * 4);
                uint2 hh, ll;
                split2(v.x, v.y, hh.x, ll.x);
                split2(v.z, v.w, hh.y, ll.y);
                *reinterpret_cast<uint2*>(dh + q * 8) = hh;
                *reinterpret_cast<uint2*>(dl + q * 8) = ll;
            }
        }
        {
            const int kk = tid >> 2, cg = (tid & 3) * 16;
            const u16* sh = Bh_g + (size_t)(k0 + kk) * LDB + bcol + cg;
            const u16* sl = Bl_g + (size_t)(k0 + kk) * LDB + bcol + cg;
            char* dh = smem + 36864 + kk * 144 + cg * 2;
            char* dl = smem + 46080 + kk * 144 + cg * 2;
            *reinterpret_cast<uint4*>(dh)      = *reinterpret_cast<const uint4*>(sh);
            *reinterpret_cast<uint4*>(dh + 16) = *reinterpret_cast<const uint4*>(sh + 8);
            *reinterpret_cast<uint4*>(dl)      = *reinterpret_cast<const uint4*>(sl);
            *reinterpret_cast<uint4*>(dl + 16) = *reinterpret_cast<const uint4*>(sl + 8);
        }
        __syncthreads();

#pragma unroll
        for (int k16 = 0; k16 < 4; k16++) {
            const int kk = k16 * 16;
            u32 bh[8], bl[8];
            ldsm4t(bh[0], bh[1], bh[2], bh[3], bh_b + ((kk + lr) * 72 + ncol0 + lc) * 2);
            ldsm4t(bh[4], bh[5], bh[6], bh[7], bh_b + ((kk + lr) * 72 + ncol0 + 16 + lc) * 2);
            ldsm4t(bl[0], bl[1], bl[2], bl[3], bl_b + ((kk + lr) * 72 + ncol0 + lc) * 2);
            ldsm4t(bl[4], bl[5], bl[6], bl[7], bl_b + ((kk + lr) * 72 + ncol0 + 16 + lc) * 2);
#pragma unroll
            for (int mt = 0; mt < 2; mt++) {
                u32 ah[4], al[4];
                ldsm4(ah[0], ah[1], ah[2], ah[3],
                      ah_b + ((mrow0 + mt * 16 + lr) * 72 + kk + lc) * 2);
                ldsm4(al[0], al[1], al[2], al[3],
                      al_b + ((mrow0 + mt * 16 + lr) * 72 + kk + lc) * 2);
#pragma unroll
                for (int nt = 0; nt < 4; nt++) {
                    mma16816(acc[mt][nt], ah, &bh[nt * 2]);
                    mma16816(acc[mt][nt], ah, &bl[nt * 2]);
                    mma16816(acc[mt][nt], al, &bh[nt * 2]);
                }
            }
        }
        __syncthreads();
    }

#pragma unroll
    for (int mt = 0; mt < 2; mt++) {
#pragma unroll
        for (int nt = 0; nt < 4; nt++) {
            int r = row0 + mrow0 + mt * 16 + g;
            int cl = ncol0 + nt * 8 + t * 2;
            int cg = ccol0 + bcol + cl;
            float b0v = bs[cl], b1v = bs[cl + 1];
            float2 v0, v1;
            v0.x = fmaxf(acc[mt][nt][0] + b0v, 0.f);
            v0.y = fmaxf(acc[mt][nt][1] + b1v, 0.f);
            v1.x = fmaxf(acc[mt][nt][2] + b0v, 0.f);
            v1.y = fmaxf(acc[mt][nt][3] + b1v, 0.f);
            *reinterpret_cast<float2*>(C + (size_t)r * ldc + cg) = v0;
            *reinterpret_cast<float2*>(C + (size_t)(r + 8) * ldc + cg) = v1;
        }
    }
}

// ---------------------------------------------------------------------------
// K2 v4: fused attention, 16 batch rows / CTA, 256 thr, vectorized LDS.
// All f32 work buffers use stride 68 (16B-aligned rows). E2 aliases E1.
// ---------------------------------------------------------------------------
#define AT_E1H   0          // [128][72] u16 (18432)   } union with
#define AT_E1L   18432      // [128][72] u16 (18432)   } E2 [128][68] f32 (34816)
#define AT_E2    0
#define AT_WS2H  36864      // [64][72] u16 (9216)
#define AT_WS2L  46080      // (9216)
#define AT_MS    55296      // 4096 f32
#define AT_WVS   71680      // 4096 f32
#define AT_OWN   88064      // [16][68] f32 (4352)
#define AT_TT    92416      // [16][68] f32 (4352)
#define AT_W0    96768      // 384 f32 (1536)
#define AT_WS1   98304      // 448 f32 (1792)
#define AT_B0    100096     // 64 f32
#define AT_BS1   100352
#define AT_BS2   100608
#define AT_SC    100864     // 128 f32
#define AT_AL    101376     // 128 f32
#define AT_MK    101888     // 128 f32
#define ATTN_SMEM_BYTES 102400

__global__ __launch_bounds__(256, 2)
void k_attn4(const float* __restrict__ S0, const float* __restrict__ S2,
             const float* __restrict__ W0, const float* __restrict__ b0,
             const float* __restrict__ Ws1, const float* __restrict__ bs1,
             const float* __restrict__ bs2, const float* __restrict__ Wv) {
    extern __shared__ char smem[];
    float* E2   = (float*)(smem + AT_E2);
    float* Ms   = (float*)(smem + AT_MS);
    float* Wvs  = (float*)(smem + AT_WVS);
    float* own  = (float*)(smem + AT_OWN);
    float* tt   = (float*)(smem + AT_TT);
    float* W0s  = (float*)(smem + AT_W0);
    float* Ws1s = (float*)(smem + AT_WS1);
    float* b0s  = (float*)(smem + AT_B0);
    float* bs1s = (float*)(smem + AT_BS1);
    float* bs2s = (float*)(smem + AT_BS2);
    float* sc   = (float*)(smem + AT_SC);
    float* al   = (float*)(smem + AT_AL);
    float* mk   = (float*)(smem + AT_MK);
    const u32 sbase = smem_u32(smem);
    const u32 e1h_b = sbase + AT_E1H, e1l_b = sbase + AT_E1L;
    const u32 wsh_b = sbase + AT_WS2H, wsl_b = sbase + AT_WS2L;

    const int tid = threadIdx.x;
    const int wid = tid >> 5, lane = tid & 31;
    const int gb0 = blockIdx.x * 16;

    // ---- init: vectorized weight staging ----
    {   // Ms, Wvs: 4096 f32 each -> 4 uint4 per thread per array
        const float4* gm = reinterpret_cast<const float4*>(g_M);
        const float4* gv = reinterpret_cast<const float4*>(Wv);
        float4* sm4 = reinterpret_cast<float4*>(Ms);
        float4* sv4 = reinterpret_cast<float4*>(Wvs);
#pragma unroll
        for (int q = 0; q < 4; q++) {
            int idx = tid + q * 256;
            sm4[idx] = gm[idx];
            sv4[idx] = gv[idx];
        }
    }
    if (tid < 96)  reinterpret_cast<float4*>(W0s)[tid]  =
        reinterpret_cast<const float4*>(W0)[tid];
    if (tid >= 96 && tid < 208) reinterpret_cast<float4*>(Ws1s)[tid - 96] =
        reinterpret_cast<const float4*>(Ws1)[tid - 96];
    if (tid >= 208 && tid < 224) reinterpret_cast<float4*>(b0s)[tid - 208] =
        reinterpret_cast<const float4*>(b0)[tid - 208];
    if (tid >= 224 && tid < 240) reinterpret_cast<float4*>(bs1s)[tid - 224] =
        reinterpret_cast<const float4*>(bs1)[tid - 224];
    if (tid >= 240) reinterpret_cast<float4*>(bs2s)[tid - 240] =
        reinterpret_cast<const float4*>(bs2)[tid - 240];
    {   // Ws2 pre-split -> smem stride 72
        const int kk = tid >> 2, cg = (tid & 3) * 16;
        const u16* sh = g_Ws2h + kk * 64 + cg;
        const u16* sl = g_Ws2l + kk * 64 + cg;
        char* dh = smem + AT_WS2H + kk * 144 + cg * 2;
        char* dl = smem + AT_WS2L + kk * 144 + cg * 2;
        *reinterpret_cast<uint4*>(dh)      = *reinterpret_cast<const uint4*>(sh);
        *reinterpret_cast<uint4*>(dh + 16) = *reinterpret_cast<const uint4*>(sh + 8);
        *reinterpret_cast<uint4*>(dl)      = *reinterpret_cast<const uint4*>(sl);
        *reinterpret_cast<uint4*>(dl + 16) = *reinterpret_cast<const uint4*>(sl + 8);
    }

    // P1: own_e (16 rows, 4 cols/thread) — float4 weight reads
    {
        const int row = tid >> 4, c0 = (tid & 15) * 4;
        const float* s0 = S0 + (size_t)(gb0 + row) * 6;
        float x0 = s0[0], x1 = s0[1], x2 = s0[2], x3 = s0[3], x4 = s0[4], x5 = s0[5];
        float* og = g_concat + (size_t)(gb0 + row) * 192;
        __syncthreads();  // staging complete
        float4 a4;
        {
            float4 b4 = *reinterpret_cast<const float4*>(b0s + c0);
            a4 = b4;
        }
#pragma unroll
        for (int kk = 0; kk < 6; kk++) {
            float xv = (kk == 0) ? x0 : (kk == 1) ? x1 : (kk == 2) ? x2 :
                       (kk == 3) ? x3 : (kk == 4) ? x4 : x5;
            float4 w4 = *reinterpret_cast<const float4*>(W0s + kk * 64 + c0);
            a4.x = fmaf(xv, w4.x, a4.x); a4.y = fmaf(xv, w4.y, a4.y);
            a4.z = fmaf(xv, w4.z, a4.z); a4.w = fmaf(xv, w4.w, a4.w);
        }
        a4.x = fmaxf(a4.x, 0.f); a4.y = fmaxf(a4.y, 0.f);
        a4.z = fmaxf(a4.z, 0.f); a4.w = fmaxf(a4.w, 0.f);
        *reinterpret_cast<float4*>(own + row * 68 + c0) = a4;
        *reinterpret_cast<float4*>(og + c0) = a4;
    }

    // P2: E1 = relu(S2@Ws1+bs1) -> split bf16; 2 threads/row, 32 cols each
    {
        const int rr = tid >> 1, h = tid & 1, j0 = h * 32;
        const float* s2 = S2 + ((size_t)gb0 * 8 + rr) * 7;
        float y0 = s2[0], y1 = s2[1], y2 = s2[2], y3 = s2[3], y4 = s2[4], y5 = s2[5], y6 = s2[6];
        if (h == 0)
            mk[rr] = ((y0 + y1 + y2 + y3 + y4 + y5 + y6) != 0.f) ? 1.f : 0.f;
        float a[32];
#pragma unroll
        for (int q = 0; q < 8; q++) {
            float4 v4 = *reinterpret_cast<const float4*>(bs1s + j0 + q * 4);
            a[q * 4 + 0] = v4.x; a[q * 4 + 1] = v4.y;
            a[q * 4 + 2] = v4.z; a[q * 4 + 3] = v4.w;
        }
#pragma unroll
        for (int kk = 0; kk < 7; kk++) {
            float yv = (kk == 0) ? y0 : (kk == 1) ? y1 : (kk == 2) ? y2 :
                       (kk == 3) ? y3 : (kk == 4) ? y4 : (kk == 5) ? y5 : y6;
#pragma unroll
            for (int q = 0; q < 8; q++) {
                float4 w4 = *reinterpret_cast<const float4*>(Ws1s + kk * 64 + j0 + q * 4);
                a[q * 4 + 0] = fmaf(yv, w4.x, a[q * 4 + 0]);
                a[q * 4 + 1] = fmaf(yv, w4.y, a[q * 4 + 1]);
                a[q * 4 + 2] = fmaf(yv, w4.z, a[q * 4 + 2]);
                a[q * 4 + 3] = fmaf(yv, w4.w, a[q * 4 + 3]);
            }
        }
#pragma unroll
        for (int j = 0; j < 32; j++) a[j] = fmaxf(a[j], 0.f);
        char* dh = smem + AT_E1H + rr * 144 + j0 * 2;
        char* dl = smem + AT_E1L + rr * 144 + j0 * 2;
#pragma unroll
        for (int q = 0; q < 32; q += 8) {
            uint4 vh, vl;
            split2(a[q + 0], a[q + 1], vh.x, vl.x);
            split2(a[q + 2], a[q + 3], vh.y, vl.y);
            split2(a[q + 4], a[q + 5], vh.z, vl.z);
            split2(a[q + 6], a[q + 7], vh.w, vl.w);
            *reinterpret_cast<uint4*>(dh + q * 2) = vh;
            *reinterpret_cast<uint4*>(dl + q * 2) = vl;
        }
    }
    __syncthreads();

    // P3: E2 = relu(E1 @ Ws2 + bs2) via HMMA; 8 warps 4m x 2n, warp 32x32
    float acc[2][4][4];
    {
        const int mwarp = wid >> 1, nwarp = wid & 1;
        const int lr = lane & 15, lc = (lane >> 4) << 3;
        const int mrow0 = mwarp * 32, ncol0 = nwarp * 32;
#pragma unroll
        for (int mt = 0; mt < 2; mt++)
#pragma unroll
            for (int nt = 0; nt < 4; nt++)
#pragma unroll
                for (int r = 0; r < 4; r++) acc[mt][nt][r] = 0.f;

#pragma unroll
        for (int k16 = 0; k16 < 4; k16++) {
            const int kk = k16 * 16;
            u32 bh[8], bl[8];
            ldsm4t(bh[0], bh[1], bh[2], bh[3], wsh_b + ((kk + lr) * 72 + ncol0 + lc) * 2);
            ldsm4t(bh[4], bh[5], bh[6], bh[7], wsh_b + ((kk + lr) * 72 + ncol0 + 16 + lc) * 2);
            ldsm4t(bl[0], bl[1], bl[2], bl[3], wsl_b + ((kk + lr) * 72 + ncol0 + lc) * 2);
            ldsm4t(bl[4], bl[5], bl[6], bl[7], wsl_b + ((kk + lr) * 72 + ncol0 + 16 + lc) * 2);
#pragma unroll
            for (int mt = 0; mt < 2; mt++) {
                u32 ah[4], alr[4];
                ldsm4(ah[0], ah[1], ah[2], ah[3],
                      e1h_b + ((mrow0 + mt * 16 + lr) * 72 + kk + lc) * 2);
                ldsm4(alr[0], alr[1], alr[2], alr[3],
                      e1l_b + ((mrow0 + mt * 16 + lr) * 72 + kk + lc) * 2);
#pragma unroll
                for (int nt = 0; nt < 4; nt++) {
                    mma16816(acc[mt][nt], ah, &bh[nt * 2]);
                    mma16816(acc[mt][nt], ah, &bl[nt * 2]);
                    mma16816(acc[mt][nt], alr, &bh[nt * 2]);
                }
            }
        }
    }
    __syncthreads();   // E1 reads done; safe to overwrite with E2

    // E2 epilogue (stride 68, float2 stores) + P4 (t = own@M)
    {
        const int mwarp = wid >> 1, nwarp = wid & 1;
        const int g = lane >> 2, t = lane & 3;
        const int mrow0 = mwarp * 32, ncol0 = nwarp * 32;
#pragma unroll
        for (int mt = 0; mt < 2; mt++) {
#pragma unroll
            for (int nt = 0; nt < 4; nt++) {
                int r = mrow0 + mt * 16 + g;
                int cl = ncol0 + nt * 8 + t * 2;
                float b0v = bs2s[cl], b1v = bs2s[cl + 1];
                float2 v0, v1;
                v0.x = fmaxf(acc[mt][nt][0] + b0v, 0.f);
                v0.y = fmaxf(acc[mt][nt][1] + b1v, 0.f);
                v1.x = fmaxf(acc[mt][nt][2] + b0v, 0.f);
                v1.y = fmaxf(acc[mt][nt][3] + b1v, 0.f);
                *reinterpret_cast<float2*>(E2 + r * 68 + cl) = v0;
                *reinterpret_cast<float2*>(E2 + (r + 8) * 68 + cl) = v1;
            }
        }
    }
    {   // P4: t = own @ M, float4 over k and cols
        const int row = tid >> 4, c0 = (tid & 15) * 4;
        float4 a4 = {0.f, 0.f, 0.f, 0.f};
#pragma unroll
        for (int k = 0; k < 64; k += 4) {
            float4 o4 = *reinterpret_cast<const float4*>(own + row * 68 + k);
#pragma unroll
            for (int i = 0; i < 4; i++) {
                float xv = (i == 0) ? o4.x : (i == 1) ? o4.y : (i == 2) ? o4.z : o4.w;
                float4 m4 = *reinterpret_cast<const float4*>(Ms + (k + i) * 64 + c0);
                a4.x = fmaf(xv, m4.x, a4.x); a4.y = fmaf(xv, m4.y, a4.y);
                a4.z = fmaf(xv, m4.z, a4.z); a4.w = fmaf(xv, m4.w, a4.w);
            }
        }
        *reinterpret_cast<float4*>(tt + row * 68 + c0) = a4;
    }
    __syncthreads();

    // P5: scores — 2 threads/row, 32 k each (float4), pair-combine via shfl
    {
        const int rr = tid >> 1, h = tid & 1, k0 = h * 32;
        const int lb = rr >> 3;
        float s = 0.f;
#pragma unroll
        for (int k = 0; k < 32; k += 4) {
            float4 t4 = *reinterpret_cast<const float4*>(tt + lb * 68 + k0 + k);
            float4 e4 = *reinterpret_cast<const float4*>(E2 + rr * 68 + k0 + k);
            s = fmaf(t4.x, e4.x, s); s = fmaf(t4.y, e4.y, s);
            s = fmaf(t4.z, e4.z, s); s = fmaf(t4.w, e4.w, s);
        }
        s += __shfl_xor_sync(0xffffffffu, s, 1);
        if (h == 0)
            sc[rr] = (mk[rr] != 0.f) ? (s * 0.125f) : __int_as_float(0xff800000);
    }
    __syncthreads();

    // P6: softmax over n=8 (16 rows)
    if (tid < 16) {
        float m = __int_as_float(0xff800000);
#pragma unroll
        for (int n = 0; n < 8; n++) m = fmaxf(m, sc[tid * 8 + n]);
        float e[8]; float ssum = 0.f;
#pragma unroll
        for (int n = 0; n < 8; n++) { float v = expf(sc[tid * 8 + n] - m); e[n] = v; ssum += v; }
        float inv = 1.f / ssum;
#pragma unroll
        for (int n = 0; n < 8; n++) al[tid * 8 + n] = e[n] * inv;
    }
    __syncthreads();

    // P7a: wsum = sum_n alpha_n * E2_n -> tt  (float4)
    {
        const int row = tid >> 4, c0 = (tid & 15) * 4;
        float4 a4 = {0.f, 0.f, 0.f, 0.f};
#pragma unroll
        for (int n = 0; n < 8; n++) {
            float av = al[row * 8 + n];
            float4 e4 = *reinterpret_cast<const float4*>(E2 + (row * 8 + n) * 68 + c0);
            a4.x = fmaf(av, e4.x, a4.x); a4.y = fmaf(av, e4.y, a4.y);
            a4.z = fmaf(av, e4.z, a4.z); a4.w = fmaf(av, e4.w, a4.w);
        }
        *reinterpret_cast<float4*>(tt + row * 68 + c0) = a4;
    }
    __syncthreads();

    // P7b: v_att = wsum @ Wv -> g_concat[:,128:192]  (float4)
    {
        const int row = tid >> 4, c0 = (tid & 15) * 4;
        float4 a4 = {0.f, 0.f, 0.f, 0.f};
#pragma unroll
        for (int k = 0; k < 64; k += 4) {
            float4 t4 = *reinterpret_cast<const float4*>(tt + row * 68 + k);
#pragma unroll
            for (int i = 0; i < 4; i++) {
                float xv = (i == 0) ? t4.x : (i == 1) ? t4.y : (i == 2) ? t4.z : t4.w;
                float4 w4 = *reinterpret_cast<const float4*>(Wvs + (k + i) * 64 + c0);
                a4.x = fmaf(xv, w4.x, a4.x); a4.y = fmaf(xv, w4.y, a4.y);
                a4.z = fmaf(xv, w4.z, a4.z); a4.w = fmaf(xv, w4.w, a4.w);
            }
        }
        *reinterpret_cast<float4*>(g_concat + (size_t)(gb0 + row) * 192 + 128 + c0) = a4;
    }
}

// ---------------------------------------------------------------------------
// K4: out = tanh(g_h2 @ Wc3 + bc3)
// ---------------------------------------------------------------------------
__global__ __launch_bounds__(256)
void k_head(const float* __restrict__ Wc3, const float* __restrict__ bc3,
            float* __restrict__ out) {
    __shared__ float W3s[256];
    __shared__ float b3s[2];
    const int tid = threadIdx.x;
    const int wid = tid >> 5, lane = tid & 31;
    W3s[tid] = Wc3[tid];
    if (tid < 2) b3s[tid] = bc3[tid];
    __syncthreads();

    const int row = blockIdx.x * 8 + wid;
    float4 v = *reinterpret_cast<const float4*>(&g_h2[(size_t)row * 128 + lane * 4]);
    float s0 = 0.f, s1 = 0.f;
    int kb = lane * 4;
    s0 = fmaf(v.x, W3s[(kb + 0) * 2 + 0], s0); s1 = fmaf(v.x, W3s[(kb + 0) * 2 + 1], s1);
    s0 = fmaf(v.y, W3s[(kb + 1) * 2 + 0], s0); s1 = fmaf(v.y, W3s[(kb + 1) * 2 + 1], s1);
    s0 = fmaf(v.z, W3s[(kb + 2) * 2 + 0], s0); s1 = fmaf(v.z, W3s[(kb + 2) * 2 + 1], s1);
    s0 = fmaf(v.w, W3s[(kb + 3) * 2 + 0], s0); s1 = fmaf(v.w, W3s[(kb + 3) * 2 + 1], s1);
#pragma unroll
    for (int o = 16; o > 0; o >>= 1) {
        s0 += __shfl_xor_sync(0xffffffffu, s0, o);
        s1 += __shfl_xor_sync(0xffffffffu, s1, o);
    }
    if (lane == 0) {
        float2 o2;
        o2.x = tanhf(s0 + b3s[0]);
        o2.y = tanhf(s1 + b3s[1]);
        *reinterpret_cast<float2*>(out + (size_t)row * 2) = o2;
    }
}

// ---------------------------------------------------------------------------
// kernel_launch
// ---------------------------------------------------------------------------
extern "C" void kernel_launch(void* const* d_in, const int* in_sizes, int n_in,
                              void* d_out, int out_size) {
    const float* S0  = (const float*)d_in[0];
    const float* S1  = (const float*)d_in[1];
    const float* S2  = (const float*)d_in[2];
    const float* W0  = (const float*)d_in[3];
    const float* b0  = (const float*)d_in[4];
    const float* Wg  = (const float*)d_in[5];
    const float* bg  = (const float*)d_in[6];
    const float* Ws1 = (const float*)d_in[7];
    const float* bs1 = (const float*)d_in[8];
    const float* Ws2 = (const float*)d_in[9];
    const float* bs2 = (const float*)d_in[10];
    const float* Wq  = (const float*)d_in[11];
    const float* Wk  = (const float*)d_in[12];
    const float* Wv  = (const float*)d_in[13];
    const float* Wc1 = (const float*)d_in[14];
    const float* bc1 = (const float*)d_in[15];
    const float* Wc2 = (const float*)d_in[16];
    const float* bc2 = (const float*)d_in[17];
    const float* Wc3 = (const float*)d_in[18];
    const float* bc3 = (const float*)d_in[19];
    float* out = (float*)d_out;

    void* p;
    cudaGetSymbolAddress(&p, g_concat); float* C  = (float*)p;
    cudaGetSymbolAddress(&p, g_h);      float* Hb = (float*)p;
    cudaGetSymbolAddress(&p, g_h2);     float* H2 = (float*)p;
    cudaGetSymbolAddress(&p, g_Wgh);  u16* Wgh  = (u16*)p;
    cudaGetSymbolAddress(&p, g_Wgl);  u16* Wgl  = (u16*)p;
    cudaGetSymbolAddress(&p, g_Wc1h); u16* Wc1h = (u16*)p;
    cudaGetSymbolAddress(&p, g_Wc1l); u16* Wc1l = (u16*)p;
    cudaGetSymbolAddress(&p, g_Wc2h); u16* Wc2h = (u16*)p;
    cudaGetSymbolAddress(&p, g_Wc2l); u16* Wc2l = (u16*)p;

    cudaFuncSetAttribute(k_attn4, cudaFuncAttributeMaxDynamicSharedMemorySize,
                         ATTN_SMEM_BYTES);
    cudaFuncSetAttribute(k_mma<1024, 1024, 64>,
                         cudaFuncAttributeMaxDynamicSharedMemorySize, MMA_SMEM_BYTES);
    cudaFuncSetAttribute(k_mma<192, 192, 128>,
                         cudaFuncAttributeMaxDynamicSharedMemorySize, MMA_SMEM_BYTES);
    cudaFuncSetAttribute(k_mma<128, 128, 128>,
                         cudaFuncAttributeMaxDynamicSharedMemorySize, MMA_SMEM_BYTES);

    k_prep<<<16, 256>>>(Wq, Wk);
    k_split<<<432, 256>>>(Wg, Wc1, Wc2, Ws2);
    // K1: env_e -> g_concat[:,64:128]
    k_mma<1024, 1024, 64><<<dim3(B_TOT / 128, 1), 256, MMA_SMEM_BYTES>>>(
        S1, Wgh, Wgl, bg, C, 192, 64);
    // K2: own_e + attention -> g_concat[:,0:64], [:,128:192]
    k_attn4<<<B_TOT / 16, 256, ATTN_SMEM_BYTES>>>(S0, S2, W0, b0, Ws1, bs1, bs2, Wv);
    // K3a: h1 = relu(concat @ Wc1 + bc1)
    k_mma<192, 192, 128><<<dim3(B_TOT / 128, 2), 256, MMA_SMEM_BYTES>>>(
        C, Wc1h, Wc1l, bc1, Hb, 128, 0);
    // K3b: h2 = relu(h1 @ Wc2 + bc2)
    k_mma<128, 128, 128><<<dim3(B_TOT / 128, 2), 256, MMA_SMEM_BYTES>>>(
        Hb, Wc2h, Wc2l, bc2, H2, 128, 0);
    // K4: out
    k_head<<<B_TOT / 8, 256>>>(Wc3, bc3, out);
}

// round 8
// speedup vs baseline: 1.9183x; 1.1387x over previous
#include <cuda_runtime.h>
#include <cuda_bf16.h>
#include <math.h>
#include <stdint.h>

#define B_TOT 65536
// H=64, HC=128, N=8, OBS0=6, OBS1=1024, OBS2=7, NA=2

typedef unsigned long long u64;
typedef unsigned short u16;
typedef unsigned int u32;

// ---------------------------------------------------------------------------
// helpers
// ---------------------------------------------------------------------------
static __device__ __forceinline__ uint32_t smem_u32(const void* p) {
    uint32_t a;
    asm("{ .reg .u64 t; cvta.to.shared.u64 t, %1; cvt.u32.u64 %0, t; }"
        : "=r"(a) : "l"(p));
    return a;
}
static __device__ __forceinline__ void mma16816(float* c, const u32* a, const u32* b) {
    asm volatile(
        "mma.sync.aligned.m16n8k16.row.col.f32.bf16.bf16.f32 "
        "{%0,%1,%2,%3}, {%4,%5,%6,%7}, {%8,%9}, {%0,%1,%2,%3};"
        : "+f"(c[0]), "+f"(c[1]), "+f"(c[2]), "+f"(c[3])
        : "r"(a[0]), "r"(a[1]), "r"(a[2]), "r"(a[3]), "r"(b[0]), "r"(b[1]));
}
static __device__ __forceinline__ void ldsm4(u32& r0, u32& r1, u32& r2, u32& r3, u32 a) {
    asm volatile("ldmatrix.sync.aligned.m8n8.x4.shared.b16 {%0,%1,%2,%3}, [%4];"
                 : "=r"(r0), "=r"(r1), "=r"(r2), "=r"(r3) : "r"(a));
}
static __device__ __forceinline__ void ldsm4t(u32& r0, u32& r1, u32& r2, u32& r3, u32 a) {
    asm volatile("ldmatrix.sync.aligned.m8n8.x4.trans.shared.b16 {%0,%1,%2,%3}, [%4];"
                 : "=r"(r0), "=r"(r1), "=r"(r2), "=r"(r3) : "r"(a));
}
// exact pair split: h2 = {x0>>16, x1>>16}; l2 = bf16rn(residuals)
static __device__ __forceinline__ void split2(float x0, float x1, u32& h2, u32& l2) {
    u32 b0 = __float_as_uint(x0), b1 = __float_as_uint(x1);
    asm("prmt.b32 %0, %1, %2, 0x7632;" : "=r"(h2) : "r"(b0), "r"(b1));
    float r0 = x0 - __uint_as_float(b0 & 0xffff0000u);
    float r1 = x1 - __uint_as_float(b1 & 0xffff0000u);
    asm("cvt.rn.bf16x2.f32 %0, %1, %2;" : "=r"(l2) : "f"(r1), "f"(r0));
}

// ---------------------------------------------------------------------------
// Scratch (static device globals: allocation-free)
// ---------------------------------------------------------------------------
__device__ float g_concat[(size_t)B_TOT * 192];
__device__ float g_h[(size_t)B_TOT * 128];
__device__ float g_h2[(size_t)B_TOT * 128];
// pre-split weights, [k][n] row-major bf16
__device__ u16 g_Wgh[1024 * 64],  g_Wgl[1024 * 64];
__device__ u16 g_Wc1h[192 * 128], g_Wc1l[192 * 128];
__device__ u16 g_Wc2h[128 * 128], g_Wc2l[128 * 128];
__device__ u16 g_Ws2h[64 * 64],   g_Ws2l[64 * 64];
__device__ u16 g_Mh[64 * 64],     g_Ml[64 * 64];      // Wq@Wk^T split
__device__ u16 g_Wvh[64 * 64],    g_Wvl[64 * 64];

// ---------------------------------------------------------------------------
// K0a: M = Wq @ Wk^T (split bf16 output)
// ---------------------------------------------------------------------------
__global__ void k_prep(const float* __restrict__ Wq, const float* __restrict__ Wk) {
    int e = blockIdx.x * 256 + threadIdx.x;
    if (e < 4096) {
        int i = e >> 6, j = e & 63;
        float s = 0.f;
#pragma unroll
        for (int h = 0; h < 64; h++) s = fmaf(Wq[i * 64 + h], Wk[j * 64 + h], s);
        __nv_bfloat16 hb = __float2bfloat16(s);
        __nv_bfloat16 lb = __float2bfloat16(s - __bfloat162float(hb));
        g_Mh[e] = __bfloat16_as_ushort(hb);
        g_Ml[e] = __bfloat16_as_ushort(lb);
    }
}

// ---------------------------------------------------------------------------
// K0b: split weights into bf16 hi/lo (RN split)
// ---------------------------------------------------------------------------
__global__ void k_split(const float* __restrict__ Wg, const float* __restrict__ Wc1,
                        const float* __restrict__ Wc2, const float* __restrict__ Ws2,
                        const float* __restrict__ Wv) {
    int i = blockIdx.x * 256 + threadIdx.x;
    const float* src; u16 *dh, *dl; int off;
    if (i < 65536)       { src = Wg;  dh = g_Wgh;  dl = g_Wgl;  off = i; }
    else if (i < 90112)  { src = Wc1; dh = g_Wc1h; dl = g_Wc1l; off = i - 65536; }
    else if (i < 106496) { src = Wc2; dh = g_Wc2h; dl = g_Wc2l; off = i - 90112; }
    else if (i < 110592) { src = Ws2; dh = g_Ws2h; dl = g_Ws2l; off = i - 106496; }
    else if (i < 114688) { src = Wv;  dh = g_Wvh;  dl = g_Wvl;  off = i - 110592; }
    else return;
    float x = src[off];
    __nv_bfloat16 hb = __float2bfloat16(x);
    __nv_bfloat16 lb = __float2bfloat16(x - __bfloat162float(hb));
    dh[off] = __bfloat16_as_ushort(hb);
    dl[off] = __bfloat16_as_ushort(lb);
}

// ---------------------------------------------------------------------------
// Tensor-core GEMM: ldmatrix + pre-split B (unchanged)
// ---------------------------------------------------------------------------
#define MMA_SMEM_BYTES (55296 + 256)

template <int KTOT, int LDA, int LDB>
__global__ __launch_bounds__(256)
void k_mma(const float* __restrict__ A,
           const u16* __restrict__ Bh_g, const u16* __restrict__ Bl_g,
           const float* __restrict__ bias, float* __restrict__ C,
           int ldc, int ccol0) {
    extern __shared__ char smem[];
    const u32 sbase = smem_u32(smem);
    const u32 ah_b = sbase, al_b = sbase + 18432;
    const u32 bh_b = sbase + 36864, bl_b = sbase + 46080;
    float* bs = (float*)(smem + 55296);

    const int tid = threadIdx.x;
    const int wid = tid >> 5, lane = tid & 31;
    const int row0 = blockIdx.x * 128;
    const int bcol = blockIdx.y * 64;
    const int mwarp = wid >> 1, nwarp = wid & 1;
    const int g = lane >> 2, t = lane & 3;
    const int lr = lane & 15, lc = (lane >> 4) << 3;

    if (tid < 64) bs[tid] = bias[bcol + tid];

    float acc[2][4][4];
#pragma unroll
    for (int mt = 0; mt < 2; mt++)
#pragma unroll
        for (int nt = 0; nt < 4; nt++)
#pragma unroll
            for (int r = 0; r < 4; r++) acc[mt][nt][r] = 0.f;

    const int mrow0 = mwarp * 32, ncol0 = nwarp * 32;

    for (int c = 0; c < KTOT / 64; c++) {
        const int k0 = c * 64;
        {
            const int m = tid >> 1, h = tid & 1;
            const float* src = A + (size_t)(row0 + m) * LDA + k0 + h * 32;
            char* dh = smem + m * 144 + h * 64;
            char* dl = smem + 18432 + m * 144 + h * 64;
#pragma unroll
            for (int q = 0; q < 8; q++) {
                float4 v = *reinterpret_cast<const float4*>(src + q * 4);
                uint2 hh, ll;
                split2(v.x, v.y, hh.x, ll.x);
                split2(v.z, v.w, hh.y, ll.y);
                *reinterpret_cast<uint2*>(dh + q * 8) = hh;
                *reinterpret_cast<uint2*>(dl + q * 8) = ll;
            }
        }
        {
            const int kk = tid >> 2, cg = (tid & 3) * 16;
            const u16* sh = Bh_g + (size_t)(k0 + kk) * LDB + bcol + cg;
            const u16* sl = Bl_g + (size_t)(k0 + kk) * LDB + bcol + cg;
            char* dh = smem + 36864 + kk * 144 + cg * 2;
            char* dl = smem + 46080 + kk * 144 + cg * 2;
            *reinterpret_cast<uint4*>(dh)      = *reinterpret_cast<const uint4*>(sh);
            *reinterpret_cast<uint4*>(dh + 16) = *reinterpret_cast<const uint4*>(sh + 8);
            *reinterpret_cast<uint4*>(dl)      = *reinterpret_cast<const uint4*>(sl);
            *reinterpret_cast<uint4*>(dl + 16) = *reinterpret_cast<const uint4*>(sl + 8);
        }
        __syncthreads();

#pragma unroll
        for (int k16 = 0; k16 < 4; k16++) {
            const int kk = k16 * 16;
            u32 bh[8], bl[8];
            ldsm4t(bh[0], bh[1], bh[2], bh[3], bh_b + ((kk + lr) * 72 + ncol0 + lc) * 2);
            ldsm4t(bh[4], bh[5], bh[6], bh[7], bh_b + ((kk + lr) * 72 + ncol0 + 16 + lc) * 2);
            ldsm4t(bl[0], bl[1], bl[2], bl[3], bl_b + ((kk + lr) * 72 + ncol0 + lc) * 2);
            ldsm4t(bl[4], bl[5], bl[6], bl[7], bl_b + ((kk + lr) * 72 + ncol0 + 16 + lc) * 2);
#pragma unroll
            for (int mt = 0; mt < 2; mt++) {
                u32 ah[4], al[4];
                ldsm4(ah[0], ah[1], ah[2], ah[3],
                      ah_b + ((mrow0 + mt * 16 + lr) * 72 + kk + lc) * 2);
                ldsm4(al[0], al[1], al[2], al[3],
                      al_b + ((mrow0 + mt * 16 + lr) * 72 + kk + lc) * 2);
#pragma unroll
                for (int nt = 0; nt < 4; nt++) {
                    mma16816(acc[mt][nt], ah, &bh[nt * 2]);
                    mma16816(acc[mt][nt], ah, &bl[nt * 2]);
                    mma16816(acc[mt][nt], al, &bh[nt * 2]);
                }
            }
        }
        __syncthreads();
    }

#pragma unroll
    for (int mt = 0; mt < 2; mt++) {
#pragma unroll
        for (int nt = 0; nt < 4; nt++) {
            int r = row0 + mrow0 + mt * 16 + g;
            int cl = ncol0 + nt * 8 + t * 2;
            int cg = ccol0 + bcol + cl;
            float b0v = bs[cl], b1v = bs[cl + 1];
            float2 v0, v1;
            v0.x = fmaxf(acc[mt][nt][0] + b0v, 0.f);
            v0.y = fmaxf(acc[mt][nt][1] + b1v, 0.f);
            v1.x = fmaxf(acc[mt][nt][2] + b0v, 0.f);
            v1.y = fmaxf(acc[mt][nt][3] + b1v, 0.f);
            *reinterpret_cast<float2*>(C + (size_t)r * ldc + cg) = v0;
            *reinterpret_cast<float2*>(C + (size_t)(r + 8) * ldc + cg) = v1;
        }
    }
}

// ---------------------------------------------------------------------------
// K2 v5: fused attention, 16 batch rows / CTA, 256 thr.
// P3, P4 (own@M) and P7b (wsum@Wv) all on HMMA. ~106.8 KB smem, 2 CTA/SM.
// ---------------------------------------------------------------------------
#define AT_E1H   0          // [128][72] u16   } union with E2 [128][68] f32 (34816)
#define AT_E1L   18432
#define AT_E2    0
#define AT_WS2H  36864      // [64][72] u16
#define AT_WS2L  46080
#define AT_MH    55296      // [64][72] u16
#define AT_ML    64512
#define AT_WVH   73728      // [64][72] u16
#define AT_WVL   82944
#define AT_OWNH  92160      // [16][72] u16 (own split; later wsum split)
#define AT_OWNL  94464
#define AT_TT    96768      // [16][68] f32 (t, later wsum f32 scratch unused)
#define AT_W0    101120     // 384 f32
#define AT_WS1   102656     // 448 f32
#define AT_B0    104448     // 64 f32
#define AT_BS1   104704
#define AT_BS2   104960
#define AT_SC    105216     // 128 f32
#define AT_AL    105728
#define AT_MK    106240
#define ATTN_SMEM_BYTES 106752

__global__ __launch_bounds__(256, 2)
void k_attn5(const float* __restrict__ S0, const float* __restrict__ S2,
             const float* __restrict__ W0, const float* __restrict__ b0,
             const float* __restrict__ Ws1, const float* __restrict__ bs1,
             const float* __restrict__ bs2) {
    extern __shared__ char smem[];
    float* E2   = (float*)(smem + AT_E2);
    float* tt   = (float*)(smem + AT_TT);
    float* W0s  = (float*)(smem + AT_W0);
    float* Ws1s = (float*)(smem + AT_WS1);
    float* b0s  = (float*)(smem + AT_B0);
    float* bs1s = (float*)(smem + AT_BS1);
    float* bs2s = (float*)(smem + AT_BS2);
    float* sc   = (float*)(smem + AT_SC);
    float* al   = (float*)(smem + AT_AL);
    float* mk   = (float*)(smem + AT_MK);
    const u32 sbase = smem_u32(smem);
    const u32 e1h_b = sbase + AT_E1H, e1l_b = sbase + AT_E1L;
    const u32 wsh_b = sbase + AT_WS2H, wsl_b = sbase + AT_WS2L;
    const u32 mh_b  = sbase + AT_MH,   ml_b  = sbase + AT_ML;
    const u32 wvh_b = sbase + AT_WVH,  wvl_b = sbase + AT_WVL;
    const u32 ownh_b = sbase + AT_OWNH, ownl_b = sbase + AT_OWNL;

    const int tid = threadIdx.x;
    const int wid = tid >> 5, lane = tid & 31;
    const int gb0 = blockIdx.x * 16;

    // ---- init: stage small f32 weights + 3 split matrices (stride 72) ----
    if (tid < 96)  reinterpret_cast<float4*>(W0s)[tid]  =
        reinterpret_cast<const float4*>(W0)[tid];
    if (tid >= 96 && tid < 208) reinterpret_cast<float4*>(Ws1s)[tid - 96] =
        reinterpret_cast<const float4*>(Ws1)[tid - 96];
    if (tid >= 208 && tid < 224) reinterpret_cast<float4*>(b0s)[tid - 208] =
        reinterpret_cast<const float4*>(b0)[tid - 208];
    if (tid >= 224 && tid < 240) reinterpret_cast<float4*>(bs1s)[tid - 224] =
        reinterpret_cast<const float4*>(bs1)[tid - 224];
    if (tid >= 240) reinterpret_cast<float4*>(bs2s)[tid - 240] =
        reinterpret_cast<const float4*>(bs2)[tid - 240];
    {
        const int kk = tid >> 2, cg = (tid & 3) * 16;
        const int go = kk * 64 + cg;
        const int so = kk * 144 + cg * 2;
        const u16* srcs[6] = {g_Ws2h, g_Ws2l, g_Mh, g_Ml, g_Wvh, g_Wvl};
        const int offs[6] = {AT_WS2H, AT_WS2L, AT_MH, AT_ML, AT_WVH, AT_WVL};
#pragma unroll
        for (int a = 0; a < 6; a++) {
            char* d = smem + offs[a] + so;
            *reinterpret_cast<uint4*>(d)      = *reinterpret_cast<const uint4*>(srcs[a] + go);
            *reinterpret_cast<uint4*>(d + 16) = *reinterpret_cast<const uint4*>(srcs[a] + go + 8);
        }
    }

    // P1: own_e (16 rows, 4 cols/thread) -> split bf16 smem + f32 g_concat
    {
        const int row = tid >> 4, c0 = (tid & 15) * 4;
        const float* s0 = S0 + (size_t)(gb0 + row) * 6;
        float x0 = s0[0], x1 = s0[1], x2 = s0[2], x3 = s0[3], x4 = s0[4], x5 = s0[5];
        float* og = g_concat + (size_t)(gb0 + row) * 192;
        __syncthreads();  // staging complete
        float4 a4 = *reinterpret_cast<const float4*>(b0s + c0);
#pragma unroll
        for (int kk = 0; kk < 6; kk++) {
            float xv = (kk == 0) ? x0 : (kk == 1) ? x1 : (kk == 2) ? x2 :
                       (kk == 3) ? x3 : (kk == 4) ? x4 : x5;
            float4 w4 = *reinterpret_cast<const float4*>(W0s + kk * 64 + c0);
            a4.x = fmaf(xv, w4.x, a4.x); a4.y = fmaf(xv, w4.y, a4.y);
            a4.z = fmaf(xv, w4.z, a4.z); a4.w = fmaf(xv, w4.w, a4.w);
        }
        a4.x = fmaxf(a4.x, 0.f); a4.y = fmaxf(a4.y, 0.f);
        a4.z = fmaxf(a4.z, 0.f); a4.w = fmaxf(a4.w, 0.f);
        uint2 hh, ll;
        split2(a4.x, a4.y, hh.x, ll.x);
        split2(a4.z, a4.w, hh.y, ll.y);
        *reinterpret_cast<uint2*>(smem + AT_OWNH + row * 144 + c0 * 2) = hh;
        *reinterpret_cast<uint2*>(smem + AT_OWNL + row * 144 + c0 * 2) = ll;
        *reinterpret_cast<float4*>(og + c0) = a4;
    }

    // P2: E1 = relu(S2@Ws1+bs1) -> split bf16; 2 threads/row, 32 cols each
    {
        const int rr = tid >> 1, h = tid & 1, j0 = h * 32;
        const float* s2 = S2 + ((size_t)gb0 * 8 + rr) * 7;
        float y0 = s2[0], y1 = s2[1], y2 = s2[2], y3 = s2[3], y4 = s2[4], y5 = s2[5], y6 = s2[6];
        if (h == 0)
            mk[rr] = ((y0 + y1 + y2 + y3 + y4 + y5 + y6) != 0.f) ? 1.f : 0.f;
        float a[32];
#pragma unroll
        for (int q = 0; q < 8; q++) {
            float4 v4 = *reinterpret_cast<const float4*>(bs1s + j0 + q * 4);
            a[q * 4 + 0] = v4.x; a[q * 4 + 1] = v4.y;
            a[q * 4 + 2] = v4.z; a[q * 4 + 3] = v4.w;
        }
#pragma unroll
        for (int kk = 0; kk < 7; kk++) {
            float yv = (kk == 0) ? y0 : (kk == 1) ? y1 : (kk == 2) ? y2 :
                       (kk == 3) ? y3 : (kk == 4) ? y4 : (kk == 5) ? y5 : y6;
#pragma unroll
            for (int q = 0; q < 8; q++) {
                float4 w4 = *reinterpret_cast<const float4*>(Ws1s + kk * 64 + j0 + q * 4);
                a[q * 4 + 0] = fmaf(yv, w4.x, a[q * 4 + 0]);
                a[q * 4 + 1] = fmaf(yv, w4.y, a[q * 4 + 1]);
                a[q * 4 + 2] = fmaf(yv, w4.z, a[q * 4 + 2]);
                a[q * 4 + 3] = fmaf(yv, w4.w, a[q * 4 + 3]);
            }
        }
#pragma unroll
        for (int j = 0; j < 32; j++) a[j] = fmaxf(a[j], 0.f);
        char* dh = smem + AT_E1H + rr * 144 + j0 * 2;
        char* dl = smem + AT_E1L + rr * 144 + j0 * 2;
#pragma unroll
        for (int q = 0; q < 32; q += 8) {
            uint4 vh, vl;
            split2(a[q + 0], a[q + 1], vh.x, vl.x);
            split2(a[q + 2], a[q + 3], vh.y, vl.y);
            split2(a[q + 4], a[q + 5], vh.z, vl.z);
            split2(a[q + 6], a[q + 7], vh.w, vl.w);
            *reinterpret_cast<uint4*>(dh + q * 2) = vh;
            *reinterpret_cast<uint4*>(dl + q * 2) = vl;
        }
    }
    __syncthreads();

    // P3: E2 = relu(E1 @ Ws2 + bs2) via HMMA; 8 warps 4m x 2n, warp 32x32
    float acc[2][4][4];
    {
        const int mwarp = wid >> 1, nwarp = wid & 1;
        const int lr = lane & 15, lc = (lane >> 4) << 3;
        const int mrow0 = mwarp * 32, ncol0 = nwarp * 32;
#pragma unroll
        for (int mt = 0; mt < 2; mt++)
#pragma unroll
            for (int nt = 0; nt < 4; nt++)
#pragma unroll
                for (int r = 0; r < 4; r++) acc[mt][nt][r] = 0.f;

#pragma unroll
        for (int k16 = 0; k16 < 4; k16++) {
            const int kk = k16 * 16;
            u32 bh[8], bl[8];
            ldsm4t(bh[0], bh[1], bh[2], bh[3], wsh_b + ((kk + lr) * 72 + ncol0 + lc) * 2);
            ldsm4t(bh[4], bh[5], bh[6], bh[7], wsh_b + ((kk + lr) * 72 + ncol0 + 16 + lc) * 2);
            ldsm4t(bl[0], bl[1], bl[2], bl[3], wsl_b + ((kk + lr) * 72 + ncol0 + lc) * 2);
            ldsm4t(bl[4], bl[5], bl[6], bl[7], wsl_b + ((kk + lr) * 72 + ncol0 + 16 + lc) * 2);
#pragma unroll
            for (int mt = 0; mt < 2; mt++) {
                u32 ah[4], alr[4];
                ldsm4(ah[0], ah[1], ah[2], ah[3],
                      e1h_b + ((mrow0 + mt * 16 + lr) * 72 + kk + lc) * 2);
                ldsm4(alr[0], alr[1], alr[2], alr[3],
                      e1l_b + ((mrow0 + mt * 16 + lr) * 72 + kk + lc) * 2);
#pragma unroll
                for (int nt = 0; nt < 4; nt++) {
                    mma16816(acc[mt][nt], ah, &bh[nt * 2]);
                    mma16816(acc[mt][nt], ah, &bl[nt * 2]);
                    mma16816(acc[mt][nt], alr, &bh[nt * 2]);
                }
            }
        }
    }
    __syncthreads();   // E1 reads done; safe to overwrite with E2

    // E2 epilogue (stride 68, float2 stores) — all warps
    {
        const int mwarp = wid >> 1, nwarp = wid & 1;
        const int g = lane >> 2, t = lane & 3;
        const int mrow0 = mwarp * 32, ncol0 = nwarp * 32;
#pragma unroll
        for (int mt = 0; mt < 2; mt++) {
#pragma unroll
            for (int nt = 0; nt < 4; nt++) {
                int r = mrow0 + mt * 16 + g;
                int cl = ncol0 + nt * 8 + t * 2;
                float b0v = bs2s[cl], b1v = bs2s[cl + 1];
                float2 v0, v1;
                v0.x = fmaxf(acc[mt][nt][0] + b0v, 0.f);
                v0.y = fmaxf(acc[mt][nt][1] + b1v, 0.f);
                v1.x = fmaxf(acc[mt][nt][2] + b0v, 0.f);
                v1.y = fmaxf(acc[mt][nt][3] + b1v, 0.f);
                *reinterpret_cast<float2*>(E2 + r * 68 + cl) = v0;
                *reinterpret_cast<float2*>(E2 + (r + 8) * 68 + cl) = v1;
            }
        }
    }
    // P4: t = own @ M via HMMA (warps 0-3, 16 cols each)
    if (wid < 4) {
        const int ncol0 = wid * 16;
        const int lr = lane & 15, lc = (lane >> 4) << 3;
        float tac[2][4];
#pragma unroll
        for (int nt = 0; nt < 2; nt++)
#pragma unroll
            for (int r = 0; r < 4; r++) tac[nt][r] = 0.f;
#pragma unroll
        for (int k16 = 0; k16 < 4; k16++) {
            const int kk = k16 * 16;
            u32 bh[4], bl[4], ah[4], alr[4];
            ldsm4t(bh[0], bh[1], bh[2], bh[3], mh_b + ((kk + lr) * 72 + ncol0 + lc) * 2);
            ldsm4t(bl[0], bl[1], bl[2], bl[3], ml_b + ((kk + lr) * 72 + ncol0 + lc) * 2);
            ldsm4(ah[0], ah[1], ah[2], ah[3], ownh_b + lr * 144 + (kk + lc) * 2);
            ldsm4(alr[0], alr[1], alr[2], alr[3], ownl_b + lr * 144 + (kk + lc) * 2);
#pragma unroll
            for (int nt = 0; nt < 2; nt++) {
                mma16816(tac[nt], ah, &bh[nt * 2]);
                mma16816(tac[nt], ah, &bl[nt * 2]);
                mma16816(tac[nt], alr, &bh[nt * 2]);
            }
        }
        const int g = lane >> 2, tq = lane & 3;
#pragma unroll
        for (int nt = 0; nt < 2; nt++) {
            int cl = ncol0 + nt * 8 + tq * 2;
            *reinterpret_cast<float2*>(tt + g * 68 + cl) =
                make_float2(tac[nt][0], tac[nt][1]);
            *reinterpret_cast<float2*>(tt + (g + 8) * 68 + cl) =
                make_float2(tac[nt][2], tac[nt][3]);
        }
    }
    __syncthreads();

    // P5: scores — 2 threads/row, 32 k each (float4), pair-combine via shfl
    {
        const int rr = tid >> 1, h = tid & 1, k0 = h * 32;
        const int lb = rr >> 3;
        float s = 0.f;
#pragma unroll
        for (int k = 0; k < 32; k += 4) {
            float4 t4 = *reinterpret_cast<const float4*>(tt + lb * 68 + k0 + k);
            float4 e4 = *reinterpret_cast<const float4*>(E2 + rr * 68 + k0 + k);
            s = fmaf(t4.x, e4.x, s); s = fmaf(t4.y, e4.y, s);
            s = fmaf(t4.z, e4.z, s); s = fmaf(t4.w, e4.w, s);
        }
        s += __shfl_xor_sync(0xffffffffu, s, 1);
        if (h == 0)
            sc[rr] = (mk[rr] != 0.f) ? (s * 0.125f) : __int_as_float(0xff800000);
    }
    __syncthreads();

    // P6: softmax over n=8 (16 rows)
    if (tid < 16) {
        float m = __int_as_float(0xff800000);
#pragma unroll
        for (int n = 0; n < 8; n++) m = fmaxf(m, sc[tid * 8 + n]);
        float e[8]; float ssum = 0.f;
#pragma unroll
        for (int n = 0; n < 8; n++) { float v = expf(sc[tid * 8 + n] - m); e[n] = v; ssum += v; }
        float inv = 1.f / ssum;
#pragma unroll
        for (int n = 0; n < 8; n++) al[tid * 8 + n] = e[n] * inv;
    }
    __syncthreads();

    // P7a: wsum = sum_n alpha_n * E2_n -> split bf16 (aliases own buffers)
    {
        const int row = tid >> 4, c0 = (tid & 15) * 4;
        float4 a4 = {0.f, 0.f, 0.f, 0.f};
#pragma unroll
        for (int n = 0; n < 8; n++) {
            float av = al[row * 8 + n];
            float4 e4 = *reinterpret_cast<const float4*>(E2 + (row * 8 + n) * 68 + c0);
            a4.x = fmaf(av, e4.x, a4.x); a4.y = fmaf(av, e4.y, a4.y);
            a4.z = fmaf(av, e4.z, a4.z); a4.w = fmaf(av, e4.w, a4.w);
        }
        uint2 hh, ll;
        split2(a4.x, a4.y, hh.x, ll.x);
        split2(a4.z, a4.w, hh.y, ll.y);
        *reinterpret_cast<uint2*>(smem + AT_OWNH + row * 144 + c0 * 2) = hh;
        *reinterpret_cast<uint2*>(smem + AT_OWNL + row * 144 + c0 * 2) = ll;
    }
    __syncthreads();

    // P7b: v_att = wsum @ Wv via HMMA (warps 0-3) -> g_concat[:,128:192]
    if (wid < 4) {
        const int ncol0 = wid * 16;
        const int lr = lane & 15, lc = (lane >> 4) << 3;
        float vac[2][4];
#pragma unroll
        for (int nt = 0; nt < 2; nt++)
#pragma unroll
            for (int r = 0; r < 4; r++) vac[nt][r] = 0.f;
#pragma unroll
        for (int k16 = 0; k16 < 4; k16++) {
            const int kk = k16 * 16;
            u32 bh[4], bl[4], ah[4], alr[4];
            ldsm4t(bh[0], bh[1], bh[2], bh[3], wvh_b + ((kk + lr) * 72 + ncol0 + lc) * 2);
            ldsm4t(bl[0], bl[1], bl[2], bl[3], wvl_b + ((kk + lr) * 72 + ncol0 + lc) * 2);
            ldsm4(ah[0], ah[1], ah[2], ah[3], ownh_b + lr * 144 + (kk + lc) * 2);
            ldsm4(alr[0], alr[1], alr[2], alr[3], ownl_b + lr * 144 + (kk + lc) * 2);
#pragma unroll
            for (int nt = 0; nt < 2; nt++) {
                mma16816(vac[nt], ah, &bh[nt * 2]);
                mma16816(vac[nt], ah, &bl[nt * 2]);
                mma16816(vac[nt], alr, &bh[nt * 2]);
            }
        }
        const int g = lane >> 2, tq = lane & 3;
#pragma unroll
        for (int nt = 0; nt < 2; nt++) {
            int cl = ncol0 + nt * 8 + tq * 2;
            *reinterpret_cast<float2*>(g_concat + (size_t)(gb0 + g) * 192 + 128 + cl) =
                make_float2(vac[nt][0], vac[nt][1]);
            *reinterpret_cast<float2*>(g_concat + (size_t)(gb0 + g + 8) * 192 + 128 + cl) =
                make_float2(vac[nt][2], vac[nt][3]);
        }
    }
}

// ---------------------------------------------------------------------------
// K4: out = tanh(g_h2 @ Wc3 + bc3)
// ---------------------------------------------------------------------------
__global__ __launch_bounds__(256)
void k_head(const float* __restrict__ Wc3, const float* __restrict__ bc3,
            float* __restrict__ out) {
    __shared__ float W3s[256];
    __shared__ float b3s[2];
    const int tid = threadIdx.x;
    const int wid = tid >> 5, lane = tid & 31;
    W3s[tid] = Wc3[tid];
    if (tid < 2) b3s[tid] = bc3[tid];
    __syncthreads();

    const int row = blockIdx.x * 8 + wid;
    float4 v = *reinterpret_cast<const float4*>(&g_h2[(size_t)row * 128 + lane * 4]);
    float s0 = 0.f, s1 = 0.f;
    int kb = lane * 4;
    s0 = fmaf(v.x, W3s[(kb + 0) * 2 + 0], s0); s1 = fmaf(v.x, W3s[(kb + 0) * 2 + 1], s1);
    s0 = fmaf(v.y, W3s[(kb + 1) * 2 + 0], s0); s1 = fmaf(v.y, W3s[(kb + 1) * 2 + 1], s1);
    s0 = fmaf(v.z, W3s[(kb + 2) * 2 + 0], s0); s1 = fmaf(v.z, W3s[(kb + 2) * 2 + 1], s1);
    s0 = fmaf(v.w, W3s[(kb + 3) * 2 + 0], s0); s1 = fmaf(v.w, W3s[(kb + 3) * 2 + 1], s1);
#pragma unroll
    for (int o = 16; o > 0; o >>= 1) {
        s0 += __shfl_xor_sync(0xffffffffu, s0, o);
        s1 += __shfl_xor_sync(0xffffffffu, s1, o);
    }
    if (lane == 0) {
        float2 o2;
        o2.x = tanhf(s0 + b3s[0]);
        o2.y = tanhf(s1 + b3s[1]);
        *reinterpret_cast<float2*>(out + (size_t)row * 2) = o2;
    }
}

// ---------------------------------------------------------------------------
// kernel_launch
// ---------------------------------------------------------------------------
extern "C" void kernel_launch(void* const* d_in, const int* in_sizes, int n_in,
                              void* d_out, int out_size) {
    const float* S0  = (const float*)d_in[0];
    const float* S1  = (const float*)d_in[1];
    const float* S2  = (const float*)d_in[2];
    const float* W0  = (const float*)d_in[3];
    const float* b0  = (const float*)d_in[4];
    const float* Wg  = (const float*)d_in[5];
    const float* bg  = (const float*)d_in[6];
    const float* Ws1 = (const float*)d_in[7];
    const float* bs1 = (const float*)d_in[8];
    const float* Ws2 = (const float*)d_in[9];
    const float* bs2 = (const float*)d_in[10];
    const float* Wq  = (const float*)d_in[11];
    const float* Wk  = (const float*)d_in[12];
    const float* Wv  = (const float*)d_in[13];
    const float* Wc1 = (const float*)d_in[14];
    const float* bc1 = (const float*)d_in[15];
    const float* Wc2 = (const float*)d_in[16];
    const float* bc2 = (const float*)d_in[17];
    const float* Wc3 = (const float*)d_in[18];
    const float* bc3 = (const float*)d_in[19];
    float* out = (float*)d_out;

    void* p;
    cudaGetSymbolAddress(&p, g_concat); float* C  = (float*)p;
    cudaGetSymbolAddress(&p, g_h);      float* Hb = (float*)p;
    cudaGetSymbolAddress(&p, g_h2);     float* H2 = (float*)p;
    cudaGetSymbolAddress(&p, g_Wgh);  u16* Wgh  = (u16*)p;
    cudaGetSymbolAddress(&p, g_Wgl);  u16* Wgl  = (u16*)p;
    cudaGetSymbolAddress(&p, g_Wc1h); u16* Wc1h = (u16*)p;
    cudaGetSymbolAddress(&p, g_Wc1l); u16* Wc1l = (u16*)p;
    cudaGetSymbolAddress(&p, g_Wc2h); u16* Wc2h = (u16*)p;
    cudaGetSymbolAddress(&p, g_Wc2l); u16* Wc2l = (u16*)p;

    cudaFuncSetAttribute(k_attn5, cudaFuncAttributeMaxDynamicSharedMemorySize,
                         ATTN_SMEM_BYTES);
    cudaFuncSetAttribute(k_mma<1024, 1024, 64>,
                         cudaFuncAttributeMaxDynamicSharedMemorySize, MMA_SMEM_BYTES);
    cudaFuncSetAttribute(k_mma<192, 192, 128>,
                         cudaFuncAttributeMaxDynamicSharedMemorySize, MMA_SMEM_BYTES);
    cudaFuncSetAttribute(k_mma<128, 128, 128>,
                         cudaFuncAttributeMaxDynamicSharedMemorySize, MMA_SMEM_BYTES);

    k_prep<<<16, 256>>>(Wq, Wk);
    k_split<<<448, 256>>>(Wg, Wc1, Wc2, Ws2, Wv);
    // K1: env_e -> g_concat[:,64:128]
    k_mma<1024, 1024, 64><<<dim3(B_TOT / 128, 1), 256, MMA_SMEM_BYTES>>>(
        S1, Wgh, Wgl, bg, C, 192, 64);
    // K2: own_e + attention -> g_concat[:,0:64], [:,128:192]
    k_attn5<<<B_TOT / 16, 256, ATTN_SMEM_BYTES>>>(S0, S2, W0, b0, Ws1, bs1, bs2);
    // K3a: h1 = relu(concat @ Wc1 + bc1)
    k_mma<192, 192, 128><<<dim3(B_TOT / 128, 2), 256, MMA_SMEM_BYTES>>>(
        C, Wc1h, Wc1l, bc1, Hb, 128, 0);
    // K3b: h2 = relu(h1 @ Wc2 + bc2)
    k_mma<128, 128, 128><<<dim3(B_TOT / 128, 2), 256, MMA_SMEM_BYTES>>>(
        Hb, Wc2h, Wc2l, bc2, H2, 128, 0);
    // K4: out
    k_head<<<B_TOT / 8, 256>>>(Wc3, bc3, out);
}

// round 9
// speedup vs baseline: 2.0351x; 1.0609x over previous
#include <cuda_runtime.h>
#include <cuda_bf16.h>
#include <math.h>
#include <stdint.h>

#define B_TOT 65536
// H=64, HC=128, N=8, OBS0=6, OBS1=1024, OBS2=7, NA=2

typedef unsigned long long u64;
typedef unsigned short u16;
typedef unsigned int u32;

// ---------------------------------------------------------------------------
// helpers
// ---------------------------------------------------------------------------
static __device__ __forceinline__ uint32_t smem_u32(const void* p) {
    uint32_t a;
    asm("{ .reg .u64 t; cvta.to.shared.u64 t, %1; cvt.u32.u64 %0, t; }"
        : "=r"(a) : "l"(p));
    return a;
}
static __device__ __forceinline__ void mma16816(float* c, const u32* a, const u32* b) {
    asm volatile(
        "mma.sync.aligned.m16n8k16.row.col.f32.bf16.bf16.f32 "
        "{%0,%1,%2,%3}, {%4,%5,%6,%7}, {%8,%9}, {%0,%1,%2,%3};"
        : "+f"(c[0]), "+f"(c[1]), "+f"(c[2]), "+f"(c[3])
        : "r"(a[0]), "r"(a[1]), "r"(a[2]), "r"(a[3]), "r"(b[0]), "r"(b[1]));
}
static __device__ __forceinline__ void ldsm4(u32& r0, u32& r1, u32& r2, u32& r3, u32 a) {
    asm volatile("ldmatrix.sync.aligned.m8n8.x4.shared.b16 {%0,%1,%2,%3}, [%4];"
                 : "=r"(r0), "=r"(r1), "=r"(r2), "=r"(r3) : "r"(a));
}
static __device__ __forceinline__ void ldsm4t(u32& r0, u32& r1, u32& r2, u32& r3, u32 a) {
    asm volatile("ldmatrix.sync.aligned.m8n8.x4.trans.shared.b16 {%0,%1,%2,%3}, [%4];"
                 : "=r"(r0), "=r"(r1), "=r"(r2), "=r"(r3) : "r"(a));
}
// exact pair split: h2 = {x0>>16, x1>>16}; l2 = bf16rn(residuals)
static __device__ __forceinline__ void split2(float x0, float x1, u32& h2, u32& l2) {
    u32 b0 = __float_as_uint(x0), b1 = __float_as_uint(x1);
    asm("prmt.b32 %0, %1, %2, 0x7632;" : "=r"(h2) : "r"(b0), "r"(b1));
    float r0 = x0 - __uint_as_float(b0 & 0xffff0000u);
    float r1 = x1 - __uint_as_float(b1 & 0xffff0000u);
    asm("cvt.rn.bf16x2.f32 %0, %1, %2;" : "=r"(l2) : "f"(r1), "f"(r0));
}

// ---------------------------------------------------------------------------
// Scratch (static device globals: allocation-free)
// ---------------------------------------------------------------------------
__device__ float g_concat[(size_t)B_TOT * 192];
// pre-split weights, [k][n] row-major bf16
__device__ u16 g_Wgh[1024 * 64],  g_Wgl[1024 * 64];
__device__ u16 g_Wc1h[192 * 128], g_Wc1l[192 * 128];
__device__ u16 g_Wc2h[128 * 128], g_Wc2l[128 * 128];
__device__ u16 g_Ws2h[64 * 64],   g_Ws2l[64 * 64];
__device__ u16 g_Mh[64 * 64],     g_Ml[64 * 64];      // Wq@Wk^T split
__device__ u16 g_Wvh[64 * 64],    g_Wvl[64 * 64];

// ---------------------------------------------------------------------------
// K0: split all weights into bf16 hi/lo; also computes M = Wq@Wk^T (split)
// ---------------------------------------------------------------------------
__global__ void k_split(const float* __restrict__ Wg, const float* __restrict__ Wc1,
                        const float* __restrict__ Wc2, const float* __restrict__ Ws2,
                        const float* __restrict__ Wv,
                        const float* __restrict__ Wq, const float* __restrict__ Wk) {
    int i = blockIdx.x * 256 + threadIdx.x;
    float x;
    u16 *dh, *dl; int off;
    if (i < 65536)       { x = Wg[i];           dh = g_Wgh;  dl = g_Wgl;  off = i; }
    else if (i < 90112)  { off = i - 65536;  x = Wc1[off]; dh = g_Wc1h; dl = g_Wc1l; }
    else if (i < 106496) { off = i - 90112;  x = Wc2[off]; dh = g_Wc2h; dl = g_Wc2l; }
    else if (i < 110592) { off = i - 106496; x = Ws2[off]; dh = g_Ws2h; dl = g_Ws2l; }
    else if (i < 114688) { off = i - 110592; x = Wv[off];  dh = g_Wvh;  dl = g_Wvl; }
    else if (i < 118784) {
        off = i - 114688;
        int r = off >> 6, j = off & 63;
        float s = 0.f;
#pragma unroll
        for (int h = 0; h < 64; h++) s = fmaf(Wq[r * 64 + h], Wk[j * 64 + h], s);
        x = s; dh = g_Mh; dl = g_Ml;
    } else return;
    __nv_bfloat16 hb = __float2bfloat16(x);
    __nv_bfloat16 lb = __float2bfloat16(x - __bfloat162float(hb));
    dh[off] = __bfloat16_as_ushort(hb);
    dl[off] = __bfloat16_as_ushort(lb);
}

// ---------------------------------------------------------------------------
// Tensor-core GEMM for K1 (ldmatrix + pre-split B)
// ---------------------------------------------------------------------------
#define MMA_SMEM_BYTES (55296 + 256)

template <int KTOT, int LDA, int LDB>
__global__ __launch_bounds__(256)
void k_mma(const float* __restrict__ A,
           const u16* __restrict__ Bh_g, const u16* __restrict__ Bl_g,
           const float* __restrict__ bias, float* __restrict__ C,
           int ldc, int ccol0) {
    extern __shared__ char smem[];
    const u32 sbase = smem_u32(smem);
    const u32 ah_b = sbase, al_b = sbase + 18432;
    const u32 bh_b = sbase + 36864, bl_b = sbase + 46080;
    float* bs = (float*)(smem + 55296);

    const int tid = threadIdx.x;
    const int wid = tid >> 5, lane = tid & 31;
    const int row0 = blockIdx.x * 128;
    const int bcol = blockIdx.y * 64;
    const int mwarp = wid >> 1, nwarp = wid & 1;
    const int g = lane >> 2, t = lane & 3;
    const int lr = lane & 15, lc = (lane >> 4) << 3;

    if (tid < 64) bs[tid] = bias[bcol + tid];

    float acc[2][4][4];
#pragma unroll
    for (int mt = 0; mt < 2; mt++)
#pragma unroll
        for (int nt = 0; nt < 4; nt++)
#pragma unroll
            for (int r = 0; r < 4; r++) acc[mt][nt][r] = 0.f;

    const int mrow0 = mwarp * 32, ncol0 = nwarp * 32;

    for (int c = 0; c < KTOT / 64; c++) {
        const int k0 = c * 64;
        {
            const int m = tid >> 1, h = tid & 1;
            const float* src = A + (size_t)(row0 + m) * LDA + k0 + h * 32;
            char* dh = smem + m * 144 + h * 64;
            char* dl = smem + 18432 + m * 144 + h * 64;
#pragma unroll
            for (int q = 0; q < 8; q++) {
                float4 v = *reinterpret_cast<const float4*>(src + q * 4);
                uint2 hh, ll;
                split2(v.x, v.y, hh.x, ll.x);
                split2(v.z, v.w, hh.y, ll.y);
                *reinterpret_cast<uint2*>(dh + q * 8) = hh;
                *reinterpret_cast<uint2*>(dl + q * 8) = ll;
            }
        }
        {
            const int kk = tid >> 2, cg = (tid & 3) * 16;
            const u16* sh = Bh_g + (size_t)(k0 + kk) * LDB + bcol + cg;
            const u16* sl = Bl_g + (size_t)(k0 + kk) * LDB + bcol + cg;
            char* dh = smem + 36864 + kk * 144 + cg * 2;
            char* dl = smem + 46080 + kk * 144 + cg * 2;
            *reinterpret_cast<uint4*>(dh)      = *reinterpret_cast<const uint4*>(sh);
            *reinterpret_cast<uint4*>(dh + 16) = *reinterpret_cast<const uint4*>(sh + 8);
            *reinterpret_cast<uint4*>(dl)      = *reinterpret_cast<const uint4*>(sl);
            *reinterpret_cast<uint4*>(dl + 16) = *reinterpret_cast<const uint4*>(sl + 8);
        }
        __syncthreads();

#pragma unroll
        for (int k16 = 0; k16 < 4; k16++) {
            const int kk = k16 * 16;
            u32 bh[8], bl[8];
            ldsm4t(bh[0], bh[1], bh[2], bh[3], bh_b + ((kk + lr) * 72 + ncol0 + lc) * 2);
            ldsm4t(bh[4], bh[5], bh[6], bh[7], bh_b + ((kk + lr) * 72 + ncol0 + 16 + lc) * 2);
            ldsm4t(bl[0], bl[1], bl[2], bl[3], bl_b + ((kk + lr) * 72 + ncol0 + lc) * 2);
            ldsm4t(bl[4], bl[5], bl[6], bl[7], bl_b + ((kk + lr) * 72 + ncol0 + 16 + lc) * 2);
#pragma unroll
            for (int mt = 0; mt < 2; mt++) {
                u32 ah[4], al[4];
                ldsm4(ah[0], ah[1], ah[2], ah[3],
                      ah_b + ((mrow0 + mt * 16 + lr) * 72 + kk + lc) * 2);
                ldsm4(al[0], al[1], al[2], al[3],
                      al_b + ((mrow0 + mt * 16 + lr) * 72 + kk + lc) * 2);
#pragma unroll
                for (int nt = 0; nt < 4; nt++) {
                    mma16816(acc[mt][nt], ah, &bh[nt * 2]);
                    mma16816(acc[mt][nt], ah, &bl[nt * 2]);
                    mma16816(acc[mt][nt], al, &bh[nt * 2]);
                }
            }
        }
        __syncthreads();
    }

#pragma unroll
    for (int mt = 0; mt < 2; mt++) {
#pragma unroll
        for (int nt = 0; nt < 4; nt++) {
            int r = row0 + mrow0 + mt * 16 + g;
            int cl = ncol0 + nt * 8 + t * 2;
            int cg = ccol0 + bcol + cl;
            float b0v = bs[cl], b1v = bs[cl + 1];
            float2 v0, v1;
            v0.x = fmaxf(acc[mt][nt][0] + b0v, 0.f);
            v0.y = fmaxf(acc[mt][nt][1] + b1v, 0.f);
            v1.x = fmaxf(acc[mt][nt][2] + b0v, 0.f);
            v1.y = fmaxf(acc[mt][nt][3] + b1v, 0.f);
            *reinterpret_cast<float2*>(C + (size_t)r * ldc + cg) = v0;
            *reinterpret_cast<float2*>(C + (size_t)(r + 8) * ldc + cg) = v1;
        }
    }
}

// ---------------------------------------------------------------------------
// K2 v5: fused attention (unchanged from round 8)
// ---------------------------------------------------------------------------
#define AT_E1H   0
#define AT_E1L   18432
#define AT_E2    0
#define AT_WS2H  36864
#define AT_WS2L  46080
#define AT_MH    55296
#define AT_ML    64512
#define AT_WVH   73728
#define AT_WVL   82944
#define AT_OWNH  92160
#define AT_OWNL  94464
#define AT_TT    96768
#define AT_W0    101120
#define AT_WS1   102656
#define AT_B0    104448
#define AT_BS1   104704
#define AT_BS2   104960
#define AT_SC    105216
#define AT_AL    105728
#define AT_MK    106240
#define ATTN_SMEM_BYTES 106752

__global__ __launch_bounds__(256, 2)
void k_attn5(const float* __restrict__ S0, const float* __restrict__ S2,
             const float* __restrict__ W0, const float* __restrict__ b0,
             const float* __restrict__ Ws1, const float* __restrict__ bs1,
             const float* __restrict__ bs2) {
    extern __shared__ char smem[];
    float* E2   = (float*)(smem + AT_E2);
    float* tt   = (float*)(smem + AT_TT);
    float* W0s  = (float*)(smem + AT_W0);
    float* Ws1s = (float*)(smem + AT_WS1);
    float* b0s  = (float*)(smem + AT_B0);
    float* bs1s = (float*)(smem + AT_BS1);
    float* bs2s = (float*)(smem + AT_BS2);
    float* sc   = (float*)(smem + AT_SC);
    float* al   = (float*)(smem + AT_AL);
    float* mk   = (float*)(smem + AT_MK);
    const u32 sbase = smem_u32(smem);
    const u32 e1h_b = sbase + AT_E1H, e1l_b = sbase + AT_E1L;
    const u32 wsh_b = sbase + AT_WS2H, wsl_b = sbase + AT_WS2L;
    const u32 mh_b  = sbase + AT_MH,   ml_b  = sbase + AT_ML;
    const u32 wvh_b = sbase + AT_WVH,  wvl_b = sbase + AT_WVL;
    const u32 ownh_b = sbase + AT_OWNH, ownl_b = sbase + AT_OWNL;

    const int tid = threadIdx.x;
    const int wid = tid >> 5, lane = tid & 31;
    const int gb0 = blockIdx.x * 16;

    if (tid < 96)  reinterpret_cast<float4*>(W0s)[tid]  =
        reinterpret_cast<const float4*>(W0)[tid];
    if (tid >= 96 && tid < 208) reinterpret_cast<float4*>(Ws1s)[tid - 96] =
        reinterpret_cast<const float4*>(Ws1)[tid - 96];
    if (tid >= 208 && tid < 224) reinterpret_cast<float4*>(b0s)[tid - 208] =
        reinterpret_cast<const float4*>(b0)[tid - 208];
    if (tid >= 224 && tid < 240) reinterpret_cast<float4*>(bs1s)[tid - 224] =
        reinterpret_cast<const float4*>(bs1)[tid - 224];
    if (tid >= 240) reinterpret_cast<float4*>(bs2s)[tid - 240] =
        reinterpret_cast<const float4*>(bs2)[tid - 240];
    {
        const int kk = tid >> 2, cg = (tid & 3) * 16;
        const int go = kk * 64 + cg;
        const int so = kk * 144 + cg * 2;
        const u16* srcs[6] = {g_Ws2h, g_Ws2l, g_Mh, g_Ml, g_Wvh, g_Wvl};
        const int offs[6] = {AT_WS2H, AT_WS2L, AT_MH, AT_ML, AT_WVH, AT_WVL};
#pragma unroll
        for (int a = 0; a < 6; a++) {
            char* d = smem + offs[a] + so;
            *reinterpret_cast<uint4*>(d)      = *reinterpret_cast<const uint4*>(srcs[a] + go);
            *reinterpret_cast<uint4*>(d + 16) = *reinterpret_cast<const uint4*>(srcs[a] + go + 8);
        }
    }

    // P1: own_e
    {
        const int row = tid >> 4, c0 = (tid & 15) * 4;
        const float* s0 = S0 + (size_t)(gb0 + row) * 6;
        float x0 = s0[0], x1 = s0[1], x2 = s0[2], x3 = s0[3], x4 = s0[4], x5 = s0[5];
        float* og = g_concat + (size_t)(gb0 + row) * 192;
        __syncthreads();
        float4 a4 = *reinterpret_cast<const float4*>(b0s + c0);
#pragma unroll
        for (int kk = 0; kk < 6; kk++) {
            float xv = (kk == 0) ? x0 : (kk == 1) ? x1 : (kk == 2) ? x2 :
                       (kk == 3) ? x3 : (kk == 4) ? x4 : x5;
            float4 w4 = *reinterpret_cast<const float4*>(W0s + kk * 64 + c0);
            a4.x = fmaf(xv, w4.x, a4.x); a4.y = fmaf(xv, w4.y, a4.y);
            a4.z = fmaf(xv, w4.z, a4.z); a4.w = fmaf(xv, w4.w, a4.w);
        }
        a4.x = fmaxf(a4.x, 0.f); a4.y = fmaxf(a4.y, 0.f);
        a4.z = fmaxf(a4.z, 0.f); a4.w = fmaxf(a4.w, 0.f);
        uint2 hh, ll;
        split2(a4.x, a4.y, hh.x, ll.x);
        split2(a4.z, a4.w, hh.y, ll.y);
        *reinterpret_cast<uint2*>(smem + AT_OWNH + row * 144 + c0 * 2) = hh;
        *reinterpret_cast<uint2*>(smem + AT_OWNL + row * 144 + c0 * 2) = ll;
        *reinterpret_cast<float4*>(og + c0) = a4;
    }

    // P2: E1
    {
        const int rr = tid >> 1, h = tid & 1, j0 = h * 32;
        const float* s2 = S2 + ((size_t)gb0 * 8 + rr) * 7;
        float y0 = s2[0], y1 = s2[1], y2 = s2[2], y3 = s2[3], y4 = s2[4], y5 = s2[5], y6 = s2[6];
        if (h == 0)
            mk[rr] = ((y0 + y1 + y2 + y3 + y4 + y5 + y6) != 0.f) ? 1.f : 0.f;
        float a[32];
#pragma unroll
        for (int q = 0; q < 8; q++) {
            float4 v4 = *reinterpret_cast<const float4*>(bs1s + j0 + q * 4);
            a[q * 4 + 0] = v4.x; a[q * 4 + 1] = v4.y;
            a[q * 4 + 2] = v4.z; a[q * 4 + 3] = v4.w;
        }
#pragma unroll
        for (int kk = 0; kk < 7; kk++) {
            float yv = (kk == 0) ? y0 : (kk == 1) ? y1 : (kk == 2) ? y2 :
                       (kk == 3) ? y3 : (kk == 4) ? y4 : (kk == 5) ? y5 : y6;
#pragma unroll
            for (int q = 0; q < 8; q++) {
                float4 w4 = *reinterpret_cast<const float4*>(Ws1s + kk * 64 + j0 + q * 4);
                a[q * 4 + 0] = fmaf(yv, w4.x, a[q * 4 + 0]);
                a[q * 4 + 1] = fmaf(yv, w4.y, a[q * 4 + 1]);
                a[q * 4 + 2] = fmaf(yv, w4.z, a[q * 4 + 2]);
                a[q * 4 + 3] = fmaf(yv, w4.w, a[q * 4 + 3]);
            }
        }
#pragma unroll
        for (int j = 0; j < 32; j++) a[j] = fmaxf(a[j], 0.f);
        char* dh = smem + AT_E1H + rr * 144 + j0 * 2;
        char* dl = smem + AT_E1L + rr * 144 + j0 * 2;
#pragma unroll
        for (int q = 0; q < 32; q += 8) {
            uint4 vh, vl;
            split2(a[q + 0], a[q + 1], vh.x, vl.x);
            split2(a[q + 2], a[q + 3], vh.y, vl.y);
            split2(a[q + 4], a[q + 5], vh.z, vl.z);
            split2(a[q + 6], a[q + 7], vh.w, vl.w);
            *reinterpret_cast<uint4*>(dh + q * 2) = vh;
            *reinterpret_cast<uint4*>(dl + q * 2) = vl;
        }
    }
    __syncthreads();

    // P3: E2 = relu(E1 @ Ws2 + bs2) via HMMA
    float acc[2][4][4];
    {
        const int mwarp = wid >> 1, nwarp = wid & 1;
        const int lr = lane & 15, lc = (lane >> 4) << 3;
        const int mrow0 = mwarp * 32, ncol0 = nwarp * 32;
#pragma unroll
        for (int mt = 0; mt < 2; mt++)
#pragma unroll
            for (int nt = 0; nt < 4; nt++)
#pragma unroll
                for (int r = 0; r < 4; r++) acc[mt][nt][r] = 0.f;

#pragma unroll
        for (int k16 = 0; k16 < 4; k16++) {
            const int kk = k16 * 16;
            u32 bh[8], bl[8];
            ldsm4t(bh[0], bh[1], bh[2], bh[3], wsh_b + ((kk + lr) * 72 + ncol0 + lc) * 2);
            ldsm4t(bh[4], bh[5], bh[6], bh[7], wsh_b + ((kk + lr) * 72 + ncol0 + 16 + lc) * 2);
            ldsm4t(bl[0], bl[1], bl[2], bl[3], wsl_b + ((kk + lr) * 72 + ncol0 + lc) * 2);
            ldsm4t(bl[4], bl[5], bl[6], bl[7], wsl_b + ((kk + lr) * 72 + ncol0 + 16 + lc) * 2);
#pragma unroll
            for (int mt = 0; mt < 2; mt++) {
                u32 ah[4], alr[4];
                ldsm4(ah[0], ah[1], ah[2], ah[3],
                      e1h_b + ((mrow0 + mt * 16 + lr) * 72 + kk + lc) * 2);
                ldsm4(alr[0], alr[1], alr[2], alr[3],
                      e1l_b + ((mrow0 + mt * 16 + lr) * 72 + kk + lc) * 2);
#pragma unroll
                for (int nt = 0; nt < 4; nt++) {
                    mma16816(acc[mt][nt], ah, &bh[nt * 2]);
                    mma16816(acc[mt][nt], ah, &bl[nt * 2]);
                    mma16816(acc[mt][nt], alr, &bh[nt * 2]);
                }
            }
        }
    }
    __syncthreads();

    // E2 epilogue + P4 (own@M HMMA)
    {
        const int mwarp = wid >> 1, nwarp = wid & 1;
        const int g = lane >> 2, t = lane & 3;
        const int mrow0 = mwarp * 32, ncol0 = nwarp * 32;
#pragma unroll
        for (int mt = 0; mt < 2; mt++) {
#pragma unroll
            for (int nt = 0; nt < 4; nt++) {
                int r = mrow0 + mt * 16 + g;
                int cl = ncol0 + nt * 8 + t * 2;
                float b0v = bs2s[cl], b1v = bs2s[cl + 1];
                float2 v0, v1;
                v0.x = fmaxf(acc[mt][nt][0] + b0v, 0.f);
                v0.y = fmaxf(acc[mt][nt][1] + b1v, 0.f);
                v1.x = fmaxf(acc[mt][nt][2] + b0v, 0.f);
                v1.y = fmaxf(acc[mt][nt][3] + b1v, 0.f);
                *reinterpret_cast<float2*>(E2 + r * 68 + cl) = v0;
                *reinterpret_cast<float2*>(E2 + (r + 8) * 68 + cl) = v1;
            }
        }
    }
    if (wid < 4) {
        const int ncol0 = wid * 16;
        const int lr = lane & 15, lc = (lane >> 4) << 3;
        float tac[2][4];
#pragma unroll
        for (int nt = 0; nt < 2; nt++)
#pragma unroll
            for (int r = 0; r < 4; r++) tac[nt][r] = 0.f;
#pragma unroll
        for (int k16 = 0; k16 < 4; k16++) {
            const int kk = k16 * 16;
            u32 bh[4], bl[4], ah[4], alr[4];
            ldsm4t(bh[0], bh[1], bh[2], bh[3], mh_b + ((kk + lr) * 72 + ncol0 + lc) * 2);
            ldsm4t(bl[0], bl[1], bl[2], bl[3], ml_b + ((kk + lr) * 72 + ncol0 + lc) * 2);
            ldsm4(ah[0], ah[1], ah[2], ah[3], ownh_b + lr * 144 + (kk + lc) * 2);
            ldsm4(alr[0], alr[1], alr[2], alr[3], ownl_b + lr * 144 + (kk + lc) * 2);
#pragma unroll
            for (int nt = 0; nt < 2; nt++) {
                mma16816(tac[nt], ah, &bh[nt * 2]);
                mma16816(tac[nt], ah, &bl[nt * 2]);
                mma16816(tac[nt], alr, &bh[nt * 2]);
            }
        }
        const int g = lane >> 2, tq = lane & 3;
#pragma unroll
        for (int nt = 0; nt < 2; nt++) {
            int cl = ncol0 + nt * 8 + tq * 2;
            *reinterpret_cast<float2*>(tt + g * 68 + cl) =
                make_float2(tac[nt][0], tac[nt][1]);
            *reinterpret_cast<float2*>(tt + (g + 8) * 68 + cl) =
                make_float2(tac[nt][2], tac[nt][3]);
        }
    }
    __syncthreads();

    // P5: scores
    {
        const int rr = tid >> 1, h = tid & 1, k0 = h * 32;
        const int lb = rr >> 3;
        float s = 0.f;
#pragma unroll
        for (int k = 0; k < 32; k += 4) {
            float4 t4 = *reinterpret_cast<const float4*>(tt + lb * 68 + k0 + k);
            float4 e4 = *reinterpret_cast<const float4*>(E2 + rr * 68 + k0 + k);
            s = fmaf(t4.x, e4.x, s); s = fmaf(t4.y, e4.y, s);
            s = fmaf(t4.z, e4.z, s); s = fmaf(t4.w, e4.w, s);
        }
        s += __shfl_xor_sync(0xffffffffu, s, 1);
        if (h == 0)
            sc[rr] = (mk[rr] != 0.f) ? (s * 0.125f) : __int_as_float(0xff800000);
    }
    __syncthreads();

    // P6: softmax
    if (tid < 16) {
        float m = __int_as_float(0xff800000);
#pragma unroll
        for (int n = 0; n < 8; n++) m = fmaxf(m, sc[tid * 8 + n]);
        float e[8]; float ssum = 0.f;
#pragma unroll
        for (int n = 0; n < 8; n++) { float v = expf(sc[tid * 8 + n] - m); e[n] = v; ssum += v; }
        float inv = 1.f / ssum;
#pragma unroll
        for (int n = 0; n < 8; n++) al[tid * 8 + n] = e[n] * inv;
    }
    __syncthreads();

    // P7a: wsum -> split bf16 (aliases own buffers)
    {
        const int row = tid >> 4, c0 = (tid & 15) * 4;
        float4 a4 = {0.f, 0.f, 0.f, 0.f};
#pragma unroll
        for (int n = 0; n < 8; n++) {
            float av = al[row * 8 + n];
            float4 e4 = *reinterpret_cast<const float4*>(E2 + (row * 8 + n) * 68 + c0);
            a4.x = fmaf(av, e4.x, a4.x); a4.y = fmaf(av, e4.y, a4.y);
            a4.z = fmaf(av, e4.z, a4.z); a4.w = fmaf(av, e4.w, a4.w);
        }
        uint2 hh, ll;
        split2(a4.x, a4.y, hh.x, ll.x);
        split2(a4.z, a4.w, hh.y, ll.y);
        *reinterpret_cast<uint2*>(smem + AT_OWNH + row * 144 + c0 * 2) = hh;
        *reinterpret_cast<uint2*>(smem + AT_OWNL + row * 144 + c0 * 2) = ll;
    }
    __syncthreads();

    // P7b: v_att = wsum @ Wv via HMMA
    if (wid < 4) {
        const int ncol0 = wid * 16;
        const int lr = lane & 15, lc = (lane >> 4) << 3;
        float vac[2][4];
#pragma unroll
        for (int nt = 0; nt < 2; nt++)
#pragma unroll
            for (int r = 0; r < 4; r++) vac[nt][r] = 0.f;
#pragma unroll
        for (int k16 = 0; k16 < 4; k16++) {
            const int kk = k16 * 16;
            u32 bh[4], bl[4], ah[4], alr[4];
            ldsm4t(bh[0], bh[1], bh[2], bh[3], wvh_b + ((kk + lr) * 72 + ncol0 + lc) * 2);
            ldsm4t(bl[0], bl[1], bl[2], bl[3], wvl_b + ((kk + lr) * 72 + ncol0 + lc) * 2);
            ldsm4(ah[0], ah[1], ah[2], ah[3], ownh_b + lr * 144 + (kk + lc) * 2);
            ldsm4(alr[0], alr[1], alr[2], alr[3], ownl_b + lr * 144 + (kk + lc) * 2);
#pragma unroll
            for (int nt = 0; nt < 2; nt++) {
                mma16816(vac[nt], ah, &bh[nt * 2]);
                mma16816(vac[nt], ah, &bl[nt * 2]);
                mma16816(vac[nt], alr, &bh[nt * 2]);
            }
        }
        const int g = lane >> 2, tq = lane & 3;
#pragma unroll
        for (int nt = 0; nt < 2; nt++) {
            int cl = ncol0 + nt * 8 + tq * 2;
            *reinterpret_cast<float2*>(g_concat + (size_t)(gb0 + g) * 192 + 128 + cl) =
                make_float2(vac[nt][0], vac[nt][1]);
            *reinterpret_cast<float2*>(g_concat + (size_t)(gb0 + g + 8) * 192 + 128 + cl) =
                make_float2(vac[nt][2], vac[nt][3]);
        }
    }
}

// ---------------------------------------------------------------------------
// K3 (NEW): fused tail — h1 = relu(concat@Wc1+bc1); h2 = relu(h1@Wc2+bc2);
//           out = tanh(h2@Wc3+bc3). 64 rows/CTA, 256 thr, 2 CTA/SM.
// Warp layout: 8 warps = 2m x 4n, warp tile 32x32 over [64 x 128].
// ---------------------------------------------------------------------------
#define TL_AH   0           // [64][72] u16 (9216)   } phase1 A
#define TL_AL   9216        //                        } dies after phase1
#define TL_BH   18432       // [64][136] u16 (17408) } phase1 B
#define TL_BL   35840       //                        } dies after phase1
#define TL_H1H  0           // [64][136] u16 — aliases A+B after phase1
#define TL_H1L  17408
#define TL_B2H  53248       // [64][136] u16 (phase2 B)
#define TL_B2L  70656
#define TL_W3   88064       // 256 f32
#define TL_BC1  89088       // 128 f32
#define TL_BC2  89600       // 128 f32
#define TL_PT   90112       // [64][8] f32 partials (2048)
#define TAIL_SMEM_BYTES 92160

__global__ __launch_bounds__(256, 2)
void k_tail(const float* __restrict__ bc1, const float* __restrict__ bc2,
            const float* __restrict__ Wc3, const float* __restrict__ bc3,
            float* __restrict__ out) {
    extern __shared__ char smem[];
    const u32 sbase = smem_u32(smem);
    float* W3s = (float*)(smem + TL_W3);
    float* b1s = (float*)(smem + TL_BC1);
    float* b2s = (float*)(smem + TL_BC2);
    float* pt  = (float*)(smem + TL_PT);
    __shared__ float b3s[2];

    const int tid = threadIdx.x;
    const int wid = tid >> 5, lane = tid & 31;
    const int row0 = blockIdx.x * 64;
    const int mwarp = wid >> 2, nwarp = wid & 3;
    const int g = lane >> 2, t = lane & 3;
    const int lr = lane & 15, lc = (lane >> 4) << 3;
    const int mrow0 = mwarp * 32, ncol0 = nwarp * 32;

    if (tid < 128) b1s[tid] = bc1[tid];
    else b2s[tid - 128] = bc2[tid - 128];
    if (tid < 64) reinterpret_cast<float4*>(W3s)[tid] =
        reinterpret_cast<const float4*>(Wc3)[tid];
    if (tid == 0) { b3s[0] = bc3[0]; b3s[1] = bc3[1]; }

    float acc[2][4][4];
#pragma unroll
    for (int mt = 0; mt < 2; mt++)
#pragma unroll
        for (int nt = 0; nt < 4; nt++)
#pragma unroll
            for (int r = 0; r < 4; r++) acc[mt][nt][r] = 0.f;

    // ---- Phase 1: h1 = relu(concat @ Wc1 + bc1), K = 192 ----
    for (int c = 0; c < 3; c++) {
        const int k0 = c * 64;
        {   // A convert: 64 rows x 64 cols fp32 -> split bf16 (stride 72)
            const int m = tid >> 2, cq = tid & 3;
            const float* src = g_concat + (size_t)(row0 + m) * 192 + k0 + cq * 16;
            char* dh = smem + TL_AH + m * 144 + cq * 32;
            char* dl = smem + TL_AL + m * 144 + cq * 32;
#pragma unroll
            for (int q = 0; q < 4; q++) {
                float4 v = *reinterpret_cast<const float4*>(src + q * 4);
                uint2 hh, ll;
                split2(v.x, v.y, hh.x, ll.x);
                split2(v.z, v.w, hh.y, ll.y);
                *reinterpret_cast<uint2*>(dh + q * 8) = hh;
                *reinterpret_cast<uint2*>(dl + q * 8) = ll;
            }
        }
        {   // B: Wc1 split, rows k0..k0+63 x 128 cols (stride 136)
            const int kk = tid >> 2, cq = tid & 3;
            const u16* sh = g_Wc1h + (size_t)(k0 + kk) * 128 + cq * 32;
            const u16* sl = g_Wc1l + (size_t)(k0 + kk) * 128 + cq * 32;
            char* dh = smem + TL_BH + kk * 272 + cq * 64;
            char* dl = smem + TL_BL + kk * 272 + cq * 64;
#pragma unroll
            for (int q = 0; q < 4; q++) {
                *reinterpret_cast<uint4*>(dh + q * 16) =
                    *reinterpret_cast<const uint4*>(sh + q * 8);
                *reinterpret_cast<uint4*>(dl + q * 16) =
                    *reinterpret_cast<const uint4*>(sl + q * 8);
            }
        }
        __syncthreads();
#pragma unroll
        for (int k16 = 0; k16 < 4; k16++) {
            const int kk = k16 * 16;
            u32 bh[8], bl[8];
            ldsm4t(bh[0], bh[1], bh[2], bh[3],
                   sbase + TL_BH + ((kk + lr) * 136 + ncol0 + lc) * 2);
            ldsm4t(bh[4], bh[5], bh[6], bh[7],
                   sbase + TL_BH + ((kk + lr) * 136 + ncol0 + 16 + lc) * 2);
            ldsm4t(bl[0], bl[1], bl[2], bl[3],
                   sbase + TL_BL + ((kk + lr) * 136 + ncol0 + lc) * 2);
            ldsm4t(bl[4], bl[5], bl[6], bl[7],
                   sbase + TL_BL + ((kk + lr) * 136 + ncol0 + 16 + lc) * 2);
#pragma unroll
            for (int mt = 0; mt < 2; mt++) {
                u32 ah[4], al[4];
                ldsm4(ah[0], ah[1], ah[2], ah[3],
                      sbase + TL_AH + ((mrow0 + mt * 16 + lr) * 72 + kk + lc) * 2);
                ldsm4(al[0], al[1], al[2], al[3],
                      sbase + TL_AL + ((mrow0 + mt * 16 + lr) * 72 + kk + lc) * 2);
#pragma unroll
                for (int nt = 0; nt < 4; nt++) {
                    mma16816(acc[mt][nt], ah, &bh[nt * 2]);
                    mma16816(acc[mt][nt], ah, &bl[nt * 2]);
                    mma16816(acc[mt][nt], al, &bh[nt * 2]);
                }
            }
        }
        __syncthreads();
    }

    // h1 epilogue: relu + split -> H1 smem (stride 136); aliases A+B region
#pragma unroll
    for (int mt = 0; mt < 2; mt++) {
#pragma unroll
        for (int nt = 0; nt < 4; nt++) {
            int r = mrow0 + mt * 16 + g;
            int cl = ncol0 + nt * 8 + t * 2;
            float b0v = b1s[cl], b1v = b1s[cl + 1];
            u32 hh, ll;
            split2(fmaxf(acc[mt][nt][0] + b0v, 0.f),
                   fmaxf(acc[mt][nt][1] + b1v, 0.f), hh, ll);
            *reinterpret_cast<u32*>(smem + TL_H1H + r * 272 + cl * 2) = hh;
            *reinterpret_cast<u32*>(smem + TL_H1L + r * 272 + cl * 2) = ll;
            split2(fmaxf(acc[mt][nt][2] + b0v, 0.f),
                   fmaxf(acc[mt][nt][3] + b1v, 0.f), hh, ll);
            *reinterpret_cast<u32*>(smem + TL_H1H + (r + 8) * 272 + cl * 2) = hh;
            *reinterpret_cast<u32*>(smem + TL_H1L + (r + 8) * 272 + cl * 2) = ll;
        }
    }

    // ---- Phase 2: h2 = relu(h1 @ Wc2 + bc2), K = 128 ----
#pragma unroll
    for (int mt = 0; mt < 2; mt++)
#pragma unroll
        for (int nt = 0; nt < 4; nt++)
#pragma unroll
            for (int r = 0; r < 4; r++) acc[mt][nt][r] = 0.f;

    for (int c = 0; c < 2; c++) {
        const int k0 = c * 64;
        {   // B2: Wc2 split, rows k0..k0+63 x 128 cols (stride 136)
            const int kk = tid >> 2, cq = tid & 3;
            const u16* sh = g_Wc2h + (size_t)(k0 + kk) * 128 + cq * 32;
            const u16* sl = g_Wc2l + (size_t)(k0 + kk) * 128 + cq * 32;
            char* dh = smem + TL_B2H + kk * 272 + cq * 64;
            char* dl = smem + TL_B2L + kk * 272 + cq * 64;
#pragma unroll
            for (int q = 0; q < 4; q++) {
                *reinterpret_cast<uint4*>(dh + q * 16) =
                    *reinterpret_cast<const uint4*>(sh + q * 8);
                *reinterpret_cast<uint4*>(dl + q * 16) =
                    *reinterpret_cast<const uint4*>(sl + q * 8);
            }
        }
        __syncthreads();   // also orders H1 writes before ldsm reads (c==0)
#pragma unroll
        for (int k16 = 0; k16 < 4; k16++) {
            const int kk = k16 * 16;
            u32 bh[8], bl[8];
            ldsm4t(bh[0], bh[1], bh[2], bh[3],
                   sbase + TL_B2H + ((kk + lr) * 136 + ncol0 + lc) * 2);
            ldsm4t(bh[4], bh[5], bh[6], bh[7],
                   sbase + TL_B2H + ((kk + lr) * 136 + ncol0 + 16 + lc) * 2);
            ldsm4t(bl[0], bl[1], bl[2], bl[3],
                   sbase + TL_B2L + ((kk + lr) * 136 + ncol0 + lc) * 2);
            ldsm4t(bl[4], bl[5], bl[6], bl[7],
                   sbase + TL_B2L + ((kk + lr) * 136 + ncol0 + 16 + lc) * 2);
#pragma unroll
            for (int mt = 0; mt < 2; mt++) {
                u32 ah[4], al[4];
                ldsm4(ah[0], ah[1], ah[2], ah[3],
                      sbase + TL_H1H + ((mrow0 + mt * 16 + lr) * 136 + k0 + kk + lc) * 2);
                ldsm4(al[0], al[1], al[2], al[3],
                      sbase + TL_H1L + ((mrow0 + mt * 16 + lr) * 136 + k0 + kk + lc) * 2);
#pragma unroll
                for (int nt = 0; nt < 4; nt++) {
                    mma16816(acc[mt][nt], ah, &bh[nt * 2]);
                    mma16816(acc[mt][nt], ah, &bl[nt * 2]);
                    mma16816(acc[mt][nt], al, &bh[nt * 2]);
                }
            }
        }
        __syncthreads();
    }

    // ---- head: per-thread partial dots over owned h2 elements ----
    {
        float ph[4][2];
#pragma unroll
        for (int i = 0; i < 4; i++) { ph[i][0] = 0.f; ph[i][1] = 0.f; }
#pragma unroll
        for (int mt = 0; mt < 2; mt++) {
#pragma unroll
            for (int nt = 0; nt < 4; nt++) {
                int cl = ncol0 + nt * 8 + t * 2;
                float b0v = b2s[cl], b1v = b2s[cl + 1];
                float w00 = W3s[cl * 2], w01 = W3s[cl * 2 + 1];
                float w10 = W3s[(cl + 1) * 2], w11 = W3s[(cl + 1) * 2 + 1];
                float h0 = fmaxf(acc[mt][nt][0] + b0v, 0.f);
                float h1 = fmaxf(acc[mt][nt][1] + b1v, 0.f);
                ph[mt * 2][0] = fmaf(h0, w00, fmaf(h1, w10, ph[mt * 2][0]));
                ph[mt * 2][1] = fmaf(h0, w01, fmaf(h1, w11, ph[mt * 2][1]));
                h0 = fmaxf(acc[mt][nt][2] + b0v, 0.f);
                h1 = fmaxf(acc[mt][nt][3] + b1v, 0.f);
                ph[mt * 2 + 1][0] = fmaf(h0, w00, fmaf(h1, w10, ph[mt * 2 + 1][0]));
                ph[mt * 2 + 1][1] = fmaf(h0, w01, fmaf(h1, w11, ph[mt * 2 + 1][1]));
            }
        }
#pragma unroll
        for (int i = 0; i < 4; i++) {
#pragma unroll
            for (int a = 0; a < 2; a++) {
                ph[i][a] += __shfl_xor_sync(0xffffffffu, ph[i][a], 1);
                ph[i][a] += __shfl_xor_sync(0xffffffffu, ph[i][a], 2);
            }
        }
        if (t == 0) {
#pragma unroll
            for (int i = 0; i < 4; i++) {
                int row = mrow0 + (i >> 1) * 16 + (i & 1) * 8 + g;
                pt[row * 8 + nwarp * 2 + 0] = ph[i][0];
                pt[row * 8 + nwarp * 2 + 1] = ph[i][1];
            }
        }
    }
    __syncthreads();
    if (tid < 128) {
        int row = tid >> 1, a = tid & 1;
        float s = pt[row * 8 + a] + pt[row * 8 + 2 + a] +
                  pt[row * 8 + 4 + a] + pt[row * 8 + 6 + a];
        out[(size_t)(row0 + row) * 2 + a] = tanhf(s + b3s[a]);
    }
}

// ---------------------------------------------------------------------------
// kernel_launch
// ---------------------------------------------------------------------------
extern "C" void kernel_launch(void* const* d_in, const int* in_sizes, int n_in,
                              void* d_out, int out_size) {
    const float* S0  = (const float*)d_in[0];
    const float* S1  = (const float*)d_in[1];
    const float* S2  = (const float*)d_in[2];
    const float* W0  = (const float*)d_in[3];
    const float* b0  = (const float*)d_in[4];
    const float* Wg  = (const float*)d_in[5];
    const float* bg  = (const float*)d_in[6];
    const float* Ws1 = (const float*)d_in[7];
    const float* bs1 = (const float*)d_in[8];
    const float* Ws2 = (const float*)d_in[9];
    const float* bs2 = (const float*)d_in[10];
    const float* Wq  = (const float*)d_in[11];
    const float* Wk  = (const float*)d_in[12];
    const float* Wv  = (const float*)d_in[13];
    const float* Wc1 = (const float*)d_in[14];
    const float* bc1 = (const float*)d_in[15];
    const float* Wc2 = (const float*)d_in[16];
    const float* bc2 = (const float*)d_in[17];
    const float* Wc3 = (const float*)d_in[18];
    const float* bc3 = (const float*)d_in[19];
    float* out = (float*)d_out;

    void* p;
    cudaGetSymbolAddress(&p, g_concat); float* C = (float*)p;
    cudaGetSymbolAddress(&p, g_Wgh);  u16* Wgh = (u16*)p;
    cudaGetSymbolAddress(&p, g_Wgl);  u16* Wgl = (u16*)p;

    cudaFuncSetAttribute(k_attn5, cudaFuncAttributeMaxDynamicSharedMemorySize,
                         ATTN_SMEM_BYTES);
    cudaFuncSetAttribute(k_mma<1024, 1024, 64>,
                         cudaFuncAttributeMaxDynamicSharedMemorySize, MMA_SMEM_BYTES);
    cudaFuncSetAttribute(k_tail, cudaFuncAttributeMaxDynamicSharedMemorySize,
                         TAIL_SMEM_BYTES);

    // K0: split all weights (+ M = Wq@Wk^T)
    k_split<<<464, 256>>>(Wg, Wc1, Wc2, Ws2, Wv, Wq, Wk);
    // K1: env_e -> g_concat[:,64:128]
    k_mma<1024, 1024, 64><<<dim3(B_TOT / 128, 1), 256, MMA_SMEM_BYTES>>>(
        S1, Wgh, Wgl, bg, C, 192, 64);
    // K2: own_e + attention -> g_concat[:,0:64], [:,128:192]
    k_attn5<<<B_TOT / 16, 256, ATTN_SMEM_BYTES>>>(S0, S2, W0, b0, Ws1, bs1, bs2);
    // K3: fused tail -> out
    k_tail<<<B_TOT / 64, 256, TAIL_SMEM_BYTES>>>(bc1, bc2, Wc3, bc3, out);
}